// round 8
// baseline (speedup 1.0000x reference)
#include <cuda_runtime.h>
#include <cuda_bf16.h>
#include <math.h>

// ---------------------------------------------------------------------------
// BUTDDecoder: B=128, K=36, V_DIM=2048, EMBED=1024, HID=1024, NTOKEN=10000,
// MAX_LEN=20 (T=19 decode steps).
//
// Round 8: tensor GEMM templated on BN. BN=128 (8 warps, 128x128 tile,
// 2-stage cp.async, 128KB smem) for the three big GEMMs; BN=64 (4 warps)
// for the skinny per-step GEMMs. Launch order puts gi1c GEMM at #6 for ncu.
// ---------------------------------------------------------------------------

#define B_     128
#define KOBJ   36
#define VD     2048
#define EMB    1024
#define HID_   1024
#define NTOK   10000
#define MAXLEN 20
#define TT     19
#define H3     3072

typedef unsigned long long ull;
typedef __nv_bfloat16 bf16;

// ------------------------- scratch (device globals) ------------------------
__device__ float g_vs[B_ * KOBJ * VD];
__device__ float g_vmean[B_ * VD];
__device__ float g_vproj[B_ * KOBJ * HID_];
__device__ float g_gi1c[TT * B_ * H3];
__device__ float g_h1[B_ * HID_];
__device__ float g_h2all[(TT + 1) * B_ * HID_];
__device__ float g_gih[B_ * H3];
__device__ float g_gh1[B_ * H3];
__device__ float g_gh2[B_ * H3];
__device__ float g_q[B_ * HID_];
__device__ float g_gi2h[B_ * H3];
__device__ float g_p0[B_ * H3];
__device__ float g_Wfq[HID_ * HID_];     // Wq @ W1 (fp32, SIMT precompute)
__device__ float g_Wf2h[H3 * HID_];      // Wih2[:,2048:] @ W1
__device__ float g_bfq[HID_];            // Wq@b1 + bq
__device__ float g_bi2f[H3];             // Wih2[:,2048:]@b1 + bih2
__device__ int   g_order[B_];
__device__ int   g_dl[B_];
__device__ float g_mask[TT * B_];

// bf16 hi/lo operand arrays (activations)
__device__ bf16 g_vs_h[B_ * KOBJ * VD],        g_vs_l[B_ * KOBJ * VD];
__device__ bf16 g_x1c_h[TT * B_ * H3],         g_x1c_l[TT * B_ * H3];
__device__ bf16 g_h1_h[B_ * HID_],             g_h1_l[B_ * HID_];
__device__ bf16 g_h2_h[(TT + 1) * B_ * HID_],  g_h2_l[(TT + 1) * B_ * HID_];
__device__ bf16 g_attv_h[B_ * VD],             g_attv_l[B_ * VD];

// bf16 hi/lo weight arrays
__device__ bf16 g_wih1h_h[H3 * HID_],  g_wih1h_l[H3 * HID_];   // Wih1[:, :1024]
__device__ bf16 g_wih1x_h[H3 * H3],    g_wih1x_l[H3 * H3];     // Wih1[:, 1024:]
__device__ bf16 g_whh1_h[H3 * HID_],   g_whh1_l[H3 * HID_];
__device__ bf16 g_whh2_h[H3 * HID_],   g_whh2_l[H3 * HID_];
__device__ bf16 g_wv_h[HID_ * VD],     g_wv_l[HID_ * VD];
__device__ bf16 g_wih2v_h[H3 * VD],    g_wih2v_l[H3 * VD];     // Wih2[:, :2048]
__device__ bf16 g_w2_h[NTOK * HID_],   g_w2_l[NTOK * HID_];
__device__ bf16 g_wfq_h[HID_ * HID_],  g_wfq_l[HID_ * HID_];
__device__ bf16 g_wf2h_h[H3 * HID_],   g_wf2h_l[H3 * HID_];

// --------------------------- small helpers ---------------------------------
__device__ __forceinline__ void split2(float x, bf16& h, bf16& l) {
    h = __float2bfloat16(x);
    l = __float2bfloat16(x - __bfloat162float(h));
}
__device__ __forceinline__ unsigned smem_u32(const void* p) {
    return (unsigned)__cvta_generic_to_shared(p);
}
__device__ __forceinline__ void cpa16(unsigned dst, const void* src, int sz) {
    asm volatile("cp.async.ca.shared.global [%0], [%1], 16, %2;"
                 :: "r"(dst), "l"(src), "r"(sz));
}

#define LDM_X4(r0, r1, r2, r3, addr) \
    asm volatile("ldmatrix.sync.aligned.m8n8.x4.shared.b16 {%0,%1,%2,%3}, [%4];" \
        : "=r"(r0), "=r"(r1), "=r"(r2), "=r"(r3) : "r"(addr))

#define MMA16816(c, a, b) \
    asm volatile("mma.sync.aligned.m16n8k16.row.col.f32.bf16.bf16.f32 " \
        "{%0,%1,%2,%3}, {%4,%5,%6,%7}, {%8,%9}, {%0,%1,%2,%3};" \
        : "+f"((c)[0]), "+f"((c)[1]), "+f"((c)[2]), "+f"((c)[3]) \
        : "r"((a)[0]), "r"((a)[1]), "r"((a)[2]), "r"((a)[3]), \
          "r"((b)[0]), "r"((b)[1]))

// ----------------------------- tensor GEMM ---------------------------------
// C[m,n] = sum_k A[m,k]*W[n,k] with A = Ahi+Alo, W = Whi+Wlo (bf16 pairs).
// mode 0: +bias store; 1: relu(+bias); 2: masked scatter predict.
// Requires: M % 128 == 0, K % 64 == 0. N arbitrary (tail guarded).
struct TZ {
    const bf16 *Ahi, *Alo, *Whi, *Wlo;
    float* C; const float* bias;
    int lda, ldw, ldc, M, N, K, mode;
};
struct TP { TZ z[3]; const float* mask; };

// per-buffer smem: Ah 16K | Al 16K | Bh BN*128 | Bl BN*128
template<int BN> struct TGC {
    static constexpr int BUF   = 32768 + BN * 256;
    static constexpr int SMEM  = 2 * BUF + 1024;
    static constexpr int THR   = BN * 2;          // 128 or 256
    static constexpr int WN    = BN / 32;         // warps along n
    static constexpr int RPI   = BN / 4;          // loader rows per iteration
    static constexpr int AIT   = 128 / RPI;       // A loader iterations
};

template<int BN>
__global__ void __launch_bounds__(TGC<BN>::THR) tgemm_k(TP p)
{
    const TZ gz = p.z[blockIdx.z];
    const int bn0 = blockIdx.x * BN;  if (bn0 >= gz.N) return;
    const int bm0 = blockIdx.y * 128; if (bm0 >= gz.M) return;
    const int tid = threadIdx.x, wid = tid >> 5, lane = tid & 31;
    const int wm = wid / TGC<BN>::WN, wn = wid % TGC<BN>::WN;

    extern __shared__ char dsm[];
    unsigned dbase = smem_u32(dsm);
    unsigned s0 = (dbase + 1023u) & ~1023u;
    unsigned sAh[2], sAl[2], sBh[2], sBl[2];
#pragma unroll
    for (int b = 0; b < 2; b++) {
        sAh[b] = s0 + b * TGC<BN>::BUF;
        sAl[b] = sAh[b] + 16384;
        sBh[b] = sAl[b] + 16384;
        sBl[b] = sBh[b] + BN * 128;
    }

    // ---- coalesced cp.async chunk loader (BK=64 => 128B per row) ----
    const int lrow = tid >> 3;         // 0..RPI-1
    const int lch  = tid & 7;          // 16B chunk within row
    auto load_chunk = [&](int c, int buf) {
        const int c0 = c * 64;
#pragma unroll
        for (int i = 0; i < TGC<BN>::AIT; i++) {
            int row = i * TGC<BN>::RPI + lrow;
            unsigned off = (unsigned)(row * 128) + (unsigned)(((lch ^ (row & 7)) * 16));
            const bf16* sh = gz.Ahi + (size_t)(bm0 + row) * gz.lda + c0 + lch * 8;
            const bf16* sl = gz.Alo + (size_t)(bm0 + row) * gz.lda + c0 + lch * 8;
            cpa16(sAh[buf] + off, sh, 16);
            cpa16(sAl[buf] + off, sl, 16);
        }
#pragma unroll
        for (int i = 0; i < 4; i++) {
            int row = i * TGC<BN>::RPI + lrow;
            unsigned off = (unsigned)(row * 128) + (unsigned)(((lch ^ (row & 7)) * 16));
            int n = bn0 + row;
            int sz = (n < gz.N) ? 16 : 0;
            int nn = (n < gz.N) ? n : 0;
            const bf16* sh = gz.Whi + (size_t)nn * gz.ldw + c0 + lch * 8;
            const bf16* sl = gz.Wlo + (size_t)nn * gz.ldw + c0 + lch * 8;
            cpa16(sBh[buf] + off, sh, sz);
            cpa16(sBl[buf] + off, sl, sz);
        }
        asm volatile("cp.async.commit_group;");
    };

    float acc[4][4][4];
#pragma unroll
    for (int mi = 0; mi < 4; mi++)
#pragma unroll
        for (int nj = 0; nj < 4; nj++)
#pragma unroll
            for (int e = 0; e < 4; e++) acc[mi][nj][e] = 0.f;

    const int xorkey = lane & 7;
    const int nch = gz.K / 64;
    load_chunk(0, 0);

    for (int c = 0; c < nch; c++) {
        if (c + 1 < nch) {
            load_chunk(c + 1, (c + 1) & 1);
            asm volatile("cp.async.wait_group 1;");
        } else {
            asm volatile("cp.async.wait_group 0;");
        }
        __syncthreads();

        const unsigned tAh = sAh[c & 1], tAl = sAl[c & 1];
        const unsigned tBh = sBh[c & 1], tBl = sBl[c & 1];

#pragma unroll
        for (int ks = 0; ks < 4; ks++) {
            // ---- A fragments: 4 m-frags, hi+lo, ldmatrix.x4 non-trans ----
            unsigned Ah[4][4], Al[4][4];
            {
                const int arow = wm * 64 + (lane & 15);
                const unsigned aoff =
                    (unsigned)((((2 * ks) + (lane >> 4)) ^ xorkey) * 16);
#pragma unroll
                for (int mi = 0; mi < 4; mi++) {
                    unsigned ad = (unsigned)((arow + mi * 16) * 128) + aoff;
                    LDM_X4(Ah[mi][0], Ah[mi][1], Ah[mi][2], Ah[mi][3], tAh + ad);
                    LDM_X4(Al[mi][0], Al[mi][1], Al[mi][2], Al[mi][3], tAl + ad);
                }
            }
            // ---- B fragments: 4 n-frags, hi+lo ----
            unsigned Bh[4][2], Bl[4][2];
            {
                const int brow = wn * 32 + (lane & 7) + ((lane >> 4) << 3);
                const unsigned boff =
                    (unsigned)((((2 * ks) + ((lane >> 3) & 1)) ^ xorkey) * 16);
                unsigned r0, r1, r2, r3;
                unsigned b0 = (unsigned)(brow * 128) + boff;
                LDM_X4(r0, r1, r2, r3, tBh + b0);
                Bh[0][0] = r0; Bh[0][1] = r1; Bh[1][0] = r2; Bh[1][1] = r3;
                LDM_X4(r0, r1, r2, r3, tBh + b0 + 16 * 128);
                Bh[2][0] = r0; Bh[2][1] = r1; Bh[3][0] = r2; Bh[3][1] = r3;
                LDM_X4(r0, r1, r2, r3, tBl + b0);
                Bl[0][0] = r0; Bl[0][1] = r1; Bl[1][0] = r2; Bl[1][1] = r3;
                LDM_X4(r0, r1, r2, r3, tBl + b0 + 16 * 128);
                Bl[2][0] = r0; Bl[2][1] = r1; Bl[3][0] = r2; Bl[3][1] = r3;
            }
            // ---- 48 MMAs: hi*hi + hi*lo + lo*hi ----
#pragma unroll
            for (int mi = 0; mi < 4; mi++)
#pragma unroll
                for (int nj = 0; nj < 4; nj++) {
                    MMA16816(acc[mi][nj], Ah[mi], Bh[nj]);
                    MMA16816(acc[mi][nj], Ah[mi], Bl[nj]);
                    MMA16816(acc[mi][nj], Al[mi], Bh[nj]);
                }
        }
        __syncthreads();
    }

    // ---- epilogue: fragments straight to gmem ----
    const int g = lane >> 2, tig = lane & 3;
    auto stc = [&](int m, int n, float val) {
        if (n >= gz.N) return;
        if (gz.bias) val += gz.bias[n];
        if (gz.mode == 1) val = fmaxf(val, 0.f);
        if (gz.mode == 2) {
            int tt = m / B_, bb = m % B_;
            gz.C[((size_t)bb * MAXLEN + tt) * gz.ldc + n] = val * p.mask[m];
        } else {
            gz.C[(size_t)m * gz.ldc + n] = val;
        }
    };
#pragma unroll
    for (int mi = 0; mi < 4; mi++)
#pragma unroll
        for (int nj = 0; nj < 4; nj++) {
            int row = bm0 + wm * 64 + mi * 16 + g;
            int col = bn0 + wn * 32 + nj * 8 + 2 * tig;
            stc(row,     col,     acc[mi][nj][0]);
            stc(row,     col + 1, acc[mi][nj][1]);
            stc(row + 8, col,     acc[mi][nj][2]);
            stc(row + 8, col + 1, acc[mi][nj][3]);
        }
}

// -------------------- SIMT f32x2 GEMM (NN precompute only) ------------------
__device__ __forceinline__ void ffma2(ull& d, ull a, ull b) {
    asm("fma.rn.f32x2 %0, %1, %2, %0;" : "+l"(d) : "l"(a), "l"(b));
}
__device__ __forceinline__ float2 unpk(ull v) {
    float2 r; asm("mov.b64 {%0, %1}, %2;" : "=f"(r.x), "=f"(r.y) : "l"(v)); return r;
}
struct GemmZ {
    const float* A; const float* W; float* C;
    int lda, ldw, ldc, M, N, K;
};
struct GemmP { GemmZ z[2]; };

static inline GemmZ mkg(const float* A, int lda, const float* W, int ldw,
                        float* C, int ldc, int M, int N, int K)
{
    GemmZ z; z.A = A; z.W = W; z.C = C;
    z.lda = lda; z.ldw = ldw; z.ldc = ldc; z.M = M; z.N = N; z.K = K;
    return z;
}

// NN: C[m,n] = sum_k A[m,k] * W[k,n]
__global__ void __launch_bounds__(256, 2) gemm_nn(GemmP p)
{
    const GemmZ gz = p.z[blockIdx.z];
    const int bn0 = blockIdx.x * 128;
    const int bm0 = blockIdx.y * 128;
    if (bm0 >= gz.M) return;
    const int tid = threadIdx.x;

    __shared__ float As[16][256];
    __shared__ float Bs[16][128];
    const int tx = tid & 15, ty = tid >> 4;

    float4 pa[2], pb[2];
    const float* Abase = gz.A + (size_t)bm0 * gz.lda;
#pragma unroll
    for (int f = 0; f < 2; f++) {
        int q = tid * 2 + f;
        int r = q >> 2, c4 = (q & 3) * 4;
        pa[f] = *(const float4*)(Abase + (size_t)r * gz.lda + c4);
        int rb = q / 32, cb = q % 32;
        pb[f] = *(const float4*)(gz.W + (size_t)rb * gz.ldw + bn0 + cb * 4);
    }

    ull acc[8][4];
#pragma unroll
    for (int i = 0; i < 8; i++)
#pragma unroll
        for (int j = 0; j < 4; j++) acc[i][j] = 0ULL;

    for (int k0 = 0; k0 < gz.K; k0 += 16) {
#pragma unroll
        for (int f = 0; f < 2; f++) {
            int q = tid * 2 + f;
            int r = q >> 2, c4 = (q & 3) * 4;
            As[c4 + 0][2*r] = pa[f].x; As[c4 + 0][2*r+1] = pa[f].x;
            As[c4 + 1][2*r] = pa[f].y; As[c4 + 1][2*r+1] = pa[f].y;
            As[c4 + 2][2*r] = pa[f].z; As[c4 + 2][2*r+1] = pa[f].z;
            As[c4 + 3][2*r] = pa[f].w; As[c4 + 3][2*r+1] = pa[f].w;
            int rb = q / 32, cb = q % 32;
            *(float4*)&Bs[rb][cb * 4] = pb[f];
        }
        __syncthreads();
        if (k0 + 16 < gz.K) {
            const float* An = Abase + (k0 + 16);
            const float* Wn = gz.W + (size_t)(k0 + 16) * gz.ldw;
#pragma unroll
            for (int f = 0; f < 2; f++) {
                int q = tid * 2 + f;
                int r = q >> 2, c4 = (q & 3) * 4;
                pa[f] = *(const float4*)(An + (size_t)r * gz.lda + c4);
                int rb = q / 32, cb = q % 32;
                pb[f] = *(const float4*)(Wn + (size_t)rb * gz.ldw + bn0 + cb * 4);
            }
        }
#pragma unroll
        for (int kk = 0; kk < 16; kk++) {
            ull aa[8], bb[4];
            const float* arow = &As[kk][16 * ty];
            const float* browp = &Bs[kk][8 * tx];
#pragma unroll
            for (int i = 0; i < 8; i++) aa[i] = *(const ull*)(arow + 2 * i);
#pragma unroll
            for (int j = 0; j < 4; j++) bb[j] = *(const ull*)(browp + 2 * j);
#pragma unroll
            for (int i = 0; i < 8; i++)
#pragma unroll
                for (int j = 0; j < 4; j++) ffma2(acc[i][j], aa[i], bb[j]);
        }
        __syncthreads();
    }
#pragma unroll
    for (int i = 0; i < 8; i++) {
        int m = bm0 + ty * 8 + i;
#pragma unroll
        for (int j = 0; j < 4; j++) {
            float2 v = unpk(acc[i][j]);
            int n = bn0 + tx * 8 + 2 * j;
            gz.C[(size_t)m * gz.ldc + n]     = v.x;
            gz.C[(size_t)m * gz.ldc + n + 1] = v.y;
        }
    }
}

// ------------------------------- small kernels -----------------------------
__global__ void meta_kernel(const int* __restrict__ cap_len)
{
    int i = threadIdx.x;
    int ci = cap_len[i];
    int rank = 0;
    for (int j = 0; j < B_; j++) {
        int cj = cap_len[j];
        if (cj > ci || (cj == ci && j < i)) rank++;
    }
    g_order[rank] = i;
    __syncthreads();
    g_dl[i] = cap_len[g_order[i]] - 1;
    __syncthreads();
    int dli = g_dl[i];
    for (int t = 0; t < TT; t++) g_mask[t * B_ + i] = (t < dli) ? 1.f : 0.f;
}

__global__ void zero_init_kernel()
{
    int idx = blockIdx.x * 256 + threadIdx.x;
    if (idx < B_ * HID_) {
        g_h1[idx] = 0.f;    g_h1_h[idx] = __float2bfloat16(0.f); g_h1_l[idx] = __float2bfloat16(0.f);
        g_h2all[idx] = 0.f; g_h2_h[idx] = __float2bfloat16(0.f); g_h2_l[idx] = __float2bfloat16(0.f);
    }
}

__global__ void permute_v_kernel(const float* __restrict__ v)
{
    size_t idx = (size_t)blockIdx.x * 256 + threadIdx.x;
    if (idx >= (size_t)B_ * KOBJ * VD) return;
    int b = (int)(idx / ((size_t)KOBJ * VD));
    size_t rest = idx % ((size_t)KOBJ * VD);
    float x = v[(size_t)g_order[b] * KOBJ * VD + rest];
    g_vs[idx] = x;
    split2(x, g_vs_h[idx], g_vs_l[idx]);
}

__global__ void vmean_kernel()
{
    int idx = blockIdx.x * 256 + threadIdx.x;
    if (idx >= B_ * VD) return;
    int b = idx / VD, d = idx % VD;
    const float* p = g_vs + (size_t)b * KOBJ * VD + d;
    float s = 0.f;
#pragma unroll 6
    for (int k = 0; k < KOBJ; k++) s += p[(size_t)k * VD];
    g_vmean[idx] = s * (1.f / (float)KOBJ);
}

__global__ void build_x1c_kernel(const float* __restrict__ caption)
{
    size_t idx = (size_t)blockIdx.x * 256 + threadIdx.x;
    if (idx >= (size_t)TT * B_ * H3) return;
    int c = (int)(idx % H3);
    int r = (int)(idx / H3);
    int t = r / B_, b = r % B_;
    float val;
    if (c < VD) val = g_vmean[b * VD + c];
    else        val = caption[((size_t)g_order[b] * MAXLEN + t) * EMB + (c - VD)];
    split2(val, g_x1c_h[idx], g_x1c_l[idx]);
}

// generic fp32 -> bf16 hi/lo weight converter (with column offset + stride)
__global__ void convw_kernel(const float* __restrict__ src, int ld, int col0,
                             int rows, int cols, bf16* __restrict__ hi,
                             bf16* __restrict__ lo)
{
    size_t idx = (size_t)blockIdx.x * 256 + threadIdx.x;
    if (idx >= (size_t)rows * cols) return;
    int r = (int)(idx / cols), c = (int)(idx % cols);
    split2(src[(size_t)r * ld + col0 + c], hi[idx], lo[idx]);
}

__global__ void fusebias_kernel(const float* __restrict__ Wq,
                                const float* __restrict__ bq,
                                const float* __restrict__ b1,
                                const float* __restrict__ Wih2,
                                const float* __restrict__ bih2)
{
    int idx = blockIdx.x * 256 + threadIdx.x;
    if (idx < HID_) {
        const float* w = Wq + (size_t)idx * HID_;
        float s = 0.f;
        for (int j = 0; j < HID_; j++) s += w[j] * b1[j];
        g_bfq[idx] = s + bq[idx];
    } else if (idx < HID_ + H3) {
        int n = idx - HID_;
        const float* w = Wih2 + (size_t)n * H3 + VD;
        float s = 0.f;
        for (int j = 0; j < HID_; j++) s += w[j] * b1[j];
        g_bi2f[n] = s + bih2[n];
    }
}

// GRU pointwise; writes hout fp32 and bf16 hi/lo copies.
__global__ void gru_kernel(const float* __restrict__ gia,
                           const float* __restrict__ gib,
                           const float* __restrict__ biv,
                           const float* __restrict__ gh,
                           const float* __restrict__ hprev,
                           float* __restrict__ hout,
                           bf16* __restrict__ hout_h,
                           bf16* __restrict__ hout_l)
{
    int idx = blockIdx.x * 256 + threadIdx.x;
    if (idx >= B_ * HID_) return;
    int b = idx >> 10, j = idx & 1023;
    size_t base = (size_t)b * H3 + j;
    float gr = gia[base]            + gib[base];
    float gz = gia[base + HID_]     + gib[base + HID_];
    float gn = gia[base + 2 * HID_] + gib[base + 2 * HID_];
    if (biv) {
        gr += biv[j]; gz += biv[j + HID_]; gn += biv[j + 2 * HID_];
    }
    float r = 1.f / (1.f + expf(-(gr + gh[base])));
    float z = 1.f / (1.f + expf(-(gz + gh[base + HID_])));
    float n = tanhf(gn + r * gh[base + 2 * HID_]);
    float h = (1.f - z) * n + z * hprev[idx];
    hout[idx] = h;
    split2(h, hout_h[idx], hout_l[idx]);
}

// Attention: logits = vproj . (q*wa) + ba; softmax; masked alphas;
// att_v -> bf16 hi/lo.
__global__ void att_kernel(const float* __restrict__ wa,
                           const float* __restrict__ ba,
                           float* __restrict__ alphas, int t)
{
    int b = blockIdx.x, tid = threadIdx.x;
    __shared__ float qs[HID_];
    __shared__ float att[KOBJ];
    for (int d = tid; d < HID_; d += 256) qs[d] = g_q[b * HID_ + d] * wa[d];
    __syncthreads();

    int warp = tid >> 5, lane = tid & 31;
    for (int k = warp; k < KOBJ; k += 8) {
        const float* vp = g_vproj + ((size_t)b * KOBJ + k) * HID_;
        float s = 0.f;
        for (int d = lane; d < HID_; d += 32) s += vp[d] * qs[d];
#pragma unroll
        for (int o = 16; o; o >>= 1) s += __shfl_down_sync(0xffffffffu, s, o);
        if (lane == 0) att[k] = s + ba[0];
    }
    __syncthreads();

    if (tid == 0) {
        float mx = att[0];
        for (int k = 1; k < KOBJ; k++) mx = fmaxf(mx, att[k]);
        float ssum = 0.f;
        for (int k = 0; k < KOBJ; k++) { float e = expf(att[k] - mx); att[k] = e; ssum += e; }
        float inv = 1.f / ssum;
        for (int k = 0; k < KOBJ; k++) att[k] *= inv;
    }
    __syncthreads();

    if (tid < KOBJ) {
        float m = (t < g_dl[b]) ? 1.f : 0.f;
        alphas[((size_t)b * MAXLEN + t) * KOBJ + tid] = att[tid] * m;
    }
    for (int d = tid; d < VD; d += 256) {
        const float* vb = g_vs + (size_t)b * KOBJ * VD + d;
        float s = 0.f;
#pragma unroll 6
        for (int k = 0; k < KOBJ; k++) s += att[k] * vb[(size_t)k * VD];
        split2(s, g_attv_h[b * VD + d], g_attv_l[b * VD + d]);
    }
}

__global__ void zero_tails_kernel(float* __restrict__ predict,
                                  float* __restrict__ alphas)
{
    int idx = blockIdx.x * 256 + threadIdx.x;
    if (idx < B_ * NTOK) {
        int b = idx / NTOK, n = idx % NTOK;
        predict[((size_t)b * MAXLEN + (MAXLEN - 1)) * NTOK + n] = 0.f;
    } else if (idx < B_ * NTOK + B_ * KOBJ) {
        int r = idx - B_ * NTOK;
        int b = r / KOBJ, k = r % KOBJ;
        alphas[((size_t)b * MAXLEN + (MAXLEN - 1)) * KOBJ + k] = 0.f;
    }
}

// --------------------------------- launch ----------------------------------
static inline TZ mkt(const bf16* Ah, const bf16* Al, int lda,
                     const bf16* Wh, const bf16* Wl, int ldw,
                     float* C, int ldc, int M, int N, int K,
                     const float* bias, int mode)
{
    TZ z; z.Ahi = Ah; z.Alo = Al; z.Whi = Wh; z.Wlo = Wl;
    z.C = C; z.bias = bias; z.lda = lda; z.ldw = ldw; z.ldc = ldc;
    z.M = M; z.N = N; z.K = K; z.mode = mode;
    return z;
}

#define SYMADDR(var, sym) cudaGetSymbolAddress((void**)&var, sym)

extern "C" void kernel_launch(void* const* d_in, const int* in_sizes, int n_in,
                              void* d_out, int out_size)
{
    const float* v       = (const float*)d_in[0];
    const float* caption = (const float*)d_in[1];
    const int*   cap_len = (const int*)  d_in[2];
    const float* Wih1    = (const float*)d_in[3];
    const float* Whh1    = (const float*)d_in[4];
    const float* bih1    = (const float*)d_in[5];
    const float* bhh1    = (const float*)d_in[6];
    const float* Wih2    = (const float*)d_in[7];
    const float* Whh2    = (const float*)d_in[8];
    const float* bih2    = (const float*)d_in[9];
    const float* bhh2    = (const float*)d_in[10];
    const float* Wv      = (const float*)d_in[11];
    const float* bv      = (const float*)d_in[12];
    const float* Wq      = (const float*)d_in[13];
    const float* bq      = (const float*)d_in[14];
    const float* wa      = (const float*)d_in[15];
    const float* ba      = (const float*)d_in[16];
    const float* W1      = (const float*)d_in[17];
    const float* b1      = (const float*)d_in[18];
    const float* W2      = (const float*)d_in[19];
    const float* b2      = (const float*)d_in[20];

    float* out     = (float*)d_out;
    float* predict = out;
    float* alphas  = out + (size_t)B_ * MAXLEN * NTOK;

    // fp32 scratch addresses
    float *p_gi1c, *p_h1, *p_h2all, *p_gih, *p_gh1, *p_gh2, *p_q, *p_gi2h;
    float *p_p0, *p_Wfq, *p_Wf2h, *p_bfq, *p_bi2f, *p_mask, *p_vproj;
    SYMADDR(p_gi1c, g_gi1c);   SYMADDR(p_h1, g_h1);     SYMADDR(p_h2all, g_h2all);
    SYMADDR(p_gih, g_gih);     SYMADDR(p_gh1, g_gh1);   SYMADDR(p_gh2, g_gh2);
    SYMADDR(p_q, g_q);         SYMADDR(p_gi2h, g_gi2h); SYMADDR(p_p0, g_p0);
    SYMADDR(p_Wfq, g_Wfq);     SYMADDR(p_Wf2h, g_Wf2h); SYMADDR(p_bfq, g_bfq);
    SYMADDR(p_bi2f, g_bi2f);   SYMADDR(p_mask, g_mask); SYMADDR(p_vproj, g_vproj);

    // bf16 operand addresses
    bf16 *vs_h, *vs_l, *x1c_h, *x1c_l, *h1_h, *h1_l, *h2_h, *h2_l, *av_h, *av_l;
    bf16 *w1h_h, *w1h_l, *w1x_h, *w1x_l, *wh1_h, *wh1_l, *wh2_h, *wh2_l;
    bf16 *wv_h, *wv_l, *w2v_h, *w2v_l, *ww2_h, *ww2_l, *wfq_h, *wfq_l, *wf2_h, *wf2_l;
    SYMADDR(vs_h, g_vs_h);   SYMADDR(vs_l, g_vs_l);
    SYMADDR(x1c_h, g_x1c_h); SYMADDR(x1c_l, g_x1c_l);
    SYMADDR(h1_h, g_h1_h);   SYMADDR(h1_l, g_h1_l);
    SYMADDR(h2_h, g_h2_h);   SYMADDR(h2_l, g_h2_l);
    SYMADDR(av_h, g_attv_h); SYMADDR(av_l, g_attv_l);
    SYMADDR(w1h_h, g_wih1h_h); SYMADDR(w1h_l, g_wih1h_l);
    SYMADDR(w1x_h, g_wih1x_h); SYMADDR(w1x_l, g_wih1x_l);
    SYMADDR(wh1_h, g_whh1_h);  SYMADDR(wh1_l, g_whh1_l);
    SYMADDR(wh2_h, g_whh2_h);  SYMADDR(wh2_l, g_whh2_l);
    SYMADDR(wv_h, g_wv_h);     SYMADDR(wv_l, g_wv_l);
    SYMADDR(w2v_h, g_wih2v_h); SYMADDR(w2v_l, g_wih2v_l);
    SYMADDR(ww2_h, g_w2_h);    SYMADDR(ww2_l, g_w2_l);
    SYMADDR(wfq_h, g_wfq_h);   SYMADDR(wfq_l, g_wfq_l);
    SYMADDR(wf2_h, g_wf2h_h);  SYMADDR(wf2_l, g_wf2h_l);

    cudaFuncSetAttribute(tgemm_k<64>,  cudaFuncAttributeMaxDynamicSharedMemorySize,
                         TGC<64>::SMEM);
    cudaFuncSetAttribute(tgemm_k<128>, cudaFuncAttributeMaxDynamicSharedMemorySize,
                         TGC<128>::SMEM);

    auto cv = [](const float* s, int ld, int c0, int r, int c, bf16* h, bf16* l) {
        size_t n = (size_t)r * c;
        convw_kernel<<<(unsigned)((n + 255) / 256), 256>>>(s, ld, c0, r, c, h, l);
    };

    // ---- setup (launch #6 = gi1c big GEMM, for ncu -s 5 -c 1) ----
    meta_kernel<<<1, B_>>>(cap_len);                                      // 1
    permute_v_kernel<<<(unsigned)(((size_t)B_*KOBJ*VD + 255)/256), 256>>>(v); // 2
    vmean_kernel<<<(B_ * VD + 255) / 256, 256>>>();                       // 3
    build_x1c_kernel<<<(unsigned)(((size_t)TT*B_*H3 + 255)/256), 256>>>(caption); // 4
    cv(Wih1, HID_ + VD + EMB, 1024, H3, H3, w1x_h, w1x_l);                // 5
    {   // 6: gi1c = X1c @ Wih1[:,1024:].T + bih1   [2432 x 3072 x K=3072]
        TP P{}; P.mask = nullptr;
        P.z[0] = mkt(x1c_h, x1c_l, H3, w1x_h, w1x_l, H3,
                     p_gi1c, H3, TT * B_, H3, H3, bih1, 0);
        tgemm_k<128><<<dim3(H3/128, (TT*B_)/128, 1), TGC<128>::THR, TGC<128>::SMEM>>>(P);
    }
    zero_init_kernel<<<(B_ * HID_ + 255) / 256, 256>>>();
    // remaining weight conversions
    cv(Wih1, HID_ + VD + EMB, 0,    H3,   HID_, w1h_h, w1h_l);
    cv(Whh1, HID_,            0,    H3,   HID_, wh1_h, wh1_l);
    cv(Whh2, HID_,            0,    H3,   HID_, wh2_h, wh2_l);
    cv(Wv,   VD,              0,    HID_, VD,   wv_h,  wv_l);
    cv(Wih2, H3,              0,    H3,   VD,   w2v_h, w2v_l);
    cv(W2,   HID_,            0,    NTOK, HID_, ww2_h, ww2_l);
    // precompute fused weights (SIMT NN), then convert + fused biases
    {
        GemmP P{};
        P.z[0] = mkg(Wq,        HID_, W1, HID_, p_Wfq,  HID_, HID_, HID_, HID_);
        P.z[1] = mkg(Wih2 + VD, H3,   W1, HID_, p_Wf2h, HID_, H3,   HID_, HID_);
        gemm_nn<<<dim3(HID_/128, H3/128, 2), 256>>>(P);
    }
    cv(p_Wfq,  HID_, 0, HID_, HID_, wfq_h, wfq_l);
    cv(p_Wf2h, HID_, 0, H3,   HID_, wf2_h, wf2_l);
    fusebias_kernel<<<(HID_ + H3 + 255) / 256, 256>>>(Wq, bq, b1, Wih2, bih2);

    {   // vproj = relu(v_s @ Wv.T + bv)         [4608 x 1024 x K=2048]
        TP P{}; P.mask = nullptr;
        P.z[0] = mkt(vs_h, vs_l, VD, wv_h, wv_l, VD,
                     p_vproj, HID_, B_ * KOBJ, HID_, VD, bv, 1);
        tgemm_k<128><<<dim3(HID_/128, (B_*KOBJ)/128, 1), TGC<128>::THR, TGC<128>::SMEM>>>(P);
    }

    // ---- sequential decode ----
    const int gruBlocks = (B_ * HID_ + 255) / 256;
    for (int t = 0; t < TT; t++) {
        const bf16* h2p_h = h2_h + (size_t)t * B_ * HID_;
        const bf16* h2p_l = h2_l + (size_t)t * B_ * HID_;
        const float* h2prev = p_h2all + (size_t)t * B_ * HID_;
        float*       h2next = p_h2all + (size_t)(t + 1) * B_ * HID_;

        // stage1: gih = h2@Wih1h.T ; gh1 = h1@Whh1.T+bhh1 ; gh2 = h2@Whh2.T+bhh2
        {
            TP P{}; P.mask = nullptr;
            P.z[0] = mkt(h2p_h, h2p_l, HID_, w1h_h, w1h_l, HID_,
                         p_gih, H3, B_, H3, HID_, nullptr, 0);
            P.z[1] = mkt(h1_h, h1_l, HID_, wh1_h, wh1_l, HID_,
                         p_gh1, H3, B_, H3, HID_, bhh1, 0);
            P.z[2] = mkt(h2p_h, h2p_l, HID_, wh2_h, wh2_l, HID_,
                         p_gh2, H3, B_, H3, HID_, bhh2, 0);
            tgemm_k<64><<<dim3(H3/64, 1, 3), TGC<64>::THR, TGC<64>::SMEM>>>(P);
        }
        // GRU1 (h1 in place, + bf16 split out)
        gru_kernel<<<gruBlocks, 256>>>(p_gi1c + (size_t)t * B_ * H3, p_gih,
                                       nullptr, p_gh1, p_h1, p_h1, h1_h, h1_l);
        // stage2: q = relu(h1@Wfq.T + bfq) ; gi2h = h1@Wf2h.T
        {
            TP P{}; P.mask = nullptr;
            P.z[0] = mkt(h1_h, h1_l, HID_, wfq_h, wfq_l, HID_,
                         p_q, HID_, B_, HID_, HID_, p_bfq, 1);
            P.z[1] = mkt(h1_h, h1_l, HID_, wf2_h, wf2_l, HID_,
                         p_gi2h, H3, B_, H3, HID_, nullptr, 0);
            tgemm_k<64><<<dim3(H3/64, 1, 2), TGC<64>::THR, TGC<64>::SMEM>>>(P);
        }
        // attention
        att_kernel<<<B_, 256>>>(wa, ba, alphas, t);
        // gi2_att = att_v @ Wih2[:,:2048].T    [128 x 3072 x K=2048]
        {
            TP P{}; P.mask = nullptr;
            P.z[0] = mkt(av_h, av_l, VD, w2v_h, w2v_l, VD,
                         p_p0, H3, B_, H3, VD, nullptr, 0);
            tgemm_k<64><<<dim3(H3/64, 1, 1), TGC<64>::THR, TGC<64>::SMEM>>>(P);
        }
        // GRU2
        gru_kernel<<<gruBlocks, 256>>>(p_p0, p_gi2h, p_bi2f, p_gh2, h2prev,
                                       h2next,
                                       h2_h + (size_t)(t+1) * B_ * HID_,
                                       h2_l + (size_t)(t+1) * B_ * HID_);
    }

    // words = H2all @ W2.T + b2 (masked scatter)  [2432 x 10000 x K=1024]
    {
        TP P{}; P.mask = p_mask;
        P.z[0] = mkt(h2_h + B_ * HID_, h2_l + B_ * HID_, HID_,
                     ww2_h, ww2_l, HID_,
                     predict, NTOK, TT * B_, NTOK, HID_, b2, 2);
        tgemm_k<128><<<dim3((NTOK + 127) / 128, (TT*B_)/128, 1),
                       TGC<128>::THR, TGC<128>::SMEM>>>(P);
    }
    zero_tails_kernel<<<(B_ * NTOK + B_ * KOBJ + 255) / 256, 256>>>(predict, alphas);
}

// round 9
// speedup vs baseline: 1.2245x; 1.2245x over previous
#include <cuda_runtime.h>
#include <cuda_bf16.h>
#include <math.h>

// ---------------------------------------------------------------------------
// BUTDDecoder: B=128, K=36, V_DIM=2048, EMBED=1024, HID=1024, NTOKEN=10000,
// MAX_LEN=20 (T=19 decode steps).
//
// Round 9: split-K (512-wide slices) for all sequential-loop GEMMs; GRU/att
// pointwise kernels absorb the partial-sum reduction. Launch #6 is the real
// t=0 stage1 skinny GEMM so ncu profiles the loop GEMM class.
// ---------------------------------------------------------------------------

#define B_     128
#define KOBJ   36
#define VD     2048
#define EMB    1024
#define HID_   1024
#define NTOK   10000
#define MAXLEN 20
#define TT     19
#define H3     3072

typedef unsigned long long ull;
typedef __nv_bfloat16 bf16;

// ------------------------- scratch (device globals) ------------------------
__device__ float g_vs[B_ * KOBJ * VD];
__device__ float g_vmean[B_ * VD];
__device__ float g_vproj[B_ * KOBJ * HID_];
__device__ float g_gi1c[TT * B_ * H3];
__device__ float g_h1[B_ * HID_];
__device__ float g_h2all[(TT + 1) * B_ * HID_];
__device__ float g_gihA[B_ * H3], g_gihB[B_ * H3];
__device__ float g_gh1A[B_ * H3], g_gh1B[B_ * H3];
__device__ float g_gh2A[B_ * H3], g_gh2B[B_ * H3];
__device__ float g_qA[B_ * HID_], g_qB[B_ * HID_];
__device__ float g_gi2hA[B_ * H3], g_gi2hB[B_ * H3];
__device__ float g_p0A[B_ * H3], g_p0B[B_ * H3], g_p0C[B_ * H3], g_p0D[B_ * H3];
__device__ float g_Wfq[HID_ * HID_];     // Wq @ W1 (fp32, SIMT precompute)
__device__ float g_Wf2h[H3 * HID_];      // Wih2[:,2048:] @ W1
__device__ float g_bfq[HID_];            // Wq@b1 + bq
__device__ float g_bi2f[H3];             // Wih2[:,2048:]@b1 + bih2
__device__ int   g_order[B_];
__device__ int   g_dl[B_];
__device__ float g_mask[TT * B_];

// bf16 hi/lo operand arrays (activations)
__device__ bf16 g_vs_h[B_ * KOBJ * VD],        g_vs_l[B_ * KOBJ * VD];
__device__ bf16 g_x1c_h[TT * B_ * H3],         g_x1c_l[TT * B_ * H3];
__device__ bf16 g_h1_h[B_ * HID_],             g_h1_l[B_ * HID_];
__device__ bf16 g_h2_h[(TT + 1) * B_ * HID_],  g_h2_l[(TT + 1) * B_ * HID_];
__device__ bf16 g_attv_h[B_ * VD],             g_attv_l[B_ * VD];

// bf16 hi/lo weight arrays
__device__ bf16 g_wih1h_h[H3 * HID_],  g_wih1h_l[H3 * HID_];   // Wih1[:, :1024]
__device__ bf16 g_wih1x_h[H3 * H3],    g_wih1x_l[H3 * H3];     // Wih1[:, 1024:]
__device__ bf16 g_whh1_h[H3 * HID_],   g_whh1_l[H3 * HID_];
__device__ bf16 g_whh2_h[H3 * HID_],   g_whh2_l[H3 * HID_];
__device__ bf16 g_wv_h[HID_ * VD],     g_wv_l[HID_ * VD];
__device__ bf16 g_wih2v_h[H3 * VD],    g_wih2v_l[H3 * VD];     // Wih2[:, :2048]
__device__ bf16 g_w2_h[NTOK * HID_],   g_w2_l[NTOK * HID_];
__device__ bf16 g_wfq_h[HID_ * HID_],  g_wfq_l[HID_ * HID_];
__device__ bf16 g_wf2h_h[H3 * HID_],   g_wf2h_l[H3 * HID_];

// --------------------------- small helpers ---------------------------------
__device__ __forceinline__ void split2(float x, bf16& h, bf16& l) {
    h = __float2bfloat16(x);
    l = __float2bfloat16(x - __bfloat162float(h));
}
__device__ __forceinline__ unsigned smem_u32(const void* p) {
    return (unsigned)__cvta_generic_to_shared(p);
}
__device__ __forceinline__ void cpa16(unsigned dst, const void* src, int sz) {
    asm volatile("cp.async.ca.shared.global [%0], [%1], 16, %2;"
                 :: "r"(dst), "l"(src), "r"(sz));
}

#define LDM_X4(r0, r1, r2, r3, addr) \
    asm volatile("ldmatrix.sync.aligned.m8n8.x4.shared.b16 {%0,%1,%2,%3}, [%4];" \
        : "=r"(r0), "=r"(r1), "=r"(r2), "=r"(r3) : "r"(addr))

#define MMA16816(c, a, b) \
    asm volatile("mma.sync.aligned.m16n8k16.row.col.f32.bf16.bf16.f32 " \
        "{%0,%1,%2,%3}, {%4,%5,%6,%7}, {%8,%9}, {%0,%1,%2,%3};" \
        : "+f"((c)[0]), "+f"((c)[1]), "+f"((c)[2]), "+f"((c)[3]) \
        : "r"((a)[0]), "r"((a)[1]), "r"((a)[2]), "r"((a)[3]), \
          "r"((b)[0]), "r"((b)[1]))

// ----------------------------- tensor GEMM ---------------------------------
// C[m,n] = sum_k A[m,k]*W[n,k] with A = Ahi+Alo, W = Whi+Wlo (bf16 pairs).
// mode 0: +bias store; 1: relu(+bias); 2: masked scatter predict.
// Requires: M % 128 == 0, K % 64 == 0. N arbitrary (tail guarded).
struct TZ {
    const bf16 *Ahi, *Alo, *Whi, *Wlo;
    float* C; const float* bias;
    int lda, ldw, ldc, M, N, K, mode;
};
struct TP { TZ z[6]; const float* mask; };

// per-buffer smem: Ah 16K | Al 16K | Bh BN*128 | Bl BN*128
template<int BN> struct TGC {
    static constexpr int BUF   = 32768 + BN * 256;
    static constexpr int SMEM  = 2 * BUF + 1024;
    static constexpr int THR   = BN * 2;          // 128 or 256
    static constexpr int WN    = BN / 32;         // warps along n
    static constexpr int RPI   = BN / 4;          // loader rows per iteration
    static constexpr int AIT   = 128 / RPI;       // A loader iterations
};

template<int BN>
__global__ void __launch_bounds__(TGC<BN>::THR) tgemm_k(TP p)
{
    const TZ gz = p.z[blockIdx.z];
    const int bn0 = blockIdx.x * BN;  if (bn0 >= gz.N) return;
    const int bm0 = blockIdx.y * 128; if (bm0 >= gz.M) return;
    const int tid = threadIdx.x, wid = tid >> 5, lane = tid & 31;
    const int wm = wid / TGC<BN>::WN, wn = wid % TGC<BN>::WN;

    extern __shared__ char dsm[];
    unsigned dbase = smem_u32(dsm);
    unsigned s0 = (dbase + 1023u) & ~1023u;
    unsigned sAh[2], sAl[2], sBh[2], sBl[2];
#pragma unroll
    for (int b = 0; b < 2; b++) {
        sAh[b] = s0 + b * TGC<BN>::BUF;
        sAl[b] = sAh[b] + 16384;
        sBh[b] = sAl[b] + 16384;
        sBl[b] = sBh[b] + BN * 128;
    }

    // ---- coalesced cp.async chunk loader (BK=64 => 128B per row) ----
    const int lrow = tid >> 3;         // 0..RPI-1
    const int lch  = tid & 7;          // 16B chunk within row
    auto load_chunk = [&](int c, int buf) {
        const int c0 = c * 64;
#pragma unroll
        for (int i = 0; i < TGC<BN>::AIT; i++) {
            int row = i * TGC<BN>::RPI + lrow;
            unsigned off = (unsigned)(row * 128) + (unsigned)(((lch ^ (row & 7)) * 16));
            const bf16* sh = gz.Ahi + (size_t)(bm0 + row) * gz.lda + c0 + lch * 8;
            const bf16* sl = gz.Alo + (size_t)(bm0 + row) * gz.lda + c0 + lch * 8;
            cpa16(sAh[buf] + off, sh, 16);
            cpa16(sAl[buf] + off, sl, 16);
        }
#pragma unroll
        for (int i = 0; i < 4; i++) {
            int row = i * TGC<BN>::RPI + lrow;
            unsigned off = (unsigned)(row * 128) + (unsigned)(((lch ^ (row & 7)) * 16));
            int n = bn0 + row;
            int sz = (n < gz.N) ? 16 : 0;
            int nn = (n < gz.N) ? n : 0;
            const bf16* sh = gz.Whi + (size_t)nn * gz.ldw + c0 + lch * 8;
            const bf16* sl = gz.Wlo + (size_t)nn * gz.ldw + c0 + lch * 8;
            cpa16(sBh[buf] + off, sh, sz);
            cpa16(sBl[buf] + off, sl, sz);
        }
        asm volatile("cp.async.commit_group;");
    };

    float acc[4][4][4];
#pragma unroll
    for (int mi = 0; mi < 4; mi++)
#pragma unroll
        for (int nj = 0; nj < 4; nj++)
#pragma unroll
            for (int e = 0; e < 4; e++) acc[mi][nj][e] = 0.f;

    const int xorkey = lane & 7;
    const int nch = gz.K / 64;
    load_chunk(0, 0);

    for (int c = 0; c < nch; c++) {
        if (c + 1 < nch) {
            load_chunk(c + 1, (c + 1) & 1);
            asm volatile("cp.async.wait_group 1;");
        } else {
            asm volatile("cp.async.wait_group 0;");
        }
        __syncthreads();

        const unsigned tAh = sAh[c & 1], tAl = sAl[c & 1];
        const unsigned tBh = sBh[c & 1], tBl = sBl[c & 1];

#pragma unroll
        for (int ks = 0; ks < 4; ks++) {
            // ---- A fragments: 4 m-frags, hi+lo, ldmatrix.x4 non-trans ----
            unsigned Ah[4][4], Al[4][4];
            {
                const int arow = wm * 64 + (lane & 15);
                const unsigned aoff =
                    (unsigned)((((2 * ks) + (lane >> 4)) ^ xorkey) * 16);
#pragma unroll
                for (int mi = 0; mi < 4; mi++) {
                    unsigned ad = (unsigned)((arow + mi * 16) * 128) + aoff;
                    LDM_X4(Ah[mi][0], Ah[mi][1], Ah[mi][2], Ah[mi][3], tAh + ad);
                    LDM_X4(Al[mi][0], Al[mi][1], Al[mi][2], Al[mi][3], tAl + ad);
                }
            }
            // ---- B fragments: 4 n-frags, hi+lo ----
            unsigned Bh[4][2], Bl[4][2];
            {
                const int brow = wn * 32 + (lane & 7) + ((lane >> 4) << 3);
                const unsigned boff =
                    (unsigned)((((2 * ks) + ((lane >> 3) & 1)) ^ xorkey) * 16);
                unsigned r0, r1, r2, r3;
                unsigned b0 = (unsigned)(brow * 128) + boff;
                LDM_X4(r0, r1, r2, r3, tBh + b0);
                Bh[0][0] = r0; Bh[0][1] = r1; Bh[1][0] = r2; Bh[1][1] = r3;
                LDM_X4(r0, r1, r2, r3, tBh + b0 + 16 * 128);
                Bh[2][0] = r0; Bh[2][1] = r1; Bh[3][0] = r2; Bh[3][1] = r3;
                LDM_X4(r0, r1, r2, r3, tBl + b0);
                Bl[0][0] = r0; Bl[0][1] = r1; Bl[1][0] = r2; Bl[1][1] = r3;
                LDM_X4(r0, r1, r2, r3, tBl + b0 + 16 * 128);
                Bl[2][0] = r0; Bl[2][1] = r1; Bl[3][0] = r2; Bl[3][1] = r3;
            }
            // ---- 48 MMAs: hi*hi + hi*lo + lo*hi ----
#pragma unroll
            for (int mi = 0; mi < 4; mi++)
#pragma unroll
                for (int nj = 0; nj < 4; nj++) {
                    MMA16816(acc[mi][nj], Ah[mi], Bh[nj]);
                    MMA16816(acc[mi][nj], Ah[mi], Bl[nj]);
                    MMA16816(acc[mi][nj], Al[mi], Bh[nj]);
                }
        }
        __syncthreads();
    }

    // ---- epilogue: fragments straight to gmem ----
    const int g = lane >> 2, tig = lane & 3;
    auto stc = [&](int m, int n, float val) {
        if (n >= gz.N) return;
        if (gz.bias) val += gz.bias[n];
        if (gz.mode == 1) val = fmaxf(val, 0.f);
        if (gz.mode == 2) {
            int tt = m / B_, bb = m % B_;
            gz.C[((size_t)bb * MAXLEN + tt) * gz.ldc + n] = val * p.mask[m];
        } else {
            gz.C[(size_t)m * gz.ldc + n] = val;
        }
    };
#pragma unroll
    for (int mi = 0; mi < 4; mi++)
#pragma unroll
        for (int nj = 0; nj < 4; nj++) {
            int row = bm0 + wm * 64 + mi * 16 + g;
            int col = bn0 + wn * 32 + nj * 8 + 2 * tig;
            stc(row,     col,     acc[mi][nj][0]);
            stc(row,     col + 1, acc[mi][nj][1]);
            stc(row + 8, col,     acc[mi][nj][2]);
            stc(row + 8, col + 1, acc[mi][nj][3]);
        }
}

// -------------------- SIMT f32x2 GEMM (NN precompute only) ------------------
__device__ __forceinline__ void ffma2(ull& d, ull a, ull b) {
    asm("fma.rn.f32x2 %0, %1, %2, %0;" : "+l"(d) : "l"(a), "l"(b));
}
__device__ __forceinline__ float2 unpk(ull v) {
    float2 r; asm("mov.b64 {%0, %1}, %2;" : "=f"(r.x), "=f"(r.y) : "l"(v)); return r;
}
struct GemmZ {
    const float* A; const float* W; float* C;
    int lda, ldw, ldc, M, N, K;
};
struct GemmP { GemmZ z[2]; };

static inline GemmZ mkg(const float* A, int lda, const float* W, int ldw,
                        float* C, int ldc, int M, int N, int K)
{
    GemmZ z; z.A = A; z.W = W; z.C = C;
    z.lda = lda; z.ldw = ldw; z.ldc = ldc; z.M = M; z.N = N; z.K = K;
    return z;
}

// NN: C[m,n] = sum_k A[m,k] * W[k,n]
__global__ void __launch_bounds__(256, 2) gemm_nn(GemmP p)
{
    const GemmZ gz = p.z[blockIdx.z];
    const int bn0 = blockIdx.x * 128;
    const int bm0 = blockIdx.y * 128;
    if (bm0 >= gz.M) return;
    const int tid = threadIdx.x;

    __shared__ float As[16][256];
    __shared__ float Bs[16][128];
    const int tx = tid & 15, ty = tid >> 4;

    float4 pa[2], pb[2];
    const float* Abase = gz.A + (size_t)bm0 * gz.lda;
#pragma unroll
    for (int f = 0; f < 2; f++) {
        int q = tid * 2 + f;
        int r = q >> 2, c4 = (q & 3) * 4;
        pa[f] = *(const float4*)(Abase + (size_t)r * gz.lda + c4);
        int rb = q / 32, cb = q % 32;
        pb[f] = *(const float4*)(gz.W + (size_t)rb * gz.ldw + bn0 + cb * 4);
    }

    ull acc[8][4];
#pragma unroll
    for (int i = 0; i < 8; i++)
#pragma unroll
        for (int j = 0; j < 4; j++) acc[i][j] = 0ULL;

    for (int k0 = 0; k0 < gz.K; k0 += 16) {
#pragma unroll
        for (int f = 0; f < 2; f++) {
            int q = tid * 2 + f;
            int r = q >> 2, c4 = (q & 3) * 4;
            As[c4 + 0][2*r] = pa[f].x; As[c4 + 0][2*r+1] = pa[f].x;
            As[c4 + 1][2*r] = pa[f].y; As[c4 + 1][2*r+1] = pa[f].y;
            As[c4 + 2][2*r] = pa[f].z; As[c4 + 2][2*r+1] = pa[f].z;
            As[c4 + 3][2*r] = pa[f].w; As[c4 + 3][2*r+1] = pa[f].w;
            int rb = q / 32, cb = q % 32;
            *(float4*)&Bs[rb][cb * 4] = pb[f];
        }
        __syncthreads();
        if (k0 + 16 < gz.K) {
            const float* An = Abase + (k0 + 16);
            const float* Wn = gz.W + (size_t)(k0 + 16) * gz.ldw;
#pragma unroll
            for (int f = 0; f < 2; f++) {
                int q = tid * 2 + f;
                int r = q >> 2, c4 = (q & 3) * 4;
                pa[f] = *(const float4*)(An + (size_t)r * gz.lda + c4);
                int rb = q / 32, cb = q % 32;
                pb[f] = *(const float4*)(Wn + (size_t)rb * gz.ldw + bn0 + cb * 4);
            }
        }
#pragma unroll
        for (int kk = 0; kk < 16; kk++) {
            ull aa[8], bb[4];
            const float* arow = &As[kk][16 * ty];
            const float* browp = &Bs[kk][8 * tx];
#pragma unroll
            for (int i = 0; i < 8; i++) aa[i] = *(const ull*)(arow + 2 * i);
#pragma unroll
            for (int j = 0; j < 4; j++) bb[j] = *(const ull*)(browp + 2 * j);
#pragma unroll
            for (int i = 0; i < 8; i++)
#pragma unroll
                for (int j = 0; j < 4; j++) ffma2(acc[i][j], aa[i], bb[j]);
        }
        __syncthreads();
    }
#pragma unroll
    for (int i = 0; i < 8; i++) {
        int m = bm0 + ty * 8 + i;
#pragma unroll
        for (int j = 0; j < 4; j++) {
            float2 v = unpk(acc[i][j]);
            int n = bn0 + tx * 8 + 2 * j;
            gz.C[(size_t)m * gz.ldc + n]     = v.x;
            gz.C[(size_t)m * gz.ldc + n + 1] = v.y;
        }
    }
}

// ------------------------------- small kernels -----------------------------
__global__ void meta_kernel(const int* __restrict__ cap_len)
{
    int i = threadIdx.x;
    int ci = cap_len[i];
    int rank = 0;
    for (int j = 0; j < B_; j++) {
        int cj = cap_len[j];
        if (cj > ci || (cj == ci && j < i)) rank++;
    }
    g_order[rank] = i;
    __syncthreads();
    g_dl[i] = cap_len[g_order[i]] - 1;
    __syncthreads();
    int dli = g_dl[i];
    for (int t = 0; t < TT; t++) g_mask[t * B_ + i] = (t < dli) ? 1.f : 0.f;
}

__global__ void zero_init_kernel()
{
    int idx = blockIdx.x * 256 + threadIdx.x;
    if (idx < B_ * HID_) {
        g_h1[idx] = 0.f;    g_h1_h[idx] = __float2bfloat16(0.f); g_h1_l[idx] = __float2bfloat16(0.f);
        g_h2all[idx] = 0.f; g_h2_h[idx] = __float2bfloat16(0.f); g_h2_l[idx] = __float2bfloat16(0.f);
    }
}

__global__ void permute_v_kernel(const float* __restrict__ v)
{
    size_t idx = (size_t)blockIdx.x * 256 + threadIdx.x;
    if (idx >= (size_t)B_ * KOBJ * VD) return;
    int b = (int)(idx / ((size_t)KOBJ * VD));
    size_t rest = idx % ((size_t)KOBJ * VD);
    float x = v[(size_t)g_order[b] * KOBJ * VD + rest];
    g_vs[idx] = x;
    split2(x, g_vs_h[idx], g_vs_l[idx]);
}

__global__ void vmean_kernel()
{
    int idx = blockIdx.x * 256 + threadIdx.x;
    if (idx >= B_ * VD) return;
    int b = idx / VD, d = idx % VD;
    const float* p = g_vs + (size_t)b * KOBJ * VD + d;
    float s = 0.f;
#pragma unroll 6
    for (int k = 0; k < KOBJ; k++) s += p[(size_t)k * VD];
    g_vmean[idx] = s * (1.f / (float)KOBJ);
}

__global__ void build_x1c_kernel(const float* __restrict__ caption)
{
    size_t idx = (size_t)blockIdx.x * 256 + threadIdx.x;
    if (idx >= (size_t)TT * B_ * H3) return;
    int c = (int)(idx % H3);
    int r = (int)(idx / H3);
    int t = r / B_, b = r % B_;
    float val;
    if (c < VD) val = g_vmean[b * VD + c];
    else        val = caption[((size_t)g_order[b] * MAXLEN + t) * EMB + (c - VD)];
    split2(val, g_x1c_h[idx], g_x1c_l[idx]);
}

// generic fp32 -> bf16 hi/lo weight converter (with column offset + stride)
__global__ void convw_kernel(const float* __restrict__ src, int ld, int col0,
                             int rows, int cols, bf16* __restrict__ hi,
                             bf16* __restrict__ lo)
{
    size_t idx = (size_t)blockIdx.x * 256 + threadIdx.x;
    if (idx >= (size_t)rows * cols) return;
    int r = (int)(idx / cols), c = (int)(idx % cols);
    split2(src[(size_t)r * ld + col0 + c], hi[idx], lo[idx]);
}

__global__ void fusebias_kernel(const float* __restrict__ Wq,
                                const float* __restrict__ bq,
                                const float* __restrict__ b1,
                                const float* __restrict__ Wih2,
                                const float* __restrict__ bih2)
{
    int idx = blockIdx.x * 256 + threadIdx.x;
    if (idx < HID_) {
        const float* w = Wq + (size_t)idx * HID_;
        float s = 0.f;
        for (int j = 0; j < HID_; j++) s += w[j] * b1[j];
        g_bfq[idx] = s + bq[idx];
    } else if (idx < HID_ + H3) {
        int n = idx - HID_;
        const float* w = Wih2 + (size_t)n * H3 + VD;
        float s = 0.f;
        for (int j = 0; j < HID_; j++) s += w[j] * b1[j];
        g_bi2f[n] = s + bih2[n];
    }
}

// GRU pointwise: gi = gi0+gi1+gi2 (+gi3+gi4+gi5) (+biv); gh = gha+ghb.
__global__ void gru_kernel(const float* __restrict__ gi0,
                           const float* __restrict__ gi1,
                           const float* __restrict__ gi2,
                           const float* __restrict__ gi3,
                           const float* __restrict__ gi4,
                           const float* __restrict__ gi5,
                           const float* __restrict__ biv,
                           const float* __restrict__ gha,
                           const float* __restrict__ ghb,
                           const float* __restrict__ hprev,
                           float* __restrict__ hout,
                           bf16* __restrict__ hout_h,
                           bf16* __restrict__ hout_l)
{
    int idx = blockIdx.x * 256 + threadIdx.x;
    if (idx >= B_ * HID_) return;
    int b = idx >> 10, j = idx & 1023;
    size_t base = (size_t)b * H3 + j;
    float gr = gi0[base]            + gi1[base]            + gi2[base];
    float gz = gi0[base + HID_]     + gi1[base + HID_]     + gi2[base + HID_];
    float gn = gi0[base + 2 * HID_] + gi1[base + 2 * HID_] + gi2[base + 2 * HID_];
    if (gi3) {
        gr += gi3[base]            + gi4[base]            + gi5[base];
        gz += gi3[base + HID_]     + gi4[base + HID_]     + gi5[base + HID_];
        gn += gi3[base + 2 * HID_] + gi4[base + 2 * HID_] + gi5[base + 2 * HID_];
    }
    if (biv) {
        gr += biv[j]; gz += biv[j + HID_]; gn += biv[j + 2 * HID_];
    }
    float ghr = gha[base]            + ghb[base];
    float ghz = gha[base + HID_]     + ghb[base + HID_];
    float ghn = gha[base + 2 * HID_] + ghb[base + 2 * HID_];
    float r = 1.f / (1.f + expf(-(gr + ghr)));
    float z = 1.f / (1.f + expf(-(gz + ghz)));
    float n = tanhf(gn + r * ghn);
    float h = (1.f - z) * n + z * hprev[idx];
    hout[idx] = h;
    split2(h, hout_h[idx], hout_l[idx]);
}

// Attention: q = relu(qA+qB+bfq); logits = vproj . (q*wa) + ba; softmax;
// masked alphas; att_v -> bf16 hi/lo.
__global__ void att_kernel(const float* __restrict__ qA,
                           const float* __restrict__ qB,
                           const float* __restrict__ bfq,
                           const float* __restrict__ wa,
                           const float* __restrict__ ba,
                           float* __restrict__ alphas, int t)
{
    int b = blockIdx.x, tid = threadIdx.x;
    __shared__ float qs[HID_];
    __shared__ float att[KOBJ];
    for (int d = tid; d < HID_; d += 256) {
        float qv = fmaxf(qA[b * HID_ + d] + qB[b * HID_ + d] + bfq[d], 0.f);
        qs[d] = qv * wa[d];
    }
    __syncthreads();

    int warp = tid >> 5, lane = tid & 31;
    for (int k = warp; k < KOBJ; k += 8) {
        const float* vp = g_vproj + ((size_t)b * KOBJ + k) * HID_;
        float s = 0.f;
        for (int d = lane; d < HID_; d += 32) s += vp[d] * qs[d];
#pragma unroll
        for (int o = 16; o; o >>= 1) s += __shfl_down_sync(0xffffffffu, s, o);
        if (lane == 0) att[k] = s + ba[0];
    }
    __syncthreads();

    if (tid == 0) {
        float mx = att[0];
        for (int k = 1; k < KOBJ; k++) mx = fmaxf(mx, att[k]);
        float ssum = 0.f;
        for (int k = 0; k < KOBJ; k++) { float e = expf(att[k] - mx); att[k] = e; ssum += e; }
        float inv = 1.f / ssum;
        for (int k = 0; k < KOBJ; k++) att[k] *= inv;
    }
    __syncthreads();

    if (tid < KOBJ) {
        float m = (t < g_dl[b]) ? 1.f : 0.f;
        alphas[((size_t)b * MAXLEN + t) * KOBJ + tid] = att[tid] * m;
    }
    for (int d = tid; d < VD; d += 256) {
        const float* vb = g_vs + (size_t)b * KOBJ * VD + d;
        float s = 0.f;
#pragma unroll 6
        for (int k = 0; k < KOBJ; k++) s += att[k] * vb[(size_t)k * VD];
        split2(s, g_attv_h[b * VD + d], g_attv_l[b * VD + d]);
    }
}

__global__ void zero_tails_kernel(float* __restrict__ predict,
                                  float* __restrict__ alphas)
{
    int idx = blockIdx.x * 256 + threadIdx.x;
    if (idx < B_ * NTOK) {
        int b = idx / NTOK, n = idx % NTOK;
        predict[((size_t)b * MAXLEN + (MAXLEN - 1)) * NTOK + n] = 0.f;
    } else if (idx < B_ * NTOK + B_ * KOBJ) {
        int r = idx - B_ * NTOK;
        int b = r / KOBJ, k = r % KOBJ;
        alphas[((size_t)b * MAXLEN + (MAXLEN - 1)) * KOBJ + k] = 0.f;
    }
}

// --------------------------------- launch ----------------------------------
static inline TZ mkt(const bf16* Ah, const bf16* Al, int lda,
                     const bf16* Wh, const bf16* Wl, int ldw,
                     float* C, int ldc, int M, int N, int K,
                     const float* bias, int mode)
{
    TZ z; z.Ahi = Ah; z.Alo = Al; z.Whi = Wh; z.Wlo = Wl;
    z.C = C; z.bias = bias; z.lda = lda; z.ldw = ldw; z.ldc = ldc;
    z.M = M; z.N = N; z.K = K; z.mode = mode;
    return z;
}

#define SYMADDR(var, sym) cudaGetSymbolAddress((void**)&var, sym)

extern "C" void kernel_launch(void* const* d_in, const int* in_sizes, int n_in,
                              void* d_out, int out_size)
{
    const float* v       = (const float*)d_in[0];
    const float* caption = (const float*)d_in[1];
    const int*   cap_len = (const int*)  d_in[2];
    const float* Wih1    = (const float*)d_in[3];
    const float* Whh1    = (const float*)d_in[4];
    const float* bih1    = (const float*)d_in[5];
    const float* bhh1    = (const float*)d_in[6];
    const float* Wih2    = (const float*)d_in[7];
    const float* Whh2    = (const float*)d_in[8];
    const float* bih2    = (const float*)d_in[9];
    const float* bhh2    = (const float*)d_in[10];
    const float* Wv      = (const float*)d_in[11];
    const float* bv      = (const float*)d_in[12];
    const float* Wq      = (const float*)d_in[13];
    const float* bq      = (const float*)d_in[14];
    const float* wa      = (const float*)d_in[15];
    const float* ba      = (const float*)d_in[16];
    const float* W1      = (const float*)d_in[17];
    const float* b1      = (const float*)d_in[18];
    const float* W2      = (const float*)d_in[19];
    const float* b2      = (const float*)d_in[20];

    float* out     = (float*)d_out;
    float* predict = out;
    float* alphas  = out + (size_t)B_ * MAXLEN * NTOK;

    // fp32 scratch addresses
    float *p_gi1c, *p_h1, *p_h2all;
    float *p_gihA, *p_gihB, *p_gh1A, *p_gh1B, *p_gh2A, *p_gh2B;
    float *p_qA, *p_qB, *p_gi2hA, *p_gi2hB;
    float *p_p0A, *p_p0B, *p_p0C, *p_p0D;
    float *p_Wfq, *p_Wf2h, *p_bfq, *p_bi2f, *p_mask, *p_vproj;
    SYMADDR(p_gi1c, g_gi1c);   SYMADDR(p_h1, g_h1);     SYMADDR(p_h2all, g_h2all);
    SYMADDR(p_gihA, g_gihA);   SYMADDR(p_gihB, g_gihB);
    SYMADDR(p_gh1A, g_gh1A);   SYMADDR(p_gh1B, g_gh1B);
    SYMADDR(p_gh2A, g_gh2A);   SYMADDR(p_gh2B, g_gh2B);
    SYMADDR(p_qA, g_qA);       SYMADDR(p_qB, g_qB);
    SYMADDR(p_gi2hA, g_gi2hA); SYMADDR(p_gi2hB, g_gi2hB);
    SYMADDR(p_p0A, g_p0A);     SYMADDR(p_p0B, g_p0B);
    SYMADDR(p_p0C, g_p0C);     SYMADDR(p_p0D, g_p0D);
    SYMADDR(p_Wfq, g_Wfq);     SYMADDR(p_Wf2h, g_Wf2h); SYMADDR(p_bfq, g_bfq);
    SYMADDR(p_bi2f, g_bi2f);   SYMADDR(p_mask, g_mask); SYMADDR(p_vproj, g_vproj);

    // bf16 operand addresses
    bf16 *vs_h, *vs_l, *x1c_h, *x1c_l, *h1_h, *h1_l, *h2_h, *h2_l, *av_h, *av_l;
    bf16 *w1h_h, *w1h_l, *w1x_h, *w1x_l, *wh1_h, *wh1_l, *wh2_h, *wh2_l;
    bf16 *wv_h, *wv_l, *w2v_h, *w2v_l, *ww2_h, *ww2_l, *wfq_h, *wfq_l, *wf2_h, *wf2_l;
    SYMADDR(vs_h, g_vs_h);   SYMADDR(vs_l, g_vs_l);
    SYMADDR(x1c_h, g_x1c_h); SYMADDR(x1c_l, g_x1c_l);
    SYMADDR(h1_h, g_h1_h);   SYMADDR(h1_l, g_h1_l);
    SYMADDR(h2_h, g_h2_h);   SYMADDR(h2_l, g_h2_l);
    SYMADDR(av_h, g_attv_h); SYMADDR(av_l, g_attv_l);
    SYMADDR(w1h_h, g_wih1h_h); SYMADDR(w1h_l, g_wih1h_l);
    SYMADDR(w1x_h, g_wih1x_h); SYMADDR(w1x_l, g_wih1x_l);
    SYMADDR(wh1_h, g_whh1_h);  SYMADDR(wh1_l, g_whh1_l);
    SYMADDR(wh2_h, g_whh2_h);  SYMADDR(wh2_l, g_whh2_l);
    SYMADDR(wv_h, g_wv_h);     SYMADDR(wv_l, g_wv_l);
    SYMADDR(w2v_h, g_wih2v_h); SYMADDR(w2v_l, g_wih2v_l);
    SYMADDR(ww2_h, g_w2_h);    SYMADDR(ww2_l, g_w2_l);
    SYMADDR(wfq_h, g_wfq_h);   SYMADDR(wfq_l, g_wfq_l);
    SYMADDR(wf2_h, g_wf2h_h);  SYMADDR(wf2_l, g_wf2h_l);

    cudaFuncSetAttribute(tgemm_k<64>,  cudaFuncAttributeMaxDynamicSharedMemorySize,
                         TGC<64>::SMEM);
    cudaFuncSetAttribute(tgemm_k<128>, cudaFuncAttributeMaxDynamicSharedMemorySize,
                         TGC<128>::SMEM);

    auto cv = [](const float* s, int ld, int c0, int r, int c, bf16* h, bf16* l) {
        size_t n = (size_t)r * c;
        convw_kernel<<<(unsigned)((n + 255) / 256), 256>>>(s, ld, c0, r, c, h, l);
    };

    // stage1 split-K GEMM launcher (6 z-slices, K=512 each)
    auto stage1 = [&](const bf16* h2p_h, const bf16* h2p_l) {
        TP P{}; P.mask = nullptr;
        P.z[0] = mkt(h2p_h,       h2p_l,       HID_, w1h_h,       w1h_l,       HID_,
                     p_gihA, H3, B_, H3, 512, nullptr, 0);
        P.z[1] = mkt(h2p_h + 512, h2p_l + 512, HID_, w1h_h + 512, w1h_l + 512, HID_,
                     p_gihB, H3, B_, H3, 512, nullptr, 0);
        P.z[2] = mkt(h1_h,        h1_l,        HID_, wh1_h,       wh1_l,       HID_,
                     p_gh1A, H3, B_, H3, 512, bhh1, 0);
        P.z[3] = mkt(h1_h + 512,  h1_l + 512,  HID_, wh1_h + 512, wh1_l + 512, HID_,
                     p_gh1B, H3, B_, H3, 512, nullptr, 0);
        P.z[4] = mkt(h2p_h,       h2p_l,       HID_, wh2_h,       wh2_l,       HID_,
                     p_gh2A, H3, B_, H3, 512, bhh2, 0);
        P.z[5] = mkt(h2p_h + 512, h2p_l + 512, HID_, wh2_h + 512, wh2_l + 512, HID_,
                     p_gh2B, H3, B_, H3, 512, nullptr, 0);
        tgemm_k<64><<<dim3(H3/64, 1, 6), TGC<64>::THR, TGC<64>::SMEM>>>(P);
    };

    // ---- setup: launch #6 = real t=0 stage1 (profiled by ncu -s 5 -c 1) ----
    meta_kernel<<<1, B_>>>(cap_len);                                      // 1
    zero_init_kernel<<<(B_ * HID_ + 255) / 256, 256>>>();                 // 2
    cv(Wih1, HID_ + VD + EMB, 0, H3, HID_, w1h_h, w1h_l);                 // 3
    cv(Whh1, HID_,            0, H3, HID_, wh1_h, wh1_l);                 // 4
    cv(Whh2, HID_,            0, H3, HID_, wh2_h, wh2_l);                 // 5
    stage1(h2_h, h2_l);                                                   // 6 (t=0)

    permute_v_kernel<<<(unsigned)(((size_t)B_*KOBJ*VD + 255)/256), 256>>>(v);
    vmean_kernel<<<(B_ * VD + 255) / 256, 256>>>();
    build_x1c_kernel<<<(unsigned)(((size_t)TT*B_*H3 + 255)/256), 256>>>(caption);
    cv(Wih1, HID_ + VD + EMB, 1024, H3, H3, w1x_h, w1x_l);
    {   // gi1c = X1c @ Wih1[:,1024:].T + bih1   [2432 x 3072 x K=3072]
        TP P{}; P.mask = nullptr;
        P.z[0] = mkt(x1c_h, x1c_l, H3, w1x_h, w1x_l, H3,
                     p_gi1c, H3, TT * B_, H3, H3, bih1, 0);
        tgemm_k<128><<<dim3(H3/128, (TT*B_)/128, 1), TGC<128>::THR, TGC<128>::SMEM>>>(P);
    }
    cv(Wv,   VD,   0, HID_, VD,   wv_h,  wv_l);
    cv(Wih2, H3,   0, H3,   VD,   w2v_h, w2v_l);
    cv(W2,   HID_, 0, NTOK, HID_, ww2_h, ww2_l);
    {
        GemmP P{};
        P.z[0] = mkg(Wq,        HID_, W1, HID_, p_Wfq,  HID_, HID_, HID_, HID_);
        P.z[1] = mkg(Wih2 + VD, H3,   W1, HID_, p_Wf2h, HID_, H3,   HID_, HID_);
        gemm_nn<<<dim3(HID_/128, H3/128, 2), 256>>>(P);
    }
    cv(p_Wfq,  HID_, 0, HID_, HID_, wfq_h, wfq_l);
    cv(p_Wf2h, HID_, 0, H3,   HID_, wf2_h, wf2_l);
    fusebias_kernel<<<(HID_ + H3 + 255) / 256, 256>>>(Wq, bq, b1, Wih2, bih2);
    {   // vproj = relu(v_s @ Wv.T + bv)         [4608 x 1024 x K=2048]
        TP P{}; P.mask = nullptr;
        P.z[0] = mkt(vs_h, vs_l, VD, wv_h, wv_l, VD,
                     p_vproj, HID_, B_ * KOBJ, HID_, VD, bv, 1);
        tgemm_k<128><<<dim3(HID_/128, (B_*KOBJ)/128, 1), TGC<128>::THR, TGC<128>::SMEM>>>(P);
    }

    // ---- sequential decode ----
    const int gruBlocks = (B_ * HID_ + 255) / 256;
    for (int t = 0; t < TT; t++) {
        const bf16* h2p_h = h2_h + (size_t)t * B_ * HID_;
        const bf16* h2p_l = h2_l + (size_t)t * B_ * HID_;
        const float* h2prev = p_h2all + (size_t)t * B_ * HID_;
        float*       h2next = p_h2all + (size_t)(t + 1) * B_ * HID_;

        // stage1 split-K: gih, gh1, gh2 (t=0's was already issued; reissue is
        // identical and keeps the loop uniform)
        stage1(h2p_h, h2p_l);
        // GRU1 (h1 in place, + bf16 split out)
        gru_kernel<<<gruBlocks, 256>>>(p_gi1c + (size_t)t * B_ * H3,
                                       p_gihA, p_gihB,
                                       nullptr, nullptr, nullptr, nullptr,
                                       p_gh1A, p_gh1B,
                                       p_h1, p_h1, h1_h, h1_l);
        // stage2 split-K: qA/qB (K=512 each), gi2hA/gi2hB
        {
            TP P{}; P.mask = nullptr;
            P.z[0] = mkt(h1_h,       h1_l,       HID_, wfq_h,       wfq_l,       HID_,
                         p_qA, HID_, B_, HID_, 512, nullptr, 0);
            P.z[1] = mkt(h1_h + 512, h1_l + 512, HID_, wfq_h + 512, wfq_l + 512, HID_,
                         p_qB, HID_, B_, HID_, 512, nullptr, 0);
            P.z[2] = mkt(h1_h,       h1_l,       HID_, wf2_h,       wf2_l,       HID_,
                         p_gi2hA, H3, B_, H3, 512, nullptr, 0);
            P.z[3] = mkt(h1_h + 512, h1_l + 512, HID_, wf2_h + 512, wf2_l + 512, HID_,
                         p_gi2hB, H3, B_, H3, 512, nullptr, 0);
            tgemm_k<64><<<dim3(H3/64, 1, 4), TGC<64>::THR, TGC<64>::SMEM>>>(P);
        }
        // attention (sums q partials, relu, softmax, att_v)
        att_kernel<<<B_, 256>>>(p_qA, p_qB, p_bfq, wa, ba, alphas, t);
        // gi2_att = att_v @ Wih2[:,:2048].T, split-K 4x512
        {
            TP P{}; P.mask = nullptr;
            P.z[0] = mkt(av_h,        av_l,        VD, w2v_h,        w2v_l,        VD,
                         p_p0A, H3, B_, H3, 512, nullptr, 0);
            P.z[1] = mkt(av_h + 512,  av_l + 512,  VD, w2v_h + 512,  w2v_l + 512,  VD,
                         p_p0B, H3, B_, H3, 512, nullptr, 0);
            P.z[2] = mkt(av_h + 1024, av_l + 1024, VD, w2v_h + 1024, w2v_l + 1024, VD,
                         p_p0C, H3, B_, H3, 512, nullptr, 0);
            P.z[3] = mkt(av_h + 1536, av_l + 1536, VD, w2v_h + 1536, w2v_l + 1536, VD,
                         p_p0D, H3, B_, H3, 512, nullptr, 0);
            tgemm_k<64><<<dim3(H3/64, 1, 4), TGC<64>::THR, TGC<64>::SMEM>>>(P);
        }
        // GRU2: gi = p0A..D + gi2hA + gi2hB (+bi2f); gh = gh2A + gh2B
        gru_kernel<<<gruBlocks, 256>>>(p_p0A, p_p0B, p_p0C,
                                       p_p0D, p_gi2hA, p_gi2hB,
                                       p_bi2f,
                                       p_gh2A, p_gh2B,
                                       h2prev, h2next,
                                       h2_h + (size_t)(t+1) * B_ * HID_,
                                       h2_l + (size_t)(t+1) * B_ * HID_);
    }

    // words = H2all @ W2.T + b2 (masked scatter)  [2432 x 10000 x K=1024]
    {
        TP P{}; P.mask = p_mask;
        P.z[0] = mkt(h2_h + B_ * HID_, h2_l + B_ * HID_, HID_,
                     ww2_h, ww2_l, HID_,
                     predict, NTOK, TT * B_, NTOK, HID_, b2, 2);
        tgemm_k<128><<<dim3((NTOK + 127) / 128, (TT*B_)/128, 1),
                       TGC<128>::THR, TGC<128>::SMEM>>>(P);
    }
    zero_tails_kernel<<<(B_ * NTOK + B_ * KOBJ + 255) / 256, 256>>>(predict, alphas);
}

// round 10
// speedup vs baseline: 1.2845x; 1.0490x over previous
#include <cuda_runtime.h>
#include <cuda_bf16.h>
#include <math.h>

// ---------------------------------------------------------------------------
// BUTDDecoder: B=128, K=36, V_DIM=2048, EMBED=1024, HID=1024, NTOKEN=10000,
// MAX_LEN=20 (T=19 decode steps).
//
// Round 10: split-K deepened to 256-wide slices (stage1 x12, stage2 x8,
// gi2att x8); GRU/att absorb partials via pointer arrays. Wfq/Wf2h
// precompute moved from fp32 SIMT to the bf16x3 tensor path (W1 transposed
// once). stage1 issued twice at setup so ncu capture lands on it.
// ---------------------------------------------------------------------------

#define B_     128
#define KOBJ   36
#define VD     2048
#define EMB    1024
#define HID_   1024
#define NTOK   10000
#define MAXLEN 20
#define TT     19
#define H3     3072

typedef unsigned long long ull;
typedef __nv_bfloat16 bf16;

// ------------------------- scratch (device globals) ------------------------
__device__ float g_vs[B_ * KOBJ * VD];
__device__ float g_vmean[B_ * VD];
__device__ float g_vproj[B_ * KOBJ * HID_];
__device__ float g_gi1c[TT * B_ * H3];
__device__ float g_h1[B_ * HID_];
__device__ float g_h2all[(TT + 1) * B_ * HID_];
__device__ float g_gih[4][B_ * H3];
__device__ float g_gh1[4][B_ * H3];
__device__ float g_gh2[4][B_ * H3];
__device__ float g_qp[4][B_ * HID_];
__device__ float g_gi2h[4][B_ * H3];
__device__ float g_p0[8][B_ * H3];
__device__ float g_Wfq[HID_ * HID_];     // Wq @ W1 (tensor precompute)
__device__ float g_Wf2h[H3 * HID_];      // Wih2[:,2048:] @ W1
__device__ float g_bfq[HID_];            // Wq@b1 + bq
__device__ float g_bi2f[H3];             // Wih2[:,2048:]@b1 + bih2
__device__ int   g_order[B_];
__device__ int   g_dl[B_];
__device__ float g_mask[TT * B_];

// bf16 hi/lo operand arrays (activations)
__device__ bf16 g_vs_h[B_ * KOBJ * VD],        g_vs_l[B_ * KOBJ * VD];
__device__ bf16 g_x1c_h[TT * B_ * H3],         g_x1c_l[TT * B_ * H3];
__device__ bf16 g_h1_h[B_ * HID_],             g_h1_l[B_ * HID_];
__device__ bf16 g_h2_h[(TT + 1) * B_ * HID_],  g_h2_l[(TT + 1) * B_ * HID_];
__device__ bf16 g_attv_h[B_ * VD],             g_attv_l[B_ * VD];

// bf16 hi/lo weight arrays
__device__ bf16 g_wih1h_h[H3 * HID_],  g_wih1h_l[H3 * HID_];   // Wih1[:, :1024]
__device__ bf16 g_wih1x_h[H3 * H3],    g_wih1x_l[H3 * H3];     // Wih1[:, 1024:]
__device__ bf16 g_whh1_h[H3 * HID_],   g_whh1_l[H3 * HID_];
__device__ bf16 g_whh2_h[H3 * HID_],   g_whh2_l[H3 * HID_];
__device__ bf16 g_wv_h[HID_ * VD],     g_wv_l[HID_ * VD];
__device__ bf16 g_wih2v_h[H3 * VD],    g_wih2v_l[H3 * VD];     // Wih2[:, :2048]
__device__ bf16 g_wih2x_h[H3 * HID_],  g_wih2x_l[H3 * HID_];   // Wih2[:, 2048:]
__device__ bf16 g_w2_h[NTOK * HID_],   g_w2_l[NTOK * HID_];
__device__ bf16 g_wq_h[HID_ * HID_],   g_wq_l[HID_ * HID_];
__device__ bf16 g_w1t_h[HID_ * HID_],  g_w1t_l[HID_ * HID_];   // W1 transposed
__device__ bf16 g_wfq_h[HID_ * HID_],  g_wfq_l[HID_ * HID_];
__device__ bf16 g_wf2h_h[H3 * HID_],   g_wf2h_l[H3 * HID_];

// --------------------------- small helpers ---------------------------------
__device__ __forceinline__ void split2(float x, bf16& h, bf16& l) {
    h = __float2bfloat16(x);
    l = __float2bfloat16(x - __bfloat162float(h));
}
__device__ __forceinline__ unsigned smem_u32(const void* p) {
    return (unsigned)__cvta_generic_to_shared(p);
}
__device__ __forceinline__ void cpa16(unsigned dst, const void* src, int sz) {
    asm volatile("cp.async.ca.shared.global [%0], [%1], 16, %2;"
                 :: "r"(dst), "l"(src), "r"(sz));
}

#define LDM_X4(r0, r1, r2, r3, addr) \
    asm volatile("ldmatrix.sync.aligned.m8n8.x4.shared.b16 {%0,%1,%2,%3}, [%4];" \
        : "=r"(r0), "=r"(r1), "=r"(r2), "=r"(r3) : "r"(addr))

#define MMA16816(c, a, b) \
    asm volatile("mma.sync.aligned.m16n8k16.row.col.f32.bf16.bf16.f32 " \
        "{%0,%1,%2,%3}, {%4,%5,%6,%7}, {%8,%9}, {%0,%1,%2,%3};" \
        : "+f"((c)[0]), "+f"((c)[1]), "+f"((c)[2]), "+f"((c)[3]) \
        : "r"((a)[0]), "r"((a)[1]), "r"((a)[2]), "r"((a)[3]), \
          "r"((b)[0]), "r"((b)[1]))

// ----------------------------- tensor GEMM ---------------------------------
// C[m,n] = sum_k A[m,k]*W[n,k] with A = Ahi+Alo, W = Whi+Wlo (bf16 pairs).
// mode 0: +bias store; 1: relu(+bias); 2: masked scatter predict.
// Requires: M % 128 == 0, K % 64 == 0. N arbitrary (tail guarded).
struct TZ {
    const bf16 *Ahi, *Alo, *Whi, *Wlo;
    float* C; const float* bias;
    int lda, ldw, ldc, M, N, K, mode;
};
struct TP { TZ z[12]; const float* mask; };

// per-buffer smem: Ah 16K | Al 16K | Bh BN*128 | Bl BN*128
template<int BN> struct TGC {
    static constexpr int BUF   = 32768 + BN * 256;
    static constexpr int SMEM  = 2 * BUF + 1024;
    static constexpr int THR   = BN * 2;          // 128 or 256
    static constexpr int WN    = BN / 32;         // warps along n
    static constexpr int RPI   = BN / 4;          // loader rows per iteration
    static constexpr int AIT   = 128 / RPI;       // A loader iterations
};

template<int BN>
__global__ void __launch_bounds__(TGC<BN>::THR) tgemm_k(TP p)
{
    const TZ gz = p.z[blockIdx.z];
    const int bn0 = blockIdx.x * BN;  if (bn0 >= gz.N) return;
    const int bm0 = blockIdx.y * 128; if (bm0 >= gz.M) return;
    const int tid = threadIdx.x, wid = tid >> 5, lane = tid & 31;
    const int wm = wid / TGC<BN>::WN, wn = wid % TGC<BN>::WN;

    extern __shared__ char dsm[];
    unsigned dbase = smem_u32(dsm);
    unsigned s0 = (dbase + 1023u) & ~1023u;
    unsigned sAh[2], sAl[2], sBh[2], sBl[2];
#pragma unroll
    for (int b = 0; b < 2; b++) {
        sAh[b] = s0 + b * TGC<BN>::BUF;
        sAl[b] = sAh[b] + 16384;
        sBh[b] = sAl[b] + 16384;
        sBl[b] = sBh[b] + BN * 128;
    }

    // ---- coalesced cp.async chunk loader (BK=64 => 128B per row) ----
    const int lrow = tid >> 3;         // 0..RPI-1
    const int lch  = tid & 7;          // 16B chunk within row
    auto load_chunk = [&](int c, int buf) {
        const int c0 = c * 64;
#pragma unroll
        for (int i = 0; i < TGC<BN>::AIT; i++) {
            int row = i * TGC<BN>::RPI + lrow;
            unsigned off = (unsigned)(row * 128) + (unsigned)(((lch ^ (row & 7)) * 16));
            const bf16* sh = gz.Ahi + (size_t)(bm0 + row) * gz.lda + c0 + lch * 8;
            const bf16* sl = gz.Alo + (size_t)(bm0 + row) * gz.lda + c0 + lch * 8;
            cpa16(sAh[buf] + off, sh, 16);
            cpa16(sAl[buf] + off, sl, 16);
        }
#pragma unroll
        for (int i = 0; i < 4; i++) {
            int row = i * TGC<BN>::RPI + lrow;
            unsigned off = (unsigned)(row * 128) + (unsigned)(((lch ^ (row & 7)) * 16));
            int n = bn0 + row;
            int sz = (n < gz.N) ? 16 : 0;
            int nn = (n < gz.N) ? n : 0;
            const bf16* sh = gz.Whi + (size_t)nn * gz.ldw + c0 + lch * 8;
            const bf16* sl = gz.Wlo + (size_t)nn * gz.ldw + c0 + lch * 8;
            cpa16(sBh[buf] + off, sh, sz);
            cpa16(sBl[buf] + off, sl, sz);
        }
        asm volatile("cp.async.commit_group;");
    };

    float acc[4][4][4];
#pragma unroll
    for (int mi = 0; mi < 4; mi++)
#pragma unroll
        for (int nj = 0; nj < 4; nj++)
#pragma unroll
            for (int e = 0; e < 4; e++) acc[mi][nj][e] = 0.f;

    const int xorkey = lane & 7;
    const int nch = gz.K / 64;
    load_chunk(0, 0);

    for (int c = 0; c < nch; c++) {
        if (c + 1 < nch) {
            load_chunk(c + 1, (c + 1) & 1);
            asm volatile("cp.async.wait_group 1;");
        } else {
            asm volatile("cp.async.wait_group 0;");
        }
        __syncthreads();

        const unsigned tAh = sAh[c & 1], tAl = sAl[c & 1];
        const unsigned tBh = sBh[c & 1], tBl = sBl[c & 1];

#pragma unroll
        for (int ks = 0; ks < 4; ks++) {
            // ---- A fragments: 4 m-frags, hi+lo, ldmatrix.x4 non-trans ----
            unsigned Ah[4][4], Al[4][4];
            {
                const int arow = wm * 64 + (lane & 15);
                const unsigned aoff =
                    (unsigned)((((2 * ks) + (lane >> 4)) ^ xorkey) * 16);
#pragma unroll
                for (int mi = 0; mi < 4; mi++) {
                    unsigned ad = (unsigned)((arow + mi * 16) * 128) + aoff;
                    LDM_X4(Ah[mi][0], Ah[mi][1], Ah[mi][2], Ah[mi][3], tAh + ad);
                    LDM_X4(Al[mi][0], Al[mi][1], Al[mi][2], Al[mi][3], tAl + ad);
                }
            }
            // ---- B fragments: 4 n-frags, hi+lo ----
            unsigned Bh[4][2], Bl[4][2];
            {
                const int brow = wn * 32 + (lane & 7) + ((lane >> 4) << 3);
                const unsigned boff =
                    (unsigned)((((2 * ks) + ((lane >> 3) & 1)) ^ xorkey) * 16);
                unsigned r0, r1, r2, r3;
                unsigned b0 = (unsigned)(brow * 128) + boff;
                LDM_X4(r0, r1, r2, r3, tBh + b0);
                Bh[0][0] = r0; Bh[0][1] = r1; Bh[1][0] = r2; Bh[1][1] = r3;
                LDM_X4(r0, r1, r2, r3, tBh + b0 + 16 * 128);
                Bh[2][0] = r0; Bh[2][1] = r1; Bh[3][0] = r2; Bh[3][1] = r3;
                LDM_X4(r0, r1, r2, r3, tBl + b0);
                Bl[0][0] = r0; Bl[0][1] = r1; Bl[1][0] = r2; Bl[1][1] = r3;
                LDM_X4(r0, r1, r2, r3, tBl + b0 + 16 * 128);
                Bl[2][0] = r0; Bl[2][1] = r1; Bl[3][0] = r2; Bl[3][1] = r3;
            }
            // ---- 48 MMAs: hi*hi + hi*lo + lo*hi ----
#pragma unroll
            for (int mi = 0; mi < 4; mi++)
#pragma unroll
                for (int nj = 0; nj < 4; nj++) {
                    MMA16816(acc[mi][nj], Ah[mi], Bh[nj]);
                    MMA16816(acc[mi][nj], Ah[mi], Bl[nj]);
                    MMA16816(acc[mi][nj], Al[mi], Bh[nj]);
                }
        }
        __syncthreads();
    }

    // ---- epilogue: fragments straight to gmem ----
    const int g = lane >> 2, tig = lane & 3;
    auto stc = [&](int m, int n, float val) {
        if (n >= gz.N) return;
        if (gz.bias) val += gz.bias[n];
        if (gz.mode == 1) val = fmaxf(val, 0.f);
        if (gz.mode == 2) {
            int tt = m / B_, bb = m % B_;
            gz.C[((size_t)bb * MAXLEN + tt) * gz.ldc + n] = val * p.mask[m];
        } else {
            gz.C[(size_t)m * gz.ldc + n] = val;
        }
    };
#pragma unroll
    for (int mi = 0; mi < 4; mi++)
#pragma unroll
        for (int nj = 0; nj < 4; nj++) {
            int row = bm0 + wm * 64 + mi * 16 + g;
            int col = bn0 + wn * 32 + nj * 8 + 2 * tig;
            stc(row,     col,     acc[mi][nj][0]);
            stc(row,     col + 1, acc[mi][nj][1]);
            stc(row + 8, col,     acc[mi][nj][2]);
            stc(row + 8, col + 1, acc[mi][nj][3]);
        }
}

// ------------------------------- small kernels -----------------------------
__global__ void meta_kernel(const int* __restrict__ cap_len)
{
    int i = threadIdx.x;
    int ci = cap_len[i];
    int rank = 0;
    for (int j = 0; j < B_; j++) {
        int cj = cap_len[j];
        if (cj > ci || (cj == ci && j < i)) rank++;
    }
    g_order[rank] = i;
    __syncthreads();
    g_dl[i] = cap_len[g_order[i]] - 1;
    __syncthreads();
    int dli = g_dl[i];
    for (int t = 0; t < TT; t++) g_mask[t * B_ + i] = (t < dli) ? 1.f : 0.f;
}

__global__ void zero_init_kernel()
{
    int idx = blockIdx.x * 256 + threadIdx.x;
    if (idx < B_ * HID_) {
        g_h1[idx] = 0.f;    g_h1_h[idx] = __float2bfloat16(0.f); g_h1_l[idx] = __float2bfloat16(0.f);
        g_h2all[idx] = 0.f; g_h2_h[idx] = __float2bfloat16(0.f); g_h2_l[idx] = __float2bfloat16(0.f);
    }
}

__global__ void permute_v_kernel(const float* __restrict__ v)
{
    size_t idx = (size_t)blockIdx.x * 256 + threadIdx.x;
    if (idx >= (size_t)B_ * KOBJ * VD) return;
    int b = (int)(idx / ((size_t)KOBJ * VD));
    size_t rest = idx % ((size_t)KOBJ * VD);
    float x = v[(size_t)g_order[b] * KOBJ * VD + rest];
    g_vs[idx] = x;
    split2(x, g_vs_h[idx], g_vs_l[idx]);
}

__global__ void vmean_kernel()
{
    int idx = blockIdx.x * 256 + threadIdx.x;
    if (idx >= B_ * VD) return;
    int b = idx / VD, d = idx % VD;
    const float* p = g_vs + (size_t)b * KOBJ * VD + d;
    float s = 0.f;
#pragma unroll 6
    for (int k = 0; k < KOBJ; k++) s += p[(size_t)k * VD];
    g_vmean[idx] = s * (1.f / (float)KOBJ);
}

__global__ void build_x1c_kernel(const float* __restrict__ caption)
{
    size_t idx = (size_t)blockIdx.x * 256 + threadIdx.x;
    if (idx >= (size_t)TT * B_ * H3) return;
    int c = (int)(idx % H3);
    int r = (int)(idx / H3);
    int t = r / B_, b = r % B_;
    float val;
    if (c < VD) val = g_vmean[b * VD + c];
    else        val = caption[((size_t)g_order[b] * MAXLEN + t) * EMB + (c - VD)];
    split2(val, g_x1c_h[idx], g_x1c_l[idx]);
}

// generic fp32 -> bf16 hi/lo weight converter (with column offset + stride)
__global__ void convw_kernel(const float* __restrict__ src, int ld, int col0,
                             int rows, int cols, bf16* __restrict__ hi,
                             bf16* __restrict__ lo)
{
    size_t idx = (size_t)blockIdx.x * 256 + threadIdx.x;
    if (idx >= (size_t)rows * cols) return;
    int r = (int)(idx / cols), c = (int)(idx % cols);
    split2(src[(size_t)r * ld + col0 + c], hi[idx], lo[idx]);
}

// tiled transpose + hi/lo split for the 1024x1024 W1: out[j,i] = W1[i,j]
__global__ void tsplit_kernel(const float* __restrict__ src,
                              bf16* __restrict__ hi, bf16* __restrict__ lo)
{
    __shared__ float tile[32][33];
    int bx = blockIdx.x * 32, by = blockIdx.y * 32;
#pragma unroll
    for (int i = 0; i < 32; i += 8)
        tile[threadIdx.y + i][threadIdx.x] =
            src[(size_t)(by + threadIdx.y + i) * HID_ + bx + threadIdx.x];
    __syncthreads();
#pragma unroll
    for (int i = 0; i < 32; i += 8) {
        float vv = tile[threadIdx.x][threadIdx.y + i];
        size_t o = (size_t)(bx + threadIdx.y + i) * HID_ + by + threadIdx.x;
        split2(vv, hi[o], lo[o]);
    }
}

__global__ void fusebias_kernel(const float* __restrict__ Wq,
                                const float* __restrict__ bq,
                                const float* __restrict__ b1,
                                const float* __restrict__ Wih2,
                                const float* __restrict__ bih2)
{
    int idx = blockIdx.x * 256 + threadIdx.x;
    if (idx < HID_) {
        const float* w = Wq + (size_t)idx * HID_;
        float s = 0.f;
        for (int j = 0; j < HID_; j++) s += w[j] * b1[j];
        g_bfq[idx] = s + bq[idx];
    } else if (idx < HID_ + H3) {
        int n = idx - HID_;
        const float* w = Wih2 + (size_t)n * H3 + VD;
        float s = 0.f;
        for (int j = 0; j < HID_; j++) s += w[j] * b1[j];
        g_bi2f[n] = s + bih2[n];
    }
}

// GRU pointwise with partial-sum arrays.
struct GruP {
    const float* gi[13]; const float* gh[4];
    const float* biv; const float* hprev;
    float* hout; bf16* hh; bf16* hl;
    int ngi, ngh;
};
__global__ void gru_kernel(GruP p)
{
    int idx = blockIdx.x * 256 + threadIdx.x;
    if (idx >= B_ * HID_) return;
    int b = idx >> 10, j = idx & 1023;
    size_t base = (size_t)b * H3 + j;
    float gr = 0.f, gz = 0.f, gn = 0.f;
    for (int s = 0; s < p.ngi; s++) {
        const float* gi = p.gi[s];
        gr += gi[base]; gz += gi[base + HID_]; gn += gi[base + 2 * HID_];
    }
    if (p.biv) {
        gr += p.biv[j]; gz += p.biv[j + HID_]; gn += p.biv[j + 2 * HID_];
    }
    float ghr = 0.f, ghz = 0.f, ghn = 0.f;
    for (int s = 0; s < p.ngh; s++) {
        const float* gh = p.gh[s];
        ghr += gh[base]; ghz += gh[base + HID_]; ghn += gh[base + 2 * HID_];
    }
    float r = 1.f / (1.f + expf(-(gr + ghr)));
    float z = 1.f / (1.f + expf(-(gz + ghz)));
    float n = tanhf(gn + r * ghn);
    float h = (1.f - z) * n + z * p.hprev[idx];
    p.hout[idx] = h;
    split2(h, p.hh[idx], p.hl[idx]);
}

// Attention: q = relu(q0+q1+q2+q3+bfq); logits = vproj . (q*wa) + ba;
// softmax; masked alphas; att_v -> bf16 hi/lo.
__global__ void att_kernel(const float* __restrict__ q0,
                           const float* __restrict__ q1,
                           const float* __restrict__ q2,
                           const float* __restrict__ q3,
                           const float* __restrict__ bfq,
                           const float* __restrict__ wa,
                           const float* __restrict__ ba,
                           float* __restrict__ alphas, int t)
{
    int b = blockIdx.x, tid = threadIdx.x;
    __shared__ float qs[HID_];
    __shared__ float att[KOBJ];
    for (int d = tid; d < HID_; d += 256) {
        float qv = q0[b * HID_ + d] + q1[b * HID_ + d]
                 + q2[b * HID_ + d] + q3[b * HID_ + d] + bfq[d];
        qs[d] = fmaxf(qv, 0.f) * wa[d];
    }
    __syncthreads();

    int warp = tid >> 5, lane = tid & 31;
    for (int k = warp; k < KOBJ; k += 8) {
        const float* vp = g_vproj + ((size_t)b * KOBJ + k) * HID_;
        float s = 0.f;
        for (int d = lane; d < HID_; d += 32) s += vp[d] * qs[d];
#pragma unroll
        for (int o = 16; o; o >>= 1) s += __shfl_down_sync(0xffffffffu, s, o);
        if (lane == 0) att[k] = s + ba[0];
    }
    __syncthreads();

    if (tid == 0) {
        float mx = att[0];
        for (int k = 1; k < KOBJ; k++) mx = fmaxf(mx, att[k]);
        float ssum = 0.f;
        for (int k = 0; k < KOBJ; k++) { float e = expf(att[k] - mx); att[k] = e; ssum += e; }
        float inv = 1.f / ssum;
        for (int k = 0; k < KOBJ; k++) att[k] *= inv;
    }
    __syncthreads();

    if (tid < KOBJ) {
        float m = (t < g_dl[b]) ? 1.f : 0.f;
        alphas[((size_t)b * MAXLEN + t) * KOBJ + tid] = att[tid] * m;
    }
    for (int d = tid; d < VD; d += 256) {
        const float* vb = g_vs + (size_t)b * KOBJ * VD + d;
        float s = 0.f;
#pragma unroll 6
        for (int k = 0; k < KOBJ; k++) s += att[k] * vb[(size_t)k * VD];
        split2(s, g_attv_h[b * VD + d], g_attv_l[b * VD + d]);
    }
}

__global__ void zero_tails_kernel(float* __restrict__ predict,
                                  float* __restrict__ alphas)
{
    int idx = blockIdx.x * 256 + threadIdx.x;
    if (idx < B_ * NTOK) {
        int b = idx / NTOK, n = idx % NTOK;
        predict[((size_t)b * MAXLEN + (MAXLEN - 1)) * NTOK + n] = 0.f;
    } else if (idx < B_ * NTOK + B_ * KOBJ) {
        int r = idx - B_ * NTOK;
        int b = r / KOBJ, k = r % KOBJ;
        alphas[((size_t)b * MAXLEN + (MAXLEN - 1)) * KOBJ + k] = 0.f;
    }
}

// --------------------------------- launch ----------------------------------
static inline TZ mkt(const bf16* Ah, const bf16* Al, int lda,
                     const bf16* Wh, const bf16* Wl, int ldw,
                     float* C, int ldc, int M, int N, int K,
                     const float* bias, int mode)
{
    TZ z; z.Ahi = Ah; z.Alo = Al; z.Whi = Wh; z.Wlo = Wl;
    z.C = C; z.bias = bias; z.lda = lda; z.ldw = ldw; z.ldc = ldc;
    z.M = M; z.N = N; z.K = K; z.mode = mode;
    return z;
}

#define SYMADDR(var, sym) cudaGetSymbolAddress((void**)&var, sym)

extern "C" void kernel_launch(void* const* d_in, const int* in_sizes, int n_in,
                              void* d_out, int out_size)
{
    const float* v       = (const float*)d_in[0];
    const float* caption = (const float*)d_in[1];
    const int*   cap_len = (const int*)  d_in[2];
    const float* Wih1    = (const float*)d_in[3];
    const float* Whh1    = (const float*)d_in[4];
    const float* bih1    = (const float*)d_in[5];
    const float* bhh1    = (const float*)d_in[6];
    const float* Wih2    = (const float*)d_in[7];
    const float* Whh2    = (const float*)d_in[8];
    const float* bih2    = (const float*)d_in[9];
    const float* bhh2    = (const float*)d_in[10];
    const float* Wv      = (const float*)d_in[11];
    const float* bv      = (const float*)d_in[12];
    const float* Wq      = (const float*)d_in[13];
    const float* bq      = (const float*)d_in[14];
    const float* wa      = (const float*)d_in[15];
    const float* ba      = (const float*)d_in[16];
    const float* W1      = (const float*)d_in[17];
    const float* b1      = (const float*)d_in[18];
    const float* W2      = (const float*)d_in[19];
    const float* b2      = (const float*)d_in[20];

    float* out     = (float*)d_out;
    float* predict = out;
    float* alphas  = out + (size_t)B_ * MAXLEN * NTOK;

    // fp32 scratch addresses
    float *p_gi1c, *p_h1, *p_h2all;
    float *p_gih[4], *p_gh1[4], *p_gh2[4], *p_q[4], *p_gi2h[4], *p_p0[8];
    float *p_Wfq, *p_Wf2h, *p_bfq, *p_bi2f, *p_mask, *p_vproj;
    SYMADDR(p_gi1c, g_gi1c);   SYMADDR(p_h1, g_h1);     SYMADDR(p_h2all, g_h2all);
    {
        float *b0;
        SYMADDR(b0, g_gih);  for (int s = 0; s < 4; s++) p_gih[s]  = b0 + (size_t)s * B_ * H3;
        SYMADDR(b0, g_gh1);  for (int s = 0; s < 4; s++) p_gh1[s]  = b0 + (size_t)s * B_ * H3;
        SYMADDR(b0, g_gh2);  for (int s = 0; s < 4; s++) p_gh2[s]  = b0 + (size_t)s * B_ * H3;
        SYMADDR(b0, g_qp);   for (int s = 0; s < 4; s++) p_q[s]    = b0 + (size_t)s * B_ * HID_;
        SYMADDR(b0, g_gi2h); for (int s = 0; s < 4; s++) p_gi2h[s] = b0 + (size_t)s * B_ * H3;
        SYMADDR(b0, g_p0);   for (int s = 0; s < 8; s++) p_p0[s]   = b0 + (size_t)s * B_ * H3;
    }
    SYMADDR(p_Wfq, g_Wfq);     SYMADDR(p_Wf2h, g_Wf2h); SYMADDR(p_bfq, g_bfq);
    SYMADDR(p_bi2f, g_bi2f);   SYMADDR(p_mask, g_mask); SYMADDR(p_vproj, g_vproj);

    // bf16 operand addresses
    bf16 *vs_h, *vs_l, *x1c_h, *x1c_l, *h1_h, *h1_l, *h2_h, *h2_l, *av_h, *av_l;
    bf16 *w1h_h, *w1h_l, *w1x_h, *w1x_l, *wh1_h, *wh1_l, *wh2_h, *wh2_l;
    bf16 *wv_h, *wv_l, *w2v_h, *w2v_l, *w2x_h, *w2x_l, *ww2_h, *ww2_l;
    bf16 *wq_h, *wq_l, *w1t_h, *w1t_l, *wfq_h, *wfq_l, *wf2_h, *wf2_l;
    SYMADDR(vs_h, g_vs_h);   SYMADDR(vs_l, g_vs_l);
    SYMADDR(x1c_h, g_x1c_h); SYMADDR(x1c_l, g_x1c_l);
    SYMADDR(h1_h, g_h1_h);   SYMADDR(h1_l, g_h1_l);
    SYMADDR(h2_h, g_h2_h);   SYMADDR(h2_l, g_h2_l);
    SYMADDR(av_h, g_attv_h); SYMADDR(av_l, g_attv_l);
    SYMADDR(w1h_h, g_wih1h_h); SYMADDR(w1h_l, g_wih1h_l);
    SYMADDR(w1x_h, g_wih1x_h); SYMADDR(w1x_l, g_wih1x_l);
    SYMADDR(wh1_h, g_whh1_h);  SYMADDR(wh1_l, g_whh1_l);
    SYMADDR(wh2_h, g_whh2_h);  SYMADDR(wh2_l, g_whh2_l);
    SYMADDR(wv_h, g_wv_h);     SYMADDR(wv_l, g_wv_l);
    SYMADDR(w2v_h, g_wih2v_h); SYMADDR(w2v_l, g_wih2v_l);
    SYMADDR(w2x_h, g_wih2x_h); SYMADDR(w2x_l, g_wih2x_l);
    SYMADDR(ww2_h, g_w2_h);    SYMADDR(ww2_l, g_w2_l);
    SYMADDR(wq_h, g_wq_h);     SYMADDR(wq_l, g_wq_l);
    SYMADDR(w1t_h, g_w1t_h);   SYMADDR(w1t_l, g_w1t_l);
    SYMADDR(wfq_h, g_wfq_h);   SYMADDR(wfq_l, g_wfq_l);
    SYMADDR(wf2_h, g_wf2h_h);  SYMADDR(wf2_l, g_wf2h_l);

    cudaFuncSetAttribute(tgemm_k<64>,  cudaFuncAttributeMaxDynamicSharedMemorySize,
                         TGC<64>::SMEM);
    cudaFuncSetAttribute(tgemm_k<128>, cudaFuncAttributeMaxDynamicSharedMemorySize,
                         TGC<128>::SMEM);

    auto cv = [](const float* s, int ld, int c0, int r, int c, bf16* h, bf16* l) {
        size_t n = (size_t)r * c;
        convw_kernel<<<(unsigned)((n + 255) / 256), 256>>>(s, ld, c0, r, c, h, l);
    };

    // stage1 split-K GEMM launcher: 12 z-slices (gih, gh1, gh2 x K/256)
    auto stage1 = [&](const bf16* h2p_h, const bf16* h2p_l) {
        TP P{}; P.mask = nullptr;
        for (int s = 0; s < 4; s++) {
            int o = s * 256;
            P.z[s]     = mkt(h2p_h + o, h2p_l + o, HID_, w1h_h + o, w1h_l + o, HID_,
                             p_gih[s], H3, B_, H3, 256, nullptr, 0);
            P.z[4 + s] = mkt(h1_h + o, h1_l + o, HID_, wh1_h + o, wh1_l + o, HID_,
                             p_gh1[s], H3, B_, H3, 256, s == 0 ? bhh1 : nullptr, 0);
            P.z[8 + s] = mkt(h2p_h + o, h2p_l + o, HID_, wh2_h + o, wh2_l + o, HID_,
                             p_gh2[s], H3, B_, H3, 256, s == 0 ? bhh2 : nullptr, 0);
        }
        tgemm_k<64><<<dim3(H3/64, 1, 12), TGC<64>::THR, TGC<64>::SMEM>>>(P);
    };

    // ---- setup: stage1 issued at launches #6 AND #7 so ncu lands on it ----
    meta_kernel<<<1, B_>>>(cap_len);                                      // 1
    zero_init_kernel<<<(B_ * HID_ + 255) / 256, 256>>>();                 // 2
    cv(Wih1, HID_ + VD + EMB, 0, H3, HID_, w1h_h, w1h_l);                 // 3
    cv(Whh1, HID_,            0, H3, HID_, wh1_h, wh1_l);                 // 4
    cv(Whh2, HID_,            0, H3, HID_, wh2_h, wh2_l);                 // 5
    stage1(h2_h, h2_l);                                                   // 6 (t=0)
    stage1(h2_h, h2_l);                                                   // 7 (dup)

    permute_v_kernel<<<(unsigned)(((size_t)B_*KOBJ*VD + 255)/256), 256>>>(v);
    vmean_kernel<<<(B_ * VD + 255) / 256, 256>>>();
    build_x1c_kernel<<<(unsigned)(((size_t)TT*B_*H3 + 255)/256), 256>>>(caption);
    cv(Wih1, HID_ + VD + EMB, 1024, H3, H3, w1x_h, w1x_l);
    {   // gi1c = X1c @ Wih1[:,1024:].T + bih1   [2432 x 3072 x K=3072]
        TP P{}; P.mask = nullptr;
        P.z[0] = mkt(x1c_h, x1c_l, H3, w1x_h, w1x_l, H3,
                     p_gi1c, H3, TT * B_, H3, H3, bih1, 0);
        tgemm_k<128><<<dim3(H3/128, (TT*B_)/128, 1), TGC<128>::THR, TGC<128>::SMEM>>>(P);
    }
    cv(Wv,   VD,   0,    HID_, VD,   wv_h,  wv_l);
    cv(Wih2, H3,   0,    H3,   VD,   w2v_h, w2v_l);
    cv(Wih2, H3,   2048, H3,   HID_, w2x_h, w2x_l);
    cv(Wq,   HID_, 0,    HID_, HID_, wq_h,  wq_l);
    cv(W2,   HID_, 0,    NTOK, HID_, ww2_h, ww2_l);
    tsplit_kernel<<<dim3(32, 32), dim3(32, 8)>>>(W1, w1t_h, w1t_l);
    {   // tensor precompute: Wfq = Wq@W1 (via W1T, NT form); Wf2h = Wih2x@W1
        TP P{}; P.mask = nullptr;
        P.z[0] = mkt(wq_h,  wq_l,  HID_, w1t_h, w1t_l, HID_,
                     p_Wfq,  HID_, HID_, HID_, HID_, nullptr, 0);
        P.z[1] = mkt(w2x_h, w2x_l, HID_, w1t_h, w1t_l, HID_,
                     p_Wf2h, HID_, H3,   HID_, HID_, nullptr, 0);
        tgemm_k<64><<<dim3(HID_/64, H3/128, 2), TGC<64>::THR, TGC<64>::SMEM>>>(P);
    }
    cv(p_Wfq,  HID_, 0, HID_, HID_, wfq_h, wfq_l);
    cv(p_Wf2h, HID_, 0, H3,   HID_, wf2_h, wf2_l);
    fusebias_kernel<<<(HID_ + H3 + 255) / 256, 256>>>(Wq, bq, b1, Wih2, bih2);
    {   // vproj = relu(v_s @ Wv.T + bv)         [4608 x 1024 x K=2048]
        TP P{}; P.mask = nullptr;
        P.z[0] = mkt(vs_h, vs_l, VD, wv_h, wv_l, VD,
                     p_vproj, HID_, B_ * KOBJ, HID_, VD, bv, 1);
        tgemm_k<128><<<dim3(HID_/128, (B_*KOBJ)/128, 1), TGC<128>::THR, TGC<128>::SMEM>>>(P);
    }

    // ---- sequential decode ----
    const int gruBlocks = (B_ * HID_ + 255) / 256;
    for (int t = 0; t < TT; t++) {
        const bf16* h2p_h = h2_h + (size_t)t * B_ * HID_;
        const bf16* h2p_l = h2_l + (size_t)t * B_ * HID_;
        const float* h2prev = p_h2all + (size_t)t * B_ * HID_;
        float*       h2next = p_h2all + (size_t)(t + 1) * B_ * HID_;

        // stage1 split-K x12 (t=0's already issued at setup; reissue identical)
        stage1(h2p_h, h2p_l);
        // GRU1: gi = gi1c[t] + gih[0..3]; gh = gh1[0..3]
        {
            GruP G{};
            G.gi[0] = p_gi1c + (size_t)t * B_ * H3;
            for (int s = 0; s < 4; s++) G.gi[1 + s] = p_gih[s];
            G.ngi = 5;
            for (int s = 0; s < 4; s++) G.gh[s] = p_gh1[s];
            G.ngh = 4;
            G.biv = nullptr; G.hprev = p_h1; G.hout = p_h1;
            G.hh = h1_h; G.hl = h1_l;
            gru_kernel<<<gruBlocks, 256>>>(G);
        }
        // stage2 split-K x8: q[0..3] (K=256 each), gi2h[0..3]
        {
            TP P{}; P.mask = nullptr;
            for (int s = 0; s < 4; s++) {
                int o = s * 256;
                P.z[s]     = mkt(h1_h + o, h1_l + o, HID_, wfq_h + o, wfq_l + o, HID_,
                                 p_q[s], HID_, B_, HID_, 256, nullptr, 0);
                P.z[4 + s] = mkt(h1_h + o, h1_l + o, HID_, wf2_h + o, wf2_l + o, HID_,
                                 p_gi2h[s], H3, B_, H3, 256, nullptr, 0);
            }
            tgemm_k<64><<<dim3(H3/64, 1, 8), TGC<64>::THR, TGC<64>::SMEM>>>(P);
        }
        // attention (sums 4 q partials, relu, softmax, att_v)
        att_kernel<<<B_, 256>>>(p_q[0], p_q[1], p_q[2], p_q[3],
                                p_bfq, wa, ba, alphas, t);
        // gi2_att = att_v @ Wih2[:,:2048].T, split-K 8x256
        {
            TP P{}; P.mask = nullptr;
            for (int s = 0; s < 8; s++) {
                int o = s * 256;
                P.z[s] = mkt(av_h + o, av_l + o, VD, w2v_h + o, w2v_l + o, VD,
                             p_p0[s], H3, B_, H3, 256, nullptr, 0);
            }
            tgemm_k<64><<<dim3(H3/64, 1, 8), TGC<64>::THR, TGC<64>::SMEM>>>(P);
        }
        // GRU2: gi = p0[0..7] + gi2h[0..3] (+bi2f); gh = gh2[0..3]
        {
            GruP G{};
            for (int s = 0; s < 8; s++) G.gi[s] = p_p0[s];
            for (int s = 0; s < 4; s++) G.gi[8 + s] = p_gi2h[s];
            G.ngi = 12;
            for (int s = 0; s < 4; s++) G.gh[s] = p_gh2[s];
            G.ngh = 4;
            G.biv = p_bi2f; G.hprev = h2prev; G.hout = h2next;
            G.hh = h2_h + (size_t)(t + 1) * B_ * HID_;
            G.hl = h2_l + (size_t)(t + 1) * B_ * HID_;
            gru_kernel<<<gruBlocks, 256>>>(G);
        }
    }

    // words = H2all @ W2.T + b2 (masked scatter)  [2432 x 10000 x K=1024]
    {
        TP P{}; P.mask = p_mask;
        P.z[0] = mkt(h2_h + B_ * HID_, h2_l + B_ * HID_, HID_,
                     ww2_h, ww2_l, HID_,
                     predict, NTOK, TT * B_, NTOK, HID_, b2, 2);
        tgemm_k<128><<<dim3((NTOK + 127) / 128, (TT*B_)/128, 1),
                       TGC<128>::THR, TGC<128>::SMEM>>>(P);
    }
    zero_tails_kernel<<<(B_ * NTOK + B_ * KOBJ + 255) / 256, 256>>>(predict, alphas);
}

// round 11
// speedup vs baseline: 1.3612x; 1.0597x over previous
#include <cuda_runtime.h>
#include <cuda_bf16.h>
#include <math.h>

// ---------------------------------------------------------------------------
// BUTDDecoder: B=128, K=36, V_DIM=2048, EMBED=1024, HID=1024, NTOKEN=10000,
// MAX_LEN=20 (T=19 decode steps).
//
// Round 11: the entire 19-step decode loop runs in ONE persistent kernel
// (148 CTAs x 256 threads, software grid barrier between phases), removing
// 114 kernel launches. GEMM work is task-stripped across CTAs (128x64 tiles,
// K=512 split slices). Big GEMMs (gi1c, vproj, W2) remain host launches.
// ---------------------------------------------------------------------------

#define B_     128
#define KOBJ   36
#define VD     2048
#define EMB    1024
#define HID_   1024
#define NTOK   10000
#define MAXLEN 20
#define TT     19
#define H3     3072
#define NCTA   148

typedef unsigned long long ull;
typedef __nv_bfloat16 bf16;

// ------------------------- scratch (device globals) ------------------------
__device__ float g_vs[B_ * KOBJ * VD];
__device__ float g_vmean[B_ * VD];
__device__ float g_vproj[B_ * KOBJ * HID_];
__device__ float g_gi1c[TT * B_ * H3];
__device__ float g_h1[B_ * HID_];
__device__ float g_h2all[(TT + 1) * B_ * HID_];
__device__ float g_gih[2][B_ * H3];
__device__ float g_gh1[2][B_ * H3];
__device__ float g_gh2[2][B_ * H3];
__device__ float g_qp[2][B_ * HID_];
__device__ float g_gi2h[2][B_ * H3];
__device__ float g_p0[4][B_ * H3];
__device__ float g_Wfq[HID_ * HID_];     // Wq @ W1 (tensor precompute)
__device__ float g_Wf2h[H3 * HID_];      // Wih2[:,2048:] @ W1
__device__ float g_bfq[HID_];            // Wq@b1 + bq
__device__ float g_bi2f[H3];             // Wih2[:,2048:]@b1 + bih2
__device__ int   g_order[B_];
__device__ int   g_dl[B_];
__device__ float g_mask[TT * B_];
__device__ int          g_barc;          // grid barrier counter
__device__ volatile int g_barg;          // grid barrier generation

// bf16 hi/lo operand arrays (activations)
__device__ bf16 g_vs_h[B_ * KOBJ * VD],        g_vs_l[B_ * KOBJ * VD];
__device__ bf16 g_x1c_h[TT * B_ * H3],         g_x1c_l[TT * B_ * H3];
__device__ bf16 g_h1_h[B_ * HID_],             g_h1_l[B_ * HID_];
__device__ bf16 g_h2_h[(TT + 1) * B_ * HID_],  g_h2_l[(TT + 1) * B_ * HID_];
__device__ bf16 g_attv_h[B_ * VD],             g_attv_l[B_ * VD];

// bf16 hi/lo weight arrays
__device__ bf16 g_wih1h_h[H3 * HID_],  g_wih1h_l[H3 * HID_];   // Wih1[:, :1024]
__device__ bf16 g_wih1x_h[H3 * H3],    g_wih1x_l[H3 * H3];     // Wih1[:, 1024:]
__device__ bf16 g_whh1_h[H3 * HID_],   g_whh1_l[H3 * HID_];
__device__ bf16 g_whh2_h[H3 * HID_],   g_whh2_l[H3 * HID_];
__device__ bf16 g_wv_h[HID_ * VD],     g_wv_l[HID_ * VD];
__device__ bf16 g_wih2v_h[H3 * VD],    g_wih2v_l[H3 * VD];     // Wih2[:, :2048]
__device__ bf16 g_wih2x_h[H3 * HID_],  g_wih2x_l[H3 * HID_];   // Wih2[:, 2048:]
__device__ bf16 g_w2_h[NTOK * HID_],   g_w2_l[NTOK * HID_];
__device__ bf16 g_wq_h[HID_ * HID_],   g_wq_l[HID_ * HID_];
__device__ bf16 g_w1t_h[HID_ * HID_],  g_w1t_l[HID_ * HID_];   // W1 transposed
__device__ bf16 g_wfq_h[HID_ * HID_],  g_wfq_l[HID_ * HID_];
__device__ bf16 g_wf2h_h[H3 * HID_],   g_wf2h_l[H3 * HID_];

// --------------------------- small helpers ---------------------------------
__device__ __forceinline__ void split2(float x, bf16& h, bf16& l) {
    h = __float2bfloat16(x);
    l = __float2bfloat16(x - __bfloat162float(h));
}
__device__ __forceinline__ unsigned smem_u32(const void* p) {
    return (unsigned)__cvta_generic_to_shared(p);
}
__device__ __forceinline__ void cpa16(unsigned dst, const void* src, int sz) {
    asm volatile("cp.async.ca.shared.global [%0], [%1], 16, %2;"
                 :: "r"(dst), "l"(src), "r"(sz));
}

#define LDM_X4(r0, r1, r2, r3, addr) \
    asm volatile("ldmatrix.sync.aligned.m8n8.x4.shared.b16 {%0,%1,%2,%3}, [%4];" \
        : "=r"(r0), "=r"(r1), "=r"(r2), "=r"(r3) : "r"(addr))

#define MMA16816(c, a, b) \
    asm volatile("mma.sync.aligned.m16n8k16.row.col.f32.bf16.bf16.f32 " \
        "{%0,%1,%2,%3}, {%4,%5,%6,%7}, {%8,%9}, {%0,%1,%2,%3};" \
        : "+f"((c)[0]), "+f"((c)[1]), "+f"((c)[2]), "+f"((c)[3]) \
        : "r"((a)[0]), "r"((a)[1]), "r"((a)[2]), "r"((a)[3]), \
          "r"((b)[0]), "r"((b)[1]))

// ----------------- host-launched tensor GEMM (big GEMMs) -------------------
struct TZ {
    const bf16 *Ahi, *Alo, *Whi, *Wlo;
    float* C; const float* bias;
    int lda, ldw, ldc, M, N, K, mode;
};
struct TP { TZ z[2]; const float* mask; };

template<int BN> struct TGC {
    static constexpr int BUF   = 32768 + BN * 256;
    static constexpr int SMEM  = 2 * BUF + 1024;
    static constexpr int THR   = BN * 2;
    static constexpr int WN    = BN / 32;
    static constexpr int RPI   = BN / 4;
    static constexpr int AIT   = 128 / RPI;
};

template<int BN>
__global__ void __launch_bounds__(TGC<BN>::THR) tgemm_k(TP p)
{
    const TZ gz = p.z[blockIdx.z];
    const int bn0 = blockIdx.x * BN;  if (bn0 >= gz.N) return;
    const int bm0 = blockIdx.y * 128; if (bm0 >= gz.M) return;
    const int tid = threadIdx.x, wid = tid >> 5, lane = tid & 31;
    const int wm = wid / TGC<BN>::WN, wn = wid % TGC<BN>::WN;

    extern __shared__ char dsm[];
    unsigned dbase = smem_u32(dsm);
    unsigned s0 = (dbase + 1023u) & ~1023u;
    unsigned sAh[2], sAl[2], sBh[2], sBl[2];
#pragma unroll
    for (int b = 0; b < 2; b++) {
        sAh[b] = s0 + b * TGC<BN>::BUF;
        sAl[b] = sAh[b] + 16384;
        sBh[b] = sAl[b] + 16384;
        sBl[b] = sBh[b] + BN * 128;
    }

    const int lrow = tid >> 3;
    const int lch  = tid & 7;
    auto load_chunk = [&](int c, int buf) {
        const int c0 = c * 64;
#pragma unroll
        for (int i = 0; i < TGC<BN>::AIT; i++) {
            int row = i * TGC<BN>::RPI + lrow;
            unsigned off = (unsigned)(row * 128) + (unsigned)(((lch ^ (row & 7)) * 16));
            cpa16(sAh[buf] + off, gz.Ahi + (size_t)(bm0 + row) * gz.lda + c0 + lch * 8, 16);
            cpa16(sAl[buf] + off, gz.Alo + (size_t)(bm0 + row) * gz.lda + c0 + lch * 8, 16);
        }
#pragma unroll
        for (int i = 0; i < 4; i++) {
            int row = i * TGC<BN>::RPI + lrow;
            unsigned off = (unsigned)(row * 128) + (unsigned)(((lch ^ (row & 7)) * 16));
            int n = bn0 + row;
            int sz = (n < gz.N) ? 16 : 0;
            int nn = (n < gz.N) ? n : 0;
            cpa16(sBh[buf] + off, gz.Whi + (size_t)nn * gz.ldw + c0 + lch * 8, sz);
            cpa16(sBl[buf] + off, gz.Wlo + (size_t)nn * gz.ldw + c0 + lch * 8, sz);
        }
        asm volatile("cp.async.commit_group;");
    };

    float acc[4][4][4];
#pragma unroll
    for (int mi = 0; mi < 4; mi++)
#pragma unroll
        for (int nj = 0; nj < 4; nj++)
#pragma unroll
            for (int e = 0; e < 4; e++) acc[mi][nj][e] = 0.f;

    const int xorkey = lane & 7;
    const int nch = gz.K / 64;
    load_chunk(0, 0);

    for (int c = 0; c < nch; c++) {
        if (c + 1 < nch) {
            load_chunk(c + 1, (c + 1) & 1);
            asm volatile("cp.async.wait_group 1;");
        } else {
            asm volatile("cp.async.wait_group 0;");
        }
        __syncthreads();
        const unsigned tAh = sAh[c & 1], tAl = sAl[c & 1];
        const unsigned tBh = sBh[c & 1], tBl = sBl[c & 1];
#pragma unroll
        for (int ks = 0; ks < 4; ks++) {
            unsigned Ah[4][4], Al[4][4];
            {
                const int arow = wm * 64 + (lane & 15);
                const unsigned aoff =
                    (unsigned)((((2 * ks) + (lane >> 4)) ^ xorkey) * 16);
#pragma unroll
                for (int mi = 0; mi < 4; mi++) {
                    unsigned ad = (unsigned)((arow + mi * 16) * 128) + aoff;
                    LDM_X4(Ah[mi][0], Ah[mi][1], Ah[mi][2], Ah[mi][3], tAh + ad);
                    LDM_X4(Al[mi][0], Al[mi][1], Al[mi][2], Al[mi][3], tAl + ad);
                }
            }
            unsigned Bh[4][2], Bl[4][2];
            {
                const int brow = wn * 32 + (lane & 7) + ((lane >> 4) << 3);
                const unsigned boff =
                    (unsigned)((((2 * ks) + ((lane >> 3) & 1)) ^ xorkey) * 16);
                unsigned r0, r1, r2, r3;
                unsigned b0 = (unsigned)(brow * 128) + boff;
                LDM_X4(r0, r1, r2, r3, tBh + b0);
                Bh[0][0] = r0; Bh[0][1] = r1; Bh[1][0] = r2; Bh[1][1] = r3;
                LDM_X4(r0, r1, r2, r3, tBh + b0 + 16 * 128);
                Bh[2][0] = r0; Bh[2][1] = r1; Bh[3][0] = r2; Bh[3][1] = r3;
                LDM_X4(r0, r1, r2, r3, tBl + b0);
                Bl[0][0] = r0; Bl[0][1] = r1; Bl[1][0] = r2; Bl[1][1] = r3;
                LDM_X4(r0, r1, r2, r3, tBl + b0 + 16 * 128);
                Bl[2][0] = r0; Bl[2][1] = r1; Bl[3][0] = r2; Bl[3][1] = r3;
            }
#pragma unroll
            for (int mi = 0; mi < 4; mi++)
#pragma unroll
                for (int nj = 0; nj < 4; nj++) {
                    MMA16816(acc[mi][nj], Ah[mi], Bh[nj]);
                    MMA16816(acc[mi][nj], Ah[mi], Bl[nj]);
                    MMA16816(acc[mi][nj], Al[mi], Bh[nj]);
                }
        }
        __syncthreads();
    }

    const int g = lane >> 2, tig = lane & 3;
    auto stc = [&](int m, int n, float val) {
        if (n >= gz.N) return;
        if (gz.bias) val += gz.bias[n];
        if (gz.mode == 1) val = fmaxf(val, 0.f);
        if (gz.mode == 2) {
            int tt = m / B_, bb = m % B_;
            gz.C[((size_t)bb * MAXLEN + tt) * gz.ldc + n] = val * p.mask[m];
        } else {
            gz.C[(size_t)m * gz.ldc + n] = val;
        }
    };
#pragma unroll
    for (int mi = 0; mi < 4; mi++)
#pragma unroll
        for (int nj = 0; nj < 4; nj++) {
            int row = bm0 + wm * 64 + mi * 16 + g;
            int col = bn0 + wn * 32 + nj * 8 + 2 * tig;
            stc(row,     col,     acc[mi][nj][0]);
            stc(row,     col + 1, acc[mi][nj][1]);
            stc(row + 8, col,     acc[mi][nj][2]);
            stc(row + 8, col + 1, acc[mi][nj][3]);
        }
}

// ------------------ persistent-loop device machinery ------------------------
__device__ __forceinline__ void grid_bar()
{
    __syncthreads();
    if (threadIdx.x == 0) {
        int gen = g_barg;
        __threadfence();
        if (atomicAdd(&g_barc, 1) == NCTA - 1) {
            g_barc = 0;
            __threadfence();
            g_barg = gen + 1;
        } else {
            while (g_barg == gen) __nanosleep(32);
            __threadfence();
        }
    }
    __syncthreads();
}

// one 128x64xK GEMM tile, 256 threads (8 warps: 4m x 2n), K multiple of 64.
// C[m, bn0+n] = sum_k A[m,k]*W[bn0+n,k]  (+bias)
__device__ void gemm_task(const bf16* __restrict__ Ah0, const bf16* __restrict__ Al0,
                          int lda,
                          const bf16* __restrict__ Wh0, const bf16* __restrict__ Wl0,
                          int ldw,
                          float* __restrict__ C, int ldc, int bn0, int Ksz,
                          const float* __restrict__ bias, char* dsm)
{
    const int tid = threadIdx.x, wid = tid >> 5, lane = tid & 31;
    const int wm = wid >> 1, wn = wid & 1;

    unsigned dbase = smem_u32(dsm);
    unsigned s0 = (dbase + 1023u) & ~1023u;
    unsigned sAh[2], sAl[2], sBh[2], sBl[2];
#pragma unroll
    for (int b = 0; b < 2; b++) {
        sAh[b] = s0 + b * 49152;
        sAl[b] = sAh[b] + 16384;
        sBh[b] = sAl[b] + 16384;
        sBl[b] = sBh[b] + 8192;
    }

    const int lrow = tid >> 3;         // 0..31
    const int lch  = tid & 7;
    const bf16* Wb_h = Wh0 + (size_t)bn0 * ldw;
    const bf16* Wb_l = Wl0 + (size_t)bn0 * ldw;
    auto load_chunk = [&](int c, int buf) {
        const int c0 = c * 64;
#pragma unroll
        for (int i = 0; i < 4; i++) {
            int row = i * 32 + lrow;
            unsigned off = (unsigned)(row * 128) + (unsigned)(((lch ^ (row & 7)) * 16));
            cpa16(sAh[buf] + off, Ah0 + (size_t)row * lda + c0 + lch * 8, 16);
            cpa16(sAl[buf] + off, Al0 + (size_t)row * lda + c0 + lch * 8, 16);
        }
#pragma unroll
        for (int i = 0; i < 2; i++) {
            int row = i * 32 + lrow;
            unsigned off = (unsigned)(row * 128) + (unsigned)(((lch ^ (row & 7)) * 16));
            cpa16(sBh[buf] + off, Wb_h + (size_t)row * ldw + c0 + lch * 8, 16);
            cpa16(sBl[buf] + off, Wb_l + (size_t)row * ldw + c0 + lch * 8, 16);
        }
        asm volatile("cp.async.commit_group;");
    };

    float acc[2][4][4];
#pragma unroll
    for (int mi = 0; mi < 2; mi++)
#pragma unroll
        for (int nj = 0; nj < 4; nj++)
#pragma unroll
            for (int e = 0; e < 4; e++) acc[mi][nj][e] = 0.f;

    const int xorkey = lane & 7;
    const int nch = Ksz / 64;
    load_chunk(0, 0);

    for (int c = 0; c < nch; c++) {
        if (c + 1 < nch) {
            load_chunk(c + 1, (c + 1) & 1);
            asm volatile("cp.async.wait_group 1;");
        } else {
            asm volatile("cp.async.wait_group 0;");
        }
        __syncthreads();
        const unsigned tAh = sAh[c & 1], tAl = sAl[c & 1];
        const unsigned tBh = sBh[c & 1], tBl = sBl[c & 1];
#pragma unroll
        for (int ks = 0; ks < 4; ks++) {
            unsigned Ahf[2][4], Alf[2][4];
            {
                const int arow = wm * 32 + (lane & 15);
                const unsigned aoff =
                    (unsigned)((((2 * ks) + (lane >> 4)) ^ xorkey) * 16);
#pragma unroll
                for (int mi = 0; mi < 2; mi++) {
                    unsigned ad = (unsigned)((arow + mi * 16) * 128) + aoff;
                    LDM_X4(Ahf[mi][0], Ahf[mi][1], Ahf[mi][2], Ahf[mi][3], tAh + ad);
                    LDM_X4(Alf[mi][0], Alf[mi][1], Alf[mi][2], Alf[mi][3], tAl + ad);
                }
            }
            unsigned Bh[4][2], Bl[4][2];
            {
                const int brow = wn * 32 + (lane & 7) + ((lane >> 4) << 3);
                const unsigned boff =
                    (unsigned)((((2 * ks) + ((lane >> 3) & 1)) ^ xorkey) * 16);
                unsigned r0, r1, r2, r3;
                unsigned b0 = (unsigned)(brow * 128) + boff;
                LDM_X4(r0, r1, r2, r3, tBh + b0);
                Bh[0][0] = r0; Bh[0][1] = r1; Bh[1][0] = r2; Bh[1][1] = r3;
                LDM_X4(r0, r1, r2, r3, tBh + b0 + 16 * 128);
                Bh[2][0] = r0; Bh[2][1] = r1; Bh[3][0] = r2; Bh[3][1] = r3;
                LDM_X4(r0, r1, r2, r3, tBl + b0);
                Bl[0][0] = r0; Bl[0][1] = r1; Bl[1][0] = r2; Bl[1][1] = r3;
                LDM_X4(r0, r1, r2, r3, tBl + b0 + 16 * 128);
                Bl[2][0] = r0; Bl[2][1] = r1; Bl[3][0] = r2; Bl[3][1] = r3;
            }
#pragma unroll
            for (int mi = 0; mi < 2; mi++)
#pragma unroll
                for (int nj = 0; nj < 4; nj++) {
                    MMA16816(acc[mi][nj], Ahf[mi], Bh[nj]);
                    MMA16816(acc[mi][nj], Ahf[mi], Bl[nj]);
                    MMA16816(acc[mi][nj], Alf[mi], Bh[nj]);
                }
        }
        __syncthreads();
    }

    const int g = lane >> 2, tig = lane & 3;
#pragma unroll
    for (int mi = 0; mi < 2; mi++)
#pragma unroll
        for (int nj = 0; nj < 4; nj++) {
            int row = wm * 32 + mi * 16 + g;
            int col = bn0 + wn * 32 + nj * 8 + 2 * tig;
            float v0 = acc[mi][nj][0], v1 = acc[mi][nj][1];
            float v2 = acc[mi][nj][2], v3 = acc[mi][nj][3];
            if (bias) {
                v0 += bias[col]; v1 += bias[col + 1];
                v2 += bias[col]; v3 += bias[col + 1];
            }
            C[(size_t)row * ldc + col]           = v0;
            C[(size_t)row * ldc + col + 1]       = v1;
            C[(size_t)(row + 8) * ldc + col]     = v2;
            C[(size_t)(row + 8) * ldc + col + 1] = v3;
        }
}

// ------------------------- persistent loop kernel ---------------------------
__global__ void __launch_bounds__(256) loop_kernel(
    const float* __restrict__ bhh1, const float* __restrict__ bhh2,
    const float* __restrict__ wa,   const float* __restrict__ ba,
    float* __restrict__ alphas)
{
    extern __shared__ char dsm[];
    const int cta = blockIdx.x;
    const int tid = threadIdx.x;

    for (int t = 0; t < TT; t++) {
        const bf16*  h2ph = g_h2_h + (size_t)t * B_ * HID_;
        const bf16*  h2pl = g_h2_l + (size_t)t * B_ * HID_;
        const float* h2prev = g_h2all + (size_t)t * B_ * HID_;
        float*       h2next = g_h2all + (size_t)(t + 1) * B_ * HID_;

        // ---- phase 1: stage1 (gih, gh1, gh2), 288 tasks of 128x64xK512 ----
        for (int task = cta; task < 288; task += NCTA) {
            int s = task & 1, x = (task >> 1) % 48, o = task / 96;
            int ko = s * 512;
            if (o == 0)
                gemm_task(h2ph + ko, h2pl + ko, HID_,
                          g_wih1h_h + ko, g_wih1h_l + ko, HID_,
                          g_gih[s], H3, x * 64, 512, nullptr, dsm);
            else if (o == 1)
                gemm_task(g_h1_h + ko, g_h1_l + ko, HID_,
                          g_whh1_h + ko, g_whh1_l + ko, HID_,
                          g_gh1[s], H3, x * 64, 512, s == 0 ? bhh1 : nullptr, dsm);
            else
                gemm_task(h2ph + ko, h2pl + ko, HID_,
                          g_whh2_h + ko, g_whh2_l + ko, HID_,
                          g_gh2[s], H3, x * 64, 512, s == 0 ? bhh2 : nullptr, dsm);
        }
        grid_bar();

        // ---- phase 2: GRU1 pointwise ----
        {
            const float* gic = g_gi1c + (size_t)t * B_ * H3;
            for (int idx = cta * 256 + tid; idx < B_ * HID_; idx += NCTA * 256) {
                int b = idx >> 10, j = idx & 1023;
                size_t base = (size_t)b * H3 + j;
                float gr = gic[base] + g_gih[0][base] + g_gih[1][base];
                float gz = gic[base + HID_] + g_gih[0][base + HID_] + g_gih[1][base + HID_];
                float gn = gic[base + 2*HID_] + g_gih[0][base + 2*HID_] + g_gih[1][base + 2*HID_];
                float ghr = g_gh1[0][base] + g_gh1[1][base];
                float ghz = g_gh1[0][base + HID_] + g_gh1[1][base + HID_];
                float ghn = g_gh1[0][base + 2*HID_] + g_gh1[1][base + 2*HID_];
                float r = 1.f / (1.f + expf(-(gr + ghr)));
                float z = 1.f / (1.f + expf(-(gz + ghz)));
                float n = tanhf(gn + r * ghn);
                float h = (1.f - z) * n + z * g_h1[idx];
                g_h1[idx] = h;
                split2(h, g_h1_h[idx], g_h1_l[idx]);
            }
        }
        grid_bar();

        // ---- phase 3: stage2 (q 32 tasks, gi2h 96 tasks), K=512 ----
        for (int task = cta; task < 128; task += NCTA) {
            if (task < 32) {
                int s = task & 1, x = (task >> 1);
                int ko = s * 512;
                gemm_task(g_h1_h + ko, g_h1_l + ko, HID_,
                          g_wfq_h + ko, g_wfq_l + ko, HID_,
                          g_qp[s], HID_, x * 64, 512, nullptr, dsm);
            } else {
                int u = task - 32;
                int s = u & 1, x = (u >> 1);
                int ko = s * 512;
                gemm_task(g_h1_h + ko, g_h1_l + ko, HID_,
                          g_wf2h_h + ko, g_wf2h_l + ko, HID_,
                          g_gi2h[s], H3, x * 64, 512, nullptr, dsm);
            }
        }
        grid_bar();

        // ---- phase 4: attention, one batch row per CTA ----
        for (int b = cta; b < B_; b += NCTA) {
            float* qs  = (float*)dsm;            // 1024 floats
            float* att = qs + HID_;              // 36 floats
            for (int d = tid; d < HID_; d += 256) {
                float qv = g_qp[0][b * HID_ + d] + g_qp[1][b * HID_ + d] + g_bfq[d];
                qs[d] = fmaxf(qv, 0.f) * wa[d];
            }
            __syncthreads();
            int warp = tid >> 5, lane = tid & 31;
            for (int k = warp; k < KOBJ; k += 8) {
                const float* vp = g_vproj + ((size_t)b * KOBJ + k) * HID_;
                float s = 0.f;
                for (int d = lane; d < HID_; d += 32) s += vp[d] * qs[d];
#pragma unroll
                for (int o = 16; o; o >>= 1) s += __shfl_down_sync(0xffffffffu, s, o);
                if (lane == 0) att[k] = s + ba[0];
            }
            __syncthreads();
            if (tid == 0) {
                float mx = att[0];
                for (int k = 1; k < KOBJ; k++) mx = fmaxf(mx, att[k]);
                float ssum = 0.f;
                for (int k = 0; k < KOBJ; k++) { float e = expf(att[k] - mx); att[k] = e; ssum += e; }
                float inv = 1.f / ssum;
                for (int k = 0; k < KOBJ; k++) att[k] *= inv;
            }
            __syncthreads();
            if (tid < KOBJ) {
                float m = (t < g_dl[b]) ? 1.f : 0.f;
                alphas[((size_t)b * MAXLEN + t) * KOBJ + tid] = att[tid] * m;
            }
            for (int d = tid; d < VD; d += 256) {
                const float* vb = g_vs + (size_t)b * KOBJ * VD + d;
                float s = 0.f;
#pragma unroll 6
                for (int k = 0; k < KOBJ; k++) s += att[k] * vb[(size_t)k * VD];
                split2(s, g_attv_h[b * VD + d], g_attv_l[b * VD + d]);
            }
            __syncthreads();
        }
        grid_bar();

        // ---- phase 5: gi2att, 192 tasks (48 tiles x K-slice 4), K=512 ----
        for (int task = cta; task < 192; task += NCTA) {
            int s = task & 3, x = task >> 2;
            int ko = s * 512;
            gemm_task(g_attv_h + ko, g_attv_l + ko, VD,
                      g_wih2v_h + ko, g_wih2v_l + ko, VD,
                      g_p0[s], H3, x * 64, 512, nullptr, dsm);
        }
        grid_bar();

        // ---- phase 6: GRU2 pointwise ----
        {
            bf16* hh = g_h2_h + (size_t)(t + 1) * B_ * HID_;
            bf16* hl = g_h2_l + (size_t)(t + 1) * B_ * HID_;
            for (int idx = cta * 256 + tid; idx < B_ * HID_; idx += NCTA * 256) {
                int b = idx >> 10, j = idx & 1023;
                size_t base = (size_t)b * H3 + j;
                float gr = g_bi2f[j], gz = g_bi2f[j + HID_], gn = g_bi2f[j + 2*HID_];
#pragma unroll
                for (int s = 0; s < 4; s++) {
                    gr += g_p0[s][base]; gz += g_p0[s][base + HID_]; gn += g_p0[s][base + 2*HID_];
                }
#pragma unroll
                for (int s = 0; s < 2; s++) {
                    gr += g_gi2h[s][base]; gz += g_gi2h[s][base + HID_]; gn += g_gi2h[s][base + 2*HID_];
                }
                float ghr = g_gh2[0][base] + g_gh2[1][base];
                float ghz = g_gh2[0][base + HID_] + g_gh2[1][base + HID_];
                float ghn = g_gh2[0][base + 2*HID_] + g_gh2[1][base + 2*HID_];
                float r = 1.f / (1.f + expf(-(gr + ghr)));
                float z = 1.f / (1.f + expf(-(gz + ghz)));
                float n = tanhf(gn + r * ghn);
                float h = (1.f - z) * n + z * h2prev[idx];
                h2next[idx] = h;
                split2(h, hh[idx], hl[idx]);
            }
        }
        grid_bar();
    }
}

// ------------------------------- small kernels -----------------------------
__global__ void meta_kernel(const int* __restrict__ cap_len)
{
    int i = threadIdx.x;
    int ci = cap_len[i];
    int rank = 0;
    for (int j = 0; j < B_; j++) {
        int cj = cap_len[j];
        if (cj > ci || (cj == ci && j < i)) rank++;
    }
    g_order[rank] = i;
    __syncthreads();
    g_dl[i] = cap_len[g_order[i]] - 1;
    __syncthreads();
    int dli = g_dl[i];
    for (int t = 0; t < TT; t++) g_mask[t * B_ + i] = (t < dli) ? 1.f : 0.f;
    if (i == 0) { g_barc = 0; g_barg = 0; }
}

__global__ void zero_init_kernel()
{
    int idx = blockIdx.x * 256 + threadIdx.x;
    if (idx < B_ * HID_) {
        g_h1[idx] = 0.f;    g_h1_h[idx] = __float2bfloat16(0.f); g_h1_l[idx] = __float2bfloat16(0.f);
        g_h2all[idx] = 0.f; g_h2_h[idx] = __float2bfloat16(0.f); g_h2_l[idx] = __float2bfloat16(0.f);
    }
}

__global__ void permute_v_kernel(const float* __restrict__ v)
{
    size_t idx = (size_t)blockIdx.x * 256 + threadIdx.x;
    if (idx >= (size_t)B_ * KOBJ * VD) return;
    int b = (int)(idx / ((size_t)KOBJ * VD));
    size_t rest = idx % ((size_t)KOBJ * VD);
    float x = v[(size_t)g_order[b] * KOBJ * VD + rest];
    g_vs[idx] = x;
    split2(x, g_vs_h[idx], g_vs_l[idx]);
}

__global__ void vmean_kernel()
{
    int idx = blockIdx.x * 256 + threadIdx.x;
    if (idx >= B_ * VD) return;
    int b = idx / VD, d = idx % VD;
    const float* p = g_vs + (size_t)b * KOBJ * VD + d;
    float s = 0.f;
#pragma unroll 6
    for (int k = 0; k < KOBJ; k++) s += p[(size_t)k * VD];
    g_vmean[idx] = s * (1.f / (float)KOBJ);
}

__global__ void build_x1c_kernel(const float* __restrict__ caption)
{
    size_t idx = (size_t)blockIdx.x * 256 + threadIdx.x;
    if (idx >= (size_t)TT * B_ * H3) return;
    int c = (int)(idx % H3);
    int r = (int)(idx / H3);
    int t = r / B_, b = r % B_;
    float val;
    if (c < VD) val = g_vmean[b * VD + c];
    else        val = caption[((size_t)g_order[b] * MAXLEN + t) * EMB + (c - VD)];
    split2(val, g_x1c_h[idx], g_x1c_l[idx]);
}

__global__ void convw_kernel(const float* __restrict__ src, int ld, int col0,
                             int rows, int cols, bf16* __restrict__ hi,
                             bf16* __restrict__ lo)
{
    size_t idx = (size_t)blockIdx.x * 256 + threadIdx.x;
    if (idx >= (size_t)rows * cols) return;
    int r = (int)(idx / cols), c = (int)(idx % cols);
    split2(src[(size_t)r * ld + col0 + c], hi[idx], lo[idx]);
}

__global__ void tsplit_kernel(const float* __restrict__ src,
                              bf16* __restrict__ hi, bf16* __restrict__ lo)
{
    __shared__ float tile[32][33];
    int bx = blockIdx.x * 32, by = blockIdx.y * 32;
#pragma unroll
    for (int i = 0; i < 32; i += 8)
        tile[threadIdx.y + i][threadIdx.x] =
            src[(size_t)(by + threadIdx.y + i) * HID_ + bx + threadIdx.x];
    __syncthreads();
#pragma unroll
    for (int i = 0; i < 32; i += 8) {
        float vv = tile[threadIdx.x][threadIdx.y + i];
        size_t o = (size_t)(bx + threadIdx.y + i) * HID_ + by + threadIdx.x;
        split2(vv, hi[o], lo[o]);
    }
}

__global__ void fusebias_kernel(const float* __restrict__ Wq,
                                const float* __restrict__ bq,
                                const float* __restrict__ b1,
                                const float* __restrict__ Wih2,
                                const float* __restrict__ bih2)
{
    int idx = blockIdx.x * 256 + threadIdx.x;
    if (idx < HID_) {
        const float* w = Wq + (size_t)idx * HID_;
        float s = 0.f;
        for (int j = 0; j < HID_; j++) s += w[j] * b1[j];
        g_bfq[idx] = s + bq[idx];
    } else if (idx < HID_ + H3) {
        int n = idx - HID_;
        const float* w = Wih2 + (size_t)n * H3 + VD;
        float s = 0.f;
        for (int j = 0; j < HID_; j++) s += w[j] * b1[j];
        g_bi2f[n] = s + bih2[n];
    }
}

__global__ void zero_tails_kernel(float* __restrict__ predict,
                                  float* __restrict__ alphas)
{
    int idx = blockIdx.x * 256 + threadIdx.x;
    if (idx < B_ * NTOK) {
        int b = idx / NTOK, n = idx % NTOK;
        predict[((size_t)b * MAXLEN + (MAXLEN - 1)) * NTOK + n] = 0.f;
    } else if (idx < B_ * NTOK + B_ * KOBJ) {
        int r = idx - B_ * NTOK;
        int b = r / KOBJ, k = r % KOBJ;
        alphas[((size_t)b * MAXLEN + (MAXLEN - 1)) * KOBJ + k] = 0.f;
    }
}

// --------------------------------- launch ----------------------------------
static inline TZ mkt(const bf16* Ah, const bf16* Al, int lda,
                     const bf16* Wh, const bf16* Wl, int ldw,
                     float* C, int ldc, int M, int N, int K,
                     const float* bias, int mode)
{
    TZ z; z.Ahi = Ah; z.Alo = Al; z.Whi = Wh; z.Wlo = Wl;
    z.C = C; z.bias = bias; z.lda = lda; z.ldw = ldw; z.ldc = ldc;
    z.M = M; z.N = N; z.K = K; z.mode = mode;
    return z;
}

#define SYMADDR(var, sym) cudaGetSymbolAddress((void**)&var, sym)

extern "C" void kernel_launch(void* const* d_in, const int* in_sizes, int n_in,
                              void* d_out, int out_size)
{
    const float* v       = (const float*)d_in[0];
    const float* caption = (const float*)d_in[1];
    const int*   cap_len = (const int*)  d_in[2];
    const float* Wih1    = (const float*)d_in[3];
    const float* Whh1    = (const float*)d_in[4];
    const float* bih1    = (const float*)d_in[5];
    const float* bhh1    = (const float*)d_in[6];
    const float* Wih2    = (const float*)d_in[7];
    const float* Whh2    = (const float*)d_in[8];
    const float* bih2    = (const float*)d_in[9];
    const float* bhh2    = (const float*)d_in[10];
    const float* Wv      = (const float*)d_in[11];
    const float* bv      = (const float*)d_in[12];
    const float* Wq      = (const float*)d_in[13];
    const float* bq      = (const float*)d_in[14];
    const float* wa      = (const float*)d_in[15];
    const float* ba      = (const float*)d_in[16];
    const float* W1      = (const float*)d_in[17];
    const float* b1      = (const float*)d_in[18];
    const float* W2      = (const float*)d_in[19];
    const float* b2      = (const float*)d_in[20];

    float* out     = (float*)d_out;
    float* predict = out;
    float* alphas  = out + (size_t)B_ * MAXLEN * NTOK;

    float *p_gi1c, *p_Wfq, *p_Wf2h, *p_mask, *p_vproj;
    SYMADDR(p_gi1c, g_gi1c);  SYMADDR(p_Wfq, g_Wfq);  SYMADDR(p_Wf2h, g_Wf2h);
    SYMADDR(p_mask, g_mask);  SYMADDR(p_vproj, g_vproj);

    bf16 *vs_h, *vs_l, *x1c_h, *x1c_l, *h2_h, *h2_l;
    bf16 *w1h_h, *w1h_l, *w1x_h, *w1x_l, *wh1_h, *wh1_l, *wh2_h, *wh2_l;
    bf16 *wv_h, *wv_l, *w2v_h, *w2v_l, *w2x_h, *w2x_l, *ww2_h, *ww2_l;
    bf16 *wq_h, *wq_l, *w1t_h, *w1t_l, *wfq_h, *wfq_l, *wf2_h, *wf2_l;
    SYMADDR(vs_h, g_vs_h);   SYMADDR(vs_l, g_vs_l);
    SYMADDR(x1c_h, g_x1c_h); SYMADDR(x1c_l, g_x1c_l);
    SYMADDR(h2_h, g_h2_h);   SYMADDR(h2_l, g_h2_l);
    SYMADDR(w1h_h, g_wih1h_h); SYMADDR(w1h_l, g_wih1h_l);
    SYMADDR(w1x_h, g_wih1x_h); SYMADDR(w1x_l, g_wih1x_l);
    SYMADDR(wh1_h, g_whh1_h);  SYMADDR(wh1_l, g_whh1_l);
    SYMADDR(wh2_h, g_whh2_h);  SYMADDR(wh2_l, g_whh2_l);
    SYMADDR(wv_h, g_wv_h);     SYMADDR(wv_l, g_wv_l);
    SYMADDR(w2v_h, g_wih2v_h); SYMADDR(w2v_l, g_wih2v_l);
    SYMADDR(w2x_h, g_wih2x_h); SYMADDR(w2x_l, g_wih2x_l);
    SYMADDR(ww2_h, g_w2_h);    SYMADDR(ww2_l, g_w2_l);
    SYMADDR(wq_h, g_wq_h);     SYMADDR(wq_l, g_wq_l);
    SYMADDR(w1t_h, g_w1t_h);   SYMADDR(w1t_l, g_w1t_l);
    SYMADDR(wfq_h, g_wfq_h);   SYMADDR(wfq_l, g_wfq_l);
    SYMADDR(wf2_h, g_wf2h_h);  SYMADDR(wf2_l, g_wf2h_l);

    const int LOOPSMEM = 2 * 49152 + 1024;
    cudaFuncSetAttribute(tgemm_k<64>,  cudaFuncAttributeMaxDynamicSharedMemorySize,
                         TGC<64>::SMEM);
    cudaFuncSetAttribute(tgemm_k<128>, cudaFuncAttributeMaxDynamicSharedMemorySize,
                         TGC<128>::SMEM);
    cudaFuncSetAttribute(loop_kernel,  cudaFuncAttributeMaxDynamicSharedMemorySize,
                         LOOPSMEM);

    auto cv = [](const float* s, int ld, int c0, int r, int c, bf16* h, bf16* l) {
        size_t n = (size_t)r * c;
        convw_kernel<<<(unsigned)((n + 255) / 256), 256>>>(s, ld, c0, r, c, h, l);
    };

    // ---- setup (launch #6 = gi1c big GEMM for ncu) ----
    meta_kernel<<<1, B_>>>(cap_len);                                       // 1
    cv(Wih1, HID_ + VD + EMB, 1024, H3, H3, w1x_h, w1x_l);                 // 2
    permute_v_kernel<<<(unsigned)(((size_t)B_*KOBJ*VD + 255)/256), 256>>>(v); // 3
    vmean_kernel<<<(B_ * VD + 255) / 256, 256>>>();                        // 4
    build_x1c_kernel<<<(unsigned)(((size_t)TT*B_*H3 + 255)/256), 256>>>(caption); // 5
    {   // 6: gi1c = X1c @ Wih1[:,1024:].T + bih1   [2432 x 3072 x K=3072]
        TP P{}; P.mask = nullptr;
        P.z[0] = mkt(x1c_h, x1c_l, H3, w1x_h, w1x_l, H3,
                     p_gi1c, H3, TT * B_, H3, H3, bih1, 0);
        tgemm_k<128><<<dim3(H3/128, (TT*B_)/128, 1), TGC<128>::THR, TGC<128>::SMEM>>>(P);
    }
    zero_init_kernel<<<(B_ * HID_ + 255) / 256, 256>>>();
    cv(Wih1, HID_ + VD + EMB, 0,    H3,   HID_, w1h_h, w1h_l);
    cv(Whh1, HID_,            0,    H3,   HID_, wh1_h, wh1_l);
    cv(Whh2, HID_,            0,    H3,   HID_, wh2_h, wh2_l);
    cv(Wv,   VD,              0,    HID_, VD,   wv_h,  wv_l);
    cv(Wih2, H3,              0,    H3,   VD,   w2v_h, w2v_l);
    cv(Wih2, H3,              2048, H3,   HID_, w2x_h, w2x_l);
    cv(Wq,   HID_,            0,    HID_, HID_, wq_h,  wq_l);
    cv(W2,   HID_,            0,    NTOK, HID_, ww2_h, ww2_l);
    tsplit_kernel<<<dim3(32, 32), dim3(32, 8)>>>(W1, w1t_h, w1t_l);
    {   // tensor precompute: Wfq = Wq@W1 (via W1T); Wf2h = Wih2x@W1
        TP P{}; P.mask = nullptr;
        P.z[0] = mkt(wq_h,  wq_l,  HID_, w1t_h, w1t_l, HID_,
                     p_Wfq,  HID_, HID_, HID_, HID_, nullptr, 0);
        P.z[1] = mkt(w2x_h, w2x_l, HID_, w1t_h, w1t_l, HID_,
                     p_Wf2h, HID_, H3,   HID_, HID_, nullptr, 0);
        tgemm_k<64><<<dim3(HID_/64, H3/128, 2), TGC<64>::THR, TGC<64>::SMEM>>>(P);
    }
    cv(p_Wfq,  HID_, 0, HID_, HID_, wfq_h, wfq_l);
    cv(p_Wf2h, HID_, 0, H3,   HID_, wf2_h, wf2_l);
    fusebias_kernel<<<(HID_ + H3 + 255) / 256, 256>>>(Wq, bq, b1, Wih2, bih2);
    {   // vproj = relu(v_s @ Wv.T + bv)         [4608 x 1024 x K=2048]
        TP P{}; P.mask = nullptr;
        P.z[0] = mkt(vs_h, vs_l, VD, wv_h, wv_l, VD,
                     p_vproj, HID_, B_ * KOBJ, HID_, VD, bv, 1);
        tgemm_k<128><<<dim3(HID_/128, (B_*KOBJ)/128, 1), TGC<128>::THR, TGC<128>::SMEM>>>(P);
    }

    // ---- persistent decode loop (replaces 114 launches) ----
    loop_kernel<<<NCTA, 256, LOOPSMEM>>>(bhh1, bhh2, wa, ba, alphas);

    // ---- words = H2all @ W2.T + b2 (masked scatter) ----
    {
        TP P{}; P.mask = p_mask;
        P.z[0] = mkt(h2_h + B_ * HID_, h2_l + B_ * HID_, HID_,
                     ww2_h, ww2_l, HID_,
                     predict, NTOK, TT * B_, NTOK, HID_, b2, 2);
        tgemm_k<128><<<dim3((NTOK + 127) / 128, (TT*B_)/128, 1),
                       TGC<128>::THR, TGC<128>::SMEM>>>(P);
    }
    zero_tails_kernel<<<(B_ * NTOK + B_ * KOBJ + 255) / 256, 256>>>(predict, alphas);
}

// round 12
// speedup vs baseline: 1.4072x; 1.0338x over previous
#include <cuda_runtime.h>
#include <cuda_bf16.h>
#include <math.h>

// ---------------------------------------------------------------------------
// BUTDDecoder: B=128, K=36, V_DIM=2048, EMBED=1024, HID=1024, NTOKEN=10000,
// MAX_LEN=20 (T=19 decode steps).
//
// Round 12:
//  * gi1c decomposed: time-invariant v_mean part computed once (giv), only
//    the prev-embedding part (gip, K=1024) per timestep.
//  * persistent loop at 2 CTAs/SM (296 CTAs, launch_bounds(256,2),
//    single-buffered 50KB smem) -> every GEMM phase is one round.
// ---------------------------------------------------------------------------

#define B_     128
#define KOBJ   36
#define VD     2048
#define EMB    1024
#define HID_   1024
#define NTOK   10000
#define MAXLEN 20
#define TT     19
#define H3     3072
#define NCTA   296

typedef unsigned long long ull;
typedef __nv_bfloat16 bf16;

// ------------------------- scratch (device globals) ------------------------
__device__ float g_vs[B_ * KOBJ * VD];
__device__ float g_vmean[B_ * VD];
__device__ float g_vproj[B_ * KOBJ * HID_];
__device__ float g_giv[B_ * H3];            // v_mean part of gi1 (+bih1)
__device__ float g_gip[TT * B_ * H3];       // prev part of gi1
__device__ float g_h1[B_ * HID_];
__device__ float g_h2all[(TT + 1) * B_ * HID_];
__device__ float g_gih[2][B_ * H3];
__device__ float g_gh1[2][B_ * H3];
__device__ float g_gh2[2][B_ * H3];
__device__ float g_qp[2][B_ * HID_];
__device__ float g_gi2h[2][B_ * H3];
__device__ float g_p0[4][B_ * H3];
__device__ float g_Wfq[HID_ * HID_];
__device__ float g_Wf2h[H3 * HID_];
__device__ float g_bfq[HID_];
__device__ float g_bi2f[H3];
__device__ int   g_order[B_];
__device__ int   g_dl[B_];
__device__ float g_mask[TT * B_];
__device__ int          g_barc;
__device__ volatile int g_barg;

// bf16 hi/lo operand arrays (activations)
__device__ bf16 g_vs_h[B_ * KOBJ * VD],        g_vs_l[B_ * KOBJ * VD];
__device__ bf16 g_vm_h[B_ * VD],               g_vm_l[B_ * VD];
__device__ bf16 g_x1p_h[TT * B_ * EMB],        g_x1p_l[TT * B_ * EMB];
__device__ bf16 g_h1_h[B_ * HID_],             g_h1_l[B_ * HID_];
__device__ bf16 g_h2_h[(TT + 1) * B_ * HID_],  g_h2_l[(TT + 1) * B_ * HID_];
__device__ bf16 g_attv_h[B_ * VD],             g_attv_l[B_ * VD];

// bf16 hi/lo weight arrays
__device__ bf16 g_wih1h_h[H3 * HID_],  g_wih1h_l[H3 * HID_];   // Wih1[:, :1024]
__device__ bf16 g_w1v_h[H3 * VD],      g_w1v_l[H3 * VD];       // Wih1[:, 1024:3072]
__device__ bf16 g_w1p_h[H3 * EMB],     g_w1p_l[H3 * EMB];      // Wih1[:, 3072:4096]
__device__ bf16 g_whh1_h[H3 * HID_],   g_whh1_l[H3 * HID_];
__device__ bf16 g_whh2_h[H3 * HID_],   g_whh2_l[H3 * HID_];
__device__ bf16 g_wv_h[HID_ * VD],     g_wv_l[HID_ * VD];
__device__ bf16 g_wih2v_h[H3 * VD],    g_wih2v_l[H3 * VD];     // Wih2[:, :2048]
__device__ bf16 g_wih2x_h[H3 * HID_],  g_wih2x_l[H3 * HID_];   // Wih2[:, 2048:]
__device__ bf16 g_w2_h[NTOK * HID_],   g_w2_l[NTOK * HID_];
__device__ bf16 g_wq_h[HID_ * HID_],   g_wq_l[HID_ * HID_];
__device__ bf16 g_w1t_h[HID_ * HID_],  g_w1t_l[HID_ * HID_];
__device__ bf16 g_wfq_h[HID_ * HID_],  g_wfq_l[HID_ * HID_];
__device__ bf16 g_wf2h_h[H3 * HID_],   g_wf2h_l[H3 * HID_];

// --------------------------- small helpers ---------------------------------
__device__ __forceinline__ void split2(float x, bf16& h, bf16& l) {
    h = __float2bfloat16(x);
    l = __float2bfloat16(x - __bfloat162float(h));
}
__device__ __forceinline__ unsigned smem_u32(const void* p) {
    return (unsigned)__cvta_generic_to_shared(p);
}
__device__ __forceinline__ void cpa16(unsigned dst, const void* src, int sz) {
    asm volatile("cp.async.ca.shared.global [%0], [%1], 16, %2;"
                 :: "r"(dst), "l"(src), "r"(sz));
}

#define LDM_X4(r0, r1, r2, r3, addr) \
    asm volatile("ldmatrix.sync.aligned.m8n8.x4.shared.b16 {%0,%1,%2,%3}, [%4];" \
        : "=r"(r0), "=r"(r1), "=r"(r2), "=r"(r3) : "r"(addr))

#define MMA16816(c, a, b) \
    asm volatile("mma.sync.aligned.m16n8k16.row.col.f32.bf16.bf16.f32 " \
        "{%0,%1,%2,%3}, {%4,%5,%6,%7}, {%8,%9}, {%0,%1,%2,%3};" \
        : "+f"((c)[0]), "+f"((c)[1]), "+f"((c)[2]), "+f"((c)[3]) \
        : "r"((a)[0]), "r"((a)[1]), "r"((a)[2]), "r"((a)[3]), \
          "r"((b)[0]), "r"((b)[1]))

// ----------------- host-launched tensor GEMM (big GEMMs) -------------------
struct TZ {
    const bf16 *Ahi, *Alo, *Whi, *Wlo;
    float* C; const float* bias;
    int lda, ldw, ldc, M, N, K, mode;
};
struct TP { TZ z[2]; const float* mask; };

template<int BN> struct TGC {
    static constexpr int BUF   = 32768 + BN * 256;
    static constexpr int SMEM  = 2 * BUF + 1024;
    static constexpr int THR   = BN * 2;
    static constexpr int WN    = BN / 32;
    static constexpr int RPI   = BN / 4;
    static constexpr int AIT   = 128 / RPI;
};

template<int BN>
__global__ void __launch_bounds__(TGC<BN>::THR) tgemm_k(TP p)
{
    const TZ gz = p.z[blockIdx.z];
    const int bn0 = blockIdx.x * BN;  if (bn0 >= gz.N) return;
    const int bm0 = blockIdx.y * 128; if (bm0 >= gz.M) return;
    const int tid = threadIdx.x, wid = tid >> 5, lane = tid & 31;
    const int wm = wid / TGC<BN>::WN, wn = wid % TGC<BN>::WN;

    extern __shared__ char dsm[];
    unsigned dbase = smem_u32(dsm);
    unsigned s0 = (dbase + 1023u) & ~1023u;
    unsigned sAh[2], sAl[2], sBh[2], sBl[2];
#pragma unroll
    for (int b = 0; b < 2; b++) {
        sAh[b] = s0 + b * TGC<BN>::BUF;
        sAl[b] = sAh[b] + 16384;
        sBh[b] = sAl[b] + 16384;
        sBl[b] = sBh[b] + BN * 128;
    }

    const int lrow = tid >> 3;
    const int lch  = tid & 7;
    auto load_chunk = [&](int c, int buf) {
        const int c0 = c * 64;
#pragma unroll
        for (int i = 0; i < TGC<BN>::AIT; i++) {
            int row = i * TGC<BN>::RPI + lrow;
            unsigned off = (unsigned)(row * 128) + (unsigned)(((lch ^ (row & 7)) * 16));
            cpa16(sAh[buf] + off, gz.Ahi + (size_t)(bm0 + row) * gz.lda + c0 + lch * 8, 16);
            cpa16(sAl[buf] + off, gz.Alo + (size_t)(bm0 + row) * gz.lda + c0 + lch * 8, 16);
        }
#pragma unroll
        for (int i = 0; i < 4; i++) {
            int row = i * TGC<BN>::RPI + lrow;
            unsigned off = (unsigned)(row * 128) + (unsigned)(((lch ^ (row & 7)) * 16));
            int n = bn0 + row;
            int sz = (n < gz.N) ? 16 : 0;
            int nn = (n < gz.N) ? n : 0;
            cpa16(sBh[buf] + off, gz.Whi + (size_t)nn * gz.ldw + c0 + lch * 8, sz);
            cpa16(sBl[buf] + off, gz.Wlo + (size_t)nn * gz.ldw + c0 + lch * 8, sz);
        }
        asm volatile("cp.async.commit_group;");
    };

    float acc[4][4][4];
#pragma unroll
    for (int mi = 0; mi < 4; mi++)
#pragma unroll
        for (int nj = 0; nj < 4; nj++)
#pragma unroll
            for (int e = 0; e < 4; e++) acc[mi][nj][e] = 0.f;

    const int xorkey = lane & 7;
    const int nch = gz.K / 64;
    load_chunk(0, 0);

    for (int c = 0; c < nch; c++) {
        if (c + 1 < nch) {
            load_chunk(c + 1, (c + 1) & 1);
            asm volatile("cp.async.wait_group 1;");
        } else {
            asm volatile("cp.async.wait_group 0;");
        }
        __syncthreads();
        const unsigned tAh = sAh[c & 1], tAl = sAl[c & 1];
        const unsigned tBh = sBh[c & 1], tBl = sBl[c & 1];
#pragma unroll
        for (int ks = 0; ks < 4; ks++) {
            unsigned Ah[4][4], Al[4][4];
            {
                const int arow = wm * 64 + (lane & 15);
                const unsigned aoff =
                    (unsigned)((((2 * ks) + (lane >> 4)) ^ xorkey) * 16);
#pragma unroll
                for (int mi = 0; mi < 4; mi++) {
                    unsigned ad = (unsigned)((arow + mi * 16) * 128) + aoff;
                    LDM_X4(Ah[mi][0], Ah[mi][1], Ah[mi][2], Ah[mi][3], tAh + ad);
                    LDM_X4(Al[mi][0], Al[mi][1], Al[mi][2], Al[mi][3], tAl + ad);
                }
            }
            unsigned Bh[4][2], Bl[4][2];
            {
                const int brow = wn * 32 + (lane & 7) + ((lane >> 4) << 3);
                const unsigned boff =
                    (unsigned)((((2 * ks) + ((lane >> 3) & 1)) ^ xorkey) * 16);
                unsigned r0, r1, r2, r3;
                unsigned b0 = (unsigned)(brow * 128) + boff;
                LDM_X4(r0, r1, r2, r3, tBh + b0);
                Bh[0][0] = r0; Bh[0][1] = r1; Bh[1][0] = r2; Bh[1][1] = r3;
                LDM_X4(r0, r1, r2, r3, tBh + b0 + 16 * 128);
                Bh[2][0] = r0; Bh[2][1] = r1; Bh[3][0] = r2; Bh[3][1] = r3;
                LDM_X4(r0, r1, r2, r3, tBl + b0);
                Bl[0][0] = r0; Bl[0][1] = r1; Bl[1][0] = r2; Bl[1][1] = r3;
                LDM_X4(r0, r1, r2, r3, tBl + b0 + 16 * 128);
                Bl[2][0] = r0; Bl[2][1] = r1; Bl[3][0] = r2; Bl[3][1] = r3;
            }
#pragma unroll
            for (int mi = 0; mi < 4; mi++)
#pragma unroll
                for (int nj = 0; nj < 4; nj++) {
                    MMA16816(acc[mi][nj], Ah[mi], Bh[nj]);
                    MMA16816(acc[mi][nj], Ah[mi], Bl[nj]);
                    MMA16816(acc[mi][nj], Al[mi], Bh[nj]);
                }
        }
        __syncthreads();
    }

    const int g = lane >> 2, tig = lane & 3;
    auto stc = [&](int m, int n, float val) {
        if (n >= gz.N) return;
        if (gz.bias) val += gz.bias[n];
        if (gz.mode == 1) val = fmaxf(val, 0.f);
        if (gz.mode == 2) {
            int tt = m / B_, bb = m % B_;
            gz.C[((size_t)bb * MAXLEN + tt) * gz.ldc + n] = val * p.mask[m];
        } else {
            gz.C[(size_t)m * gz.ldc + n] = val;
        }
    };
#pragma unroll
    for (int mi = 0; mi < 4; mi++)
#pragma unroll
        for (int nj = 0; nj < 4; nj++) {
            int row = bm0 + wm * 64 + mi * 16 + g;
            int col = bn0 + wn * 32 + nj * 8 + 2 * tig;
            stc(row,     col,     acc[mi][nj][0]);
            stc(row,     col + 1, acc[mi][nj][1]);
            stc(row + 8, col,     acc[mi][nj][2]);
            stc(row + 8, col + 1, acc[mi][nj][3]);
        }
}

// ------------------ persistent-loop device machinery ------------------------
__device__ __forceinline__ void grid_bar()
{
    __syncthreads();
    if (threadIdx.x == 0) {
        int gen = g_barg;
        __threadfence();
        if (atomicAdd(&g_barc, 1) == NCTA - 1) {
            g_barc = 0;
            __threadfence();
            g_barg = gen + 1;
        } else {
            while (g_barg == gen) __nanosleep(32);
            __threadfence();
        }
    }
    __syncthreads();
}

// one 128x64xK GEMM tile, 256 threads (8 warps: 4m x 2n), single-buffered.
__device__ void gemm_task(const bf16* __restrict__ Ah0, const bf16* __restrict__ Al0,
                          int lda,
                          const bf16* __restrict__ Wh0, const bf16* __restrict__ Wl0,
                          int ldw,
                          float* __restrict__ C, int ldc, int bn0, int Ksz,
                          const float* __restrict__ bias, char* dsm)
{
    const int tid = threadIdx.x, wid = tid >> 5, lane = tid & 31;
    const int wm = wid >> 1, wn = wid & 1;

    unsigned dbase = smem_u32(dsm);
    unsigned s0 = (dbase + 1023u) & ~1023u;
    const unsigned sAh = s0;
    const unsigned sAl = sAh + 16384;
    const unsigned sBh = sAl + 16384;
    const unsigned sBl = sBh + 8192;

    const int lrow = tid >> 3;         // 0..31
    const int lch  = tid & 7;
    const bf16* Wb_h = Wh0 + (size_t)bn0 * ldw;
    const bf16* Wb_l = Wl0 + (size_t)bn0 * ldw;

    float acc[2][4][4];
#pragma unroll
    for (int mi = 0; mi < 2; mi++)
#pragma unroll
        for (int nj = 0; nj < 4; nj++)
#pragma unroll
            for (int e = 0; e < 4; e++) acc[mi][nj][e] = 0.f;

    const int xorkey = lane & 7;
    const int nch = Ksz / 64;

    for (int c = 0; c < nch; c++) {
        const int c0 = c * 64;
#pragma unroll
        for (int i = 0; i < 4; i++) {
            int row = i * 32 + lrow;
            unsigned off = (unsigned)(row * 128) + (unsigned)(((lch ^ (row & 7)) * 16));
            cpa16(sAh + off, Ah0 + (size_t)row * lda + c0 + lch * 8, 16);
            cpa16(sAl + off, Al0 + (size_t)row * lda + c0 + lch * 8, 16);
        }
#pragma unroll
        for (int i = 0; i < 2; i++) {
            int row = i * 32 + lrow;
            unsigned off = (unsigned)(row * 128) + (unsigned)(((lch ^ (row & 7)) * 16));
            cpa16(sBh + off, Wb_h + (size_t)row * ldw + c0 + lch * 8, 16);
            cpa16(sBl + off, Wb_l + (size_t)row * ldw + c0 + lch * 8, 16);
        }
        asm volatile("cp.async.commit_group;");
        asm volatile("cp.async.wait_group 0;");
        __syncthreads();

#pragma unroll
        for (int ks = 0; ks < 4; ks++) {
            unsigned Ahf[2][4], Alf[2][4];
            {
                const int arow = wm * 32 + (lane & 15);
                const unsigned aoff =
                    (unsigned)((((2 * ks) + (lane >> 4)) ^ xorkey) * 16);
#pragma unroll
                for (int mi = 0; mi < 2; mi++) {
                    unsigned ad = (unsigned)((arow + mi * 16) * 128) + aoff;
                    LDM_X4(Ahf[mi][0], Ahf[mi][1], Ahf[mi][2], Ahf[mi][3], sAh + ad);
                    LDM_X4(Alf[mi][0], Alf[mi][1], Alf[mi][2], Alf[mi][3], sAl + ad);
                }
            }
            unsigned Bh[4][2], Bl[4][2];
            {
                const int brow = wn * 32 + (lane & 7) + ((lane >> 4) << 3);
                const unsigned boff =
                    (unsigned)((((2 * ks) + ((lane >> 3) & 1)) ^ xorkey) * 16);
                unsigned r0, r1, r2, r3;
                unsigned b0 = (unsigned)(brow * 128) + boff;
                LDM_X4(r0, r1, r2, r3, sBh + b0);
                Bh[0][0] = r0; Bh[0][1] = r1; Bh[1][0] = r2; Bh[1][1] = r3;
                LDM_X4(r0, r1, r2, r3, sBh + b0 + 16 * 128);
                Bh[2][0] = r0; Bh[2][1] = r1; Bh[3][0] = r2; Bh[3][1] = r3;
                LDM_X4(r0, r1, r2, r3, sBl + b0);
                Bl[0][0] = r0; Bl[0][1] = r1; Bl[1][0] = r2; Bl[1][1] = r3;
                LDM_X4(r0, r1, r2, r3, sBl + b0 + 16 * 128);
                Bl[2][0] = r0; Bl[2][1] = r1; Bl[3][0] = r2; Bl[3][1] = r3;
            }
#pragma unroll
            for (int mi = 0; mi < 2; mi++)
#pragma unroll
                for (int nj = 0; nj < 4; nj++) {
                    MMA16816(acc[mi][nj], Ahf[mi], Bh[nj]);
                    MMA16816(acc[mi][nj], Ahf[mi], Bl[nj]);
                    MMA16816(acc[mi][nj], Alf[mi], Bh[nj]);
                }
        }
        __syncthreads();
    }

    const int g = lane >> 2, tig = lane & 3;
#pragma unroll
    for (int mi = 0; mi < 2; mi++)
#pragma unroll
        for (int nj = 0; nj < 4; nj++) {
            int row = wm * 32 + mi * 16 + g;
            int col = bn0 + wn * 32 + nj * 8 + 2 * tig;
            float v0 = acc[mi][nj][0], v1 = acc[mi][nj][1];
            float v2 = acc[mi][nj][2], v3 = acc[mi][nj][3];
            if (bias) {
                v0 += bias[col]; v1 += bias[col + 1];
                v2 += bias[col]; v3 += bias[col + 1];
            }
            C[(size_t)row * ldc + col]           = v0;
            C[(size_t)row * ldc + col + 1]       = v1;
            C[(size_t)(row + 8) * ldc + col]     = v2;
            C[(size_t)(row + 8) * ldc + col + 1] = v3;
        }
}

// ------------------------- persistent loop kernel ---------------------------
__global__ void __launch_bounds__(256, 2) loop_kernel(
    const float* __restrict__ bhh1, const float* __restrict__ bhh2,
    const float* __restrict__ wa,   const float* __restrict__ ba,
    float* __restrict__ alphas)
{
    extern __shared__ char dsm[];
    const int cta = blockIdx.x;
    const int tid = threadIdx.x;

    for (int t = 0; t < TT; t++) {
        const bf16*  h2ph = g_h2_h + (size_t)t * B_ * HID_;
        const bf16*  h2pl = g_h2_l + (size_t)t * B_ * HID_;
        const float* h2prev = g_h2all + (size_t)t * B_ * HID_;
        float*       h2next = g_h2all + (size_t)(t + 1) * B_ * HID_;

        // ---- phase 1: stage1 (gih, gh1, gh2), 288 tasks (1 round) ----
        for (int task = cta; task < 288; task += NCTA) {
            int s = task & 1, x = (task >> 1) % 48, o = task / 96;
            int ko = s * 512;
            if (o == 0)
                gemm_task(h2ph + ko, h2pl + ko, HID_,
                          g_wih1h_h + ko, g_wih1h_l + ko, HID_,
                          g_gih[s], H3, x * 64, 512, nullptr, dsm);
            else if (o == 1)
                gemm_task(g_h1_h + ko, g_h1_l + ko, HID_,
                          g_whh1_h + ko, g_whh1_l + ko, HID_,
                          g_gh1[s], H3, x * 64, 512, s == 0 ? bhh1 : nullptr, dsm);
            else
                gemm_task(h2ph + ko, h2pl + ko, HID_,
                          g_whh2_h + ko, g_whh2_l + ko, HID_,
                          g_gh2[s], H3, x * 64, 512, s == 0 ? bhh2 : nullptr, dsm);
        }
        grid_bar();

        // ---- phase 2: GRU1 pointwise (gi = giv + gip[t] + gih) ----
        {
            const float* gip = g_gip + (size_t)t * B_ * H3;
            for (int idx = cta * 256 + tid; idx < B_ * HID_; idx += NCTA * 256) {
                int b = idx >> 10, j = idx & 1023;
                size_t base = (size_t)b * H3 + j;
                float gr = g_giv[base] + gip[base] + g_gih[0][base] + g_gih[1][base];
                float gz = g_giv[base + HID_] + gip[base + HID_]
                         + g_gih[0][base + HID_] + g_gih[1][base + HID_];
                float gn = g_giv[base + 2*HID_] + gip[base + 2*HID_]
                         + g_gih[0][base + 2*HID_] + g_gih[1][base + 2*HID_];
                float ghr = g_gh1[0][base] + g_gh1[1][base];
                float ghz = g_gh1[0][base + HID_] + g_gh1[1][base + HID_];
                float ghn = g_gh1[0][base + 2*HID_] + g_gh1[1][base + 2*HID_];
                float r = 1.f / (1.f + expf(-(gr + ghr)));
                float z = 1.f / (1.f + expf(-(gz + ghz)));
                float n = tanhf(gn + r * ghn);
                float h = (1.f - z) * n + z * g_h1[idx];
                g_h1[idx] = h;
                split2(h, g_h1_h[idx], g_h1_l[idx]);
            }
        }
        grid_bar();

        // ---- phase 3: stage2 (q 32 tasks, gi2h 96 tasks) ----
        for (int task = cta; task < 128; task += NCTA) {
            if (task < 32) {
                int s = task & 1, x = (task >> 1);
                int ko = s * 512;
                gemm_task(g_h1_h + ko, g_h1_l + ko, HID_,
                          g_wfq_h + ko, g_wfq_l + ko, HID_,
                          g_qp[s], HID_, x * 64, 512, nullptr, dsm);
            } else {
                int u = task - 32;
                int s = u & 1, x = (u >> 1);
                int ko = s * 512;
                gemm_task(g_h1_h + ko, g_h1_l + ko, HID_,
                          g_wf2h_h + ko, g_wf2h_l + ko, HID_,
                          g_gi2h[s], H3, x * 64, 512, nullptr, dsm);
            }
        }
        grid_bar();

        // ---- phase 4: attention, one batch row per CTA ----
        for (int b = cta; b < B_; b += NCTA) {
            float* qs  = (float*)dsm;
            float* att = qs + HID_;
            for (int d = tid; d < HID_; d += 256) {
                float qv = g_qp[0][b * HID_ + d] + g_qp[1][b * HID_ + d] + g_bfq[d];
                qs[d] = fmaxf(qv, 0.f) * wa[d];
            }
            __syncthreads();
            int warp = tid >> 5, lane = tid & 31;
            for (int k = warp; k < KOBJ; k += 8) {
                const float* vp = g_vproj + ((size_t)b * KOBJ + k) * HID_;
                float s = 0.f;
                for (int d = lane; d < HID_; d += 32) s += vp[d] * qs[d];
#pragma unroll
                for (int o = 16; o; o >>= 1) s += __shfl_down_sync(0xffffffffu, s, o);
                if (lane == 0) att[k] = s + ba[0];
            }
            __syncthreads();
            if (tid == 0) {
                float mx = att[0];
                for (int k = 1; k < KOBJ; k++) mx = fmaxf(mx, att[k]);
                float ssum = 0.f;
                for (int k = 0; k < KOBJ; k++) { float e = expf(att[k] - mx); att[k] = e; ssum += e; }
                float inv = 1.f / ssum;
                for (int k = 0; k < KOBJ; k++) att[k] *= inv;
            }
            __syncthreads();
            if (tid < KOBJ) {
                float m = (t < g_dl[b]) ? 1.f : 0.f;
                alphas[((size_t)b * MAXLEN + t) * KOBJ + tid] = att[tid] * m;
            }
            for (int d = tid; d < VD; d += 256) {
                const float* vb = g_vs + (size_t)b * KOBJ * VD + d;
                float s = 0.f;
#pragma unroll 6
                for (int k = 0; k < KOBJ; k++) s += att[k] * vb[(size_t)k * VD];
                split2(s, g_attv_h[b * VD + d], g_attv_l[b * VD + d]);
            }
            __syncthreads();
        }
        grid_bar();

        // ---- phase 5: gi2att, 192 tasks (1 round) ----
        for (int task = cta; task < 192; task += NCTA) {
            int s = task & 3, x = task >> 2;
            int ko = s * 512;
            gemm_task(g_attv_h + ko, g_attv_l + ko, VD,
                      g_wih2v_h + ko, g_wih2v_l + ko, VD,
                      g_p0[s], H3, x * 64, 512, nullptr, dsm);
        }
        grid_bar();

        // ---- phase 6: GRU2 pointwise ----
        {
            bf16* hh = g_h2_h + (size_t)(t + 1) * B_ * HID_;
            bf16* hl = g_h2_l + (size_t)(t + 1) * B_ * HID_;
            for (int idx = cta * 256 + tid; idx < B_ * HID_; idx += NCTA * 256) {
                int b = idx >> 10, j = idx & 1023;
                size_t base = (size_t)b * H3 + j;
                float gr = g_bi2f[j], gz = g_bi2f[j + HID_], gn = g_bi2f[j + 2*HID_];
#pragma unroll
                for (int s = 0; s < 4; s++) {
                    gr += g_p0[s][base]; gz += g_p0[s][base + HID_]; gn += g_p0[s][base + 2*HID_];
                }
#pragma unroll
                for (int s = 0; s < 2; s++) {
                    gr += g_gi2h[s][base]; gz += g_gi2h[s][base + HID_]; gn += g_gi2h[s][base + 2*HID_];
                }
                float ghr = g_gh2[0][base] + g_gh2[1][base];
                float ghz = g_gh2[0][base + HID_] + g_gh2[1][base + HID_];
                float ghn = g_gh2[0][base + 2*HID_] + g_gh2[1][base + 2*HID_];
                float r = 1.f / (1.f + expf(-(gr + ghr)));
                float z = 1.f / (1.f + expf(-(gz + ghz)));
                float n = tanhf(gn + r * ghn);
                float h = (1.f - z) * n + z * h2prev[idx];
                h2next[idx] = h;
                split2(h, hh[idx], hl[idx]);
            }
        }
        grid_bar();
    }
}

// ------------------------------- small kernels -----------------------------
__global__ void meta_kernel(const int* __restrict__ cap_len)
{
    int i = threadIdx.x;
    int ci = cap_len[i];
    int rank = 0;
    for (int j = 0; j < B_; j++) {
        int cj = cap_len[j];
        if (cj > ci || (cj == ci && j < i)) rank++;
    }
    g_order[rank] = i;
    __syncthreads();
    g_dl[i] = cap_len[g_order[i]] - 1;
    __syncthreads();
    int dli = g_dl[i];
    for (int t = 0; t < TT; t++) g_mask[t * B_ + i] = (t < dli) ? 1.f : 0.f;
    if (i == 0) { g_barc = 0; g_barg = 0; }
}

__global__ void zero_init_kernel()
{
    int idx = blockIdx.x * 256 + threadIdx.x;
    if (idx < B_ * HID_) {
        g_h1[idx] = 0.f;    g_h1_h[idx] = __float2bfloat16(0.f); g_h1_l[idx] = __float2bfloat16(0.f);
        g_h2all[idx] = 0.f; g_h2_h[idx] = __float2bfloat16(0.f); g_h2_l[idx] = __float2bfloat16(0.f);
    }
}

__global__ void permute_v_kernel(const float* __restrict__ v)
{
    size_t idx = (size_t)blockIdx.x * 256 + threadIdx.x;
    if (idx >= (size_t)B_ * KOBJ * VD) return;
    int b = (int)(idx / ((size_t)KOBJ * VD));
    size_t rest = idx % ((size_t)KOBJ * VD);
    float x = v[(size_t)g_order[b] * KOBJ * VD + rest];
    g_vs[idx] = x;
    split2(x, g_vs_h[idx], g_vs_l[idx]);
}

__global__ void vmean_kernel()
{
    int idx = blockIdx.x * 256 + threadIdx.x;
    if (idx >= B_ * VD) return;
    int b = idx / VD, d = idx % VD;
    const float* p = g_vs + (size_t)b * KOBJ * VD + d;
    float s = 0.f;
#pragma unroll 6
    for (int k = 0; k < KOBJ; k++) s += p[(size_t)k * VD];
    s *= (1.f / (float)KOBJ);
    g_vmean[idx] = s;
    split2(s, g_vm_h[idx], g_vm_l[idx]);
}

// prev embeddings -> bf16 hi/lo rows [t*B + b, 1024]
__global__ void build_x1p_kernel(const float* __restrict__ caption)
{
    size_t idx = (size_t)blockIdx.x * 256 + threadIdx.x;
    if (idx >= (size_t)TT * B_ * EMB) return;
    int c = (int)(idx % EMB);
    int r = (int)(idx / EMB);
    int t = r / B_, b = r % B_;
    float val = caption[((size_t)g_order[b] * MAXLEN + t) * EMB + c];
    split2(val, g_x1p_h[idx], g_x1p_l[idx]);
}

__global__ void convw_kernel(const float* __restrict__ src, int ld, int col0,
                             int rows, int cols, bf16* __restrict__ hi,
                             bf16* __restrict__ lo)
{
    size_t idx = (size_t)blockIdx.x * 256 + threadIdx.x;
    if (idx >= (size_t)rows * cols) return;
    int r = (int)(idx / cols), c = (int)(idx % cols);
    split2(src[(size_t)r * ld + col0 + c], hi[idx], lo[idx]);
}

__global__ void tsplit_kernel(const float* __restrict__ src,
                              bf16* __restrict__ hi, bf16* __restrict__ lo)
{
    __shared__ float tile[32][33];
    int bx = blockIdx.x * 32, by = blockIdx.y * 32;
#pragma unroll
    for (int i = 0; i < 32; i += 8)
        tile[threadIdx.y + i][threadIdx.x] =
            src[(size_t)(by + threadIdx.y + i) * HID_ + bx + threadIdx.x];
    __syncthreads();
#pragma unroll
    for (int i = 0; i < 32; i += 8) {
        float vv = tile[threadIdx.x][threadIdx.y + i];
        size_t o = (size_t)(bx + threadIdx.y + i) * HID_ + by + threadIdx.x;
        split2(vv, hi[o], lo[o]);
    }
}

__global__ void fusebias_kernel(const float* __restrict__ Wq,
                                const float* __restrict__ bq,
                                const float* __restrict__ b1,
                                const float* __restrict__ Wih2,
                                const float* __restrict__ bih2)
{
    int idx = blockIdx.x * 256 + threadIdx.x;
    if (idx < HID_) {
        const float* w = Wq + (size_t)idx * HID_;
        float s = 0.f;
        for (int j = 0; j < HID_; j++) s += w[j] * b1[j];
        g_bfq[idx] = s + bq[idx];
    } else if (idx < HID_ + H3) {
        int n = idx - HID_;
        const float* w = Wih2 + (size_t)n * H3 + VD;
        float s = 0.f;
        for (int j = 0; j < HID_; j++) s += w[j] * b1[j];
        g_bi2f[n] = s + bih2[n];
    }
}

__global__ void zero_tails_kernel(float* __restrict__ predict,
                                  float* __restrict__ alphas)
{
    int idx = blockIdx.x * 256 + threadIdx.x;
    if (idx < B_ * NTOK) {
        int b = idx / NTOK, n = idx % NTOK;
        predict[((size_t)b * MAXLEN + (MAXLEN - 1)) * NTOK + n] = 0.f;
    } else if (idx < B_ * NTOK + B_ * KOBJ) {
        int r = idx - B_ * NTOK;
        int b = r / KOBJ, k = r % KOBJ;
        alphas[((size_t)b * MAXLEN + (MAXLEN - 1)) * KOBJ + k] = 0.f;
    }
}

// --------------------------------- launch ----------------------------------
static inline TZ mkt(const bf16* Ah, const bf16* Al, int lda,
                     const bf16* Wh, const bf16* Wl, int ldw,
                     float* C, int ldc, int M, int N, int K,
                     const float* bias, int mode)
{
    TZ z; z.Ahi = Ah; z.Alo = Al; z.Whi = Wh; z.Wlo = Wl;
    z.C = C; z.bias = bias; z.lda = lda; z.ldw = ldw; z.ldc = ldc;
    z.M = M; z.N = N; z.K = K; z.mode = mode;
    return z;
}

#define SYMADDR(var, sym) cudaGetSymbolAddress((void**)&var, sym)

extern "C" void kernel_launch(void* const* d_in, const int* in_sizes, int n_in,
                              void* d_out, int out_size)
{
    const float* v       = (const float*)d_in[0];
    const float* caption = (const float*)d_in[1];
    const int*   cap_len = (const int*)  d_in[2];
    const float* Wih1    = (const float*)d_in[3];
    const float* Whh1    = (const float*)d_in[4];
    const float* bih1    = (const float*)d_in[5];
    const float* bhh1    = (const float*)d_in[6];
    const float* Wih2    = (const float*)d_in[7];
    const float* Whh2    = (const float*)d_in[8];
    const float* bih2    = (const float*)d_in[9];
    const float* bhh2    = (const float*)d_in[10];
    const float* Wv      = (const float*)d_in[11];
    const float* bv      = (const float*)d_in[12];
    const float* Wq      = (const float*)d_in[13];
    const float* bq      = (const float*)d_in[14];
    const float* wa      = (const float*)d_in[15];
    const float* ba      = (const float*)d_in[16];
    const float* W1      = (const float*)d_in[17];
    const float* b1      = (const float*)d_in[18];
    const float* W2      = (const float*)d_in[19];
    const float* b2      = (const float*)d_in[20];

    float* out     = (float*)d_out;
    float* predict = out;
    float* alphas  = out + (size_t)B_ * MAXLEN * NTOK;

    float *p_giv, *p_gip, *p_Wfq, *p_Wf2h, *p_mask, *p_vproj;
    SYMADDR(p_giv, g_giv);    SYMADDR(p_gip, g_gip);
    SYMADDR(p_Wfq, g_Wfq);    SYMADDR(p_Wf2h, g_Wf2h);
    SYMADDR(p_mask, g_mask);  SYMADDR(p_vproj, g_vproj);

    bf16 *vs_h, *vs_l, *vm_h, *vm_l, *x1p_h, *x1p_l, *h2_h, *h2_l;
    bf16 *w1h_h, *w1h_l, *w1v_h, *w1v_l, *w1p_h, *w1p_l;
    bf16 *wh1_h, *wh1_l, *wh2_h, *wh2_l;
    bf16 *wv_h, *wv_l, *w2v_h, *w2v_l, *w2x_h, *w2x_l, *ww2_h, *ww2_l;
    bf16 *wq_h, *wq_l, *w1t_h, *w1t_l, *wfq_h, *wfq_l, *wf2_h, *wf2_l;
    SYMADDR(vs_h, g_vs_h);   SYMADDR(vs_l, g_vs_l);
    SYMADDR(vm_h, g_vm_h);   SYMADDR(vm_l, g_vm_l);
    SYMADDR(x1p_h, g_x1p_h); SYMADDR(x1p_l, g_x1p_l);
    SYMADDR(h2_h, g_h2_h);   SYMADDR(h2_l, g_h2_l);
    SYMADDR(w1h_h, g_wih1h_h); SYMADDR(w1h_l, g_wih1h_l);
    SYMADDR(w1v_h, g_w1v_h);   SYMADDR(w1v_l, g_w1v_l);
    SYMADDR(w1p_h, g_w1p_h);   SYMADDR(w1p_l, g_w1p_l);
    SYMADDR(wh1_h, g_whh1_h);  SYMADDR(wh1_l, g_whh1_l);
    SYMADDR(wh2_h, g_whh2_h);  SYMADDR(wh2_l, g_whh2_l);
    SYMADDR(wv_h, g_wv_h);     SYMADDR(wv_l, g_wv_l);
    SYMADDR(w2v_h, g_wih2v_h); SYMADDR(w2v_l, g_wih2v_l);
    SYMADDR(w2x_h, g_wih2x_h); SYMADDR(w2x_l, g_wih2x_l);
    SYMADDR(ww2_h, g_w2_h);    SYMADDR(ww2_l, g_w2_l);
    SYMADDR(wq_h, g_wq_h);     SYMADDR(wq_l, g_wq_l);
    SYMADDR(w1t_h, g_w1t_h);   SYMADDR(w1t_l, g_w1t_l);
    SYMADDR(wfq_h, g_wfq_h);   SYMADDR(wfq_l, g_wfq_l);
    SYMADDR(wf2_h, g_wf2h_h);  SYMADDR(wf2_l, g_wf2h_l);

    const int LOOPSMEM = 49152 + 1024;
    cudaFuncSetAttribute(tgemm_k<64>,  cudaFuncAttributeMaxDynamicSharedMemorySize,
                         TGC<64>::SMEM);
    cudaFuncSetAttribute(tgemm_k<128>, cudaFuncAttributeMaxDynamicSharedMemorySize,
                         TGC<128>::SMEM);
    cudaFuncSetAttribute(loop_kernel,  cudaFuncAttributeMaxDynamicSharedMemorySize,
                         LOOPSMEM);

    auto cv = [](const float* s, int ld, int c0, int r, int c, bf16* h, bf16* l) {
        size_t n = (size_t)r * c;
        convw_kernel<<<(unsigned)((n + 255) / 256), 256>>>(s, ld, c0, r, c, h, l);
    };

    // ---- setup ----
    meta_kernel<<<1, B_>>>(cap_len);
    zero_init_kernel<<<(B_ * HID_ + 255) / 256, 256>>>();
    permute_v_kernel<<<(unsigned)(((size_t)B_*KOBJ*VD + 255)/256), 256>>>(v);
    vmean_kernel<<<(B_ * VD + 255) / 256, 256>>>();
    build_x1p_kernel<<<(unsigned)(((size_t)TT*B_*EMB + 255)/256), 256>>>(caption);
    cv(Wih1, HID_ + VD + EMB, 1024, H3, VD,   w1v_h, w1v_l);
    cv(Wih1, HID_ + VD + EMB, 3072, H3, EMB,  w1p_h, w1p_l);
    cv(Wih1, HID_ + VD + EMB, 0,    H3, HID_, w1h_h, w1h_l);
    {   // giv = v_mean @ Wih1[:,1024:3072].T + bih1   [128 x 3072 x K=2048]
        TP P{}; P.mask = nullptr;
        P.z[0] = mkt(vm_h, vm_l, VD, w1v_h, w1v_l, VD,
                     p_giv, H3, B_, H3, VD, bih1, 0);
        tgemm_k<64><<<dim3(H3/64, 1, 1), TGC<64>::THR, TGC<64>::SMEM>>>(P);
    }
    {   // gip = x1p @ Wih1[:,3072:4096].T   [2432 x 3072 x K=1024]
        TP P{}; P.mask = nullptr;
        P.z[0] = mkt(x1p_h, x1p_l, EMB, w1p_h, w1p_l, EMB,
                     p_gip, H3, TT * B_, H3, EMB, nullptr, 0);
        tgemm_k<128><<<dim3(H3/128, (TT*B_)/128, 1), TGC<128>::THR, TGC<128>::SMEM>>>(P);
    }
    cv(Whh1, HID_, 0,    H3,   HID_, wh1_h, wh1_l);
    cv(Whh2, HID_, 0,    H3,   HID_, wh2_h, wh2_l);
    cv(Wv,   VD,   0,    HID_, VD,   wv_h,  wv_l);
    cv(Wih2, H3,   0,    H3,   VD,   w2v_h, w2v_l);
    cv(Wih2, H3,   2048, H3,   HID_, w2x_h, w2x_l);
    cv(Wq,   HID_, 0,    HID_, HID_, wq_h,  wq_l);
    cv(W2,   HID_, 0,    NTOK, HID_, ww2_h, ww2_l);
    tsplit_kernel<<<dim3(32, 32), dim3(32, 8)>>>(W1, w1t_h, w1t_l);
    {   // tensor precompute: Wfq = Wq@W1 (via W1T); Wf2h = Wih2x@W1
        TP P{}; P.mask = nullptr;
        P.z[0] = mkt(wq_h,  wq_l,  HID_, w1t_h, w1t_l, HID_,
                     p_Wfq,  HID_, HID_, HID_, HID_, nullptr, 0);
        P.z[1] = mkt(w2x_h, w2x_l, HID_, w1t_h, w1t_l, HID_,
                     p_Wf2h, HID_, H3,   HID_, HID_, nullptr, 0);
        tgemm_k<64><<<dim3(HID_/64, H3/128, 2), TGC<64>::THR, TGC<64>::SMEM>>>(P);
    }
    cv(p_Wfq,  HID_, 0, HID_, HID_, wfq_h, wfq_l);
    cv(p_Wf2h, HID_, 0, H3,   HID_, wf2_h, wf2_l);
    fusebias_kernel<<<(HID_ + H3 + 255) / 256, 256>>>(Wq, bq, b1, Wih2, bih2);
    {   // vproj = relu(v_s @ Wv.T + bv)   [4608 x 1024 x K=2048]
        TP P{}; P.mask = nullptr;
        P.z[0] = mkt(vs_h, vs_l, VD, wv_h, wv_l, VD,
                     p_vproj, HID_, B_ * KOBJ, HID_, VD, bv, 1);
        tgemm_k<128><<<dim3(HID_/128, (B_*KOBJ)/128, 1), TGC<128>::THR, TGC<128>::SMEM>>>(P);
    }

    // ---- persistent decode loop ----
    loop_kernel<<<NCTA, 256, LOOPSMEM>>>(bhh1, bhh2, wa, ba, alphas);

    // ---- words = H2all @ W2.T + b2 (masked scatter) ----
    {
        TP P{}; P.mask = p_mask;
        P.z[0] = mkt(h2_h + B_ * HID_, h2_l + B_ * HID_, HID_,
                     ww2_h, ww2_l, HID_,
                     predict, NTOK, TT * B_, NTOK, HID_, b2, 2);
        tgemm_k<128><<<dim3((NTOK + 127) / 128, (TT*B_)/128, 1),
                       TGC<128>::THR, TGC<128>::SMEM>>>(P);
    }
    zero_tails_kernel<<<(B_ * NTOK + B_ * KOBJ + 255) / 256, 256>>>(predict, alphas);
}